// round 7
// baseline (speedup 1.0000x reference)
#include <cuda_runtime.h>
#include <cstdint>

#define BB   8
#define CC   256
#define CQ   32
#define NN   16384
#define EPSV 1e-6f
#define STK  76             // kt stride; 76 mod 32 = 12 -> conflict-free mpT frag loads
#define T1   256            // pass1 n per block (4 subtiles of 64)

// ---------------- scratch (device globals) ---------------------------------
__device__ __align__(16) uint32_t g_WtF[4 * 32 * 32 * 4];   // tf32 A-frags; 0-1 = Wq, 2-3 = Wk
__device__ float g_mpT[BB * CC * CQ];                       // (Kn @ x^T)^T : [b][c][m]
__device__ float g_S[BB * CQ];                              // sum_n Kn
__device__ float g_xsum[BB * CC];                           // sum_n x
__device__ __align__(16) uint32_t g_mfrag[BB * 16 * 4 * 32 * 4]; // matT tf32 A-frags
__device__ float g_vsum[BB * CC];                           // value_sum
__device__ __align__(16) uint4 g_qfrag[(size_t)BB * 2048 * 32 * 2]; // Qn B-frags [b][jt][lane][2]

__device__ __forceinline__ uint32_t f2tf(float f) {
    uint32_t r; asm("cvt.rna.tf32.f32 %0, %1;" : "=r"(r) : "f"(f)); return r;
}

__device__ __forceinline__ void mma_tf32(float& d0, float& d1, float& d2, float& d3,
                                         uint32_t a0, uint32_t a1, uint32_t a2, uint32_t a3,
                                         uint32_t b0, uint32_t b1) {
    asm volatile(
        "mma.sync.aligned.m16n8k8.row.col.f32.tf32.tf32.f32 "
        "{%0,%1,%2,%3},{%4,%5,%6,%7},{%8,%9},{%0,%1,%2,%3};"
        : "+f"(d0), "+f"(d1), "+f"(d2), "+f"(d3)
        : "r"(a0), "r"(a1), "r"(a2), "r"(a3), "r"(b0), "r"(b1));
}

// ---------------- kernel 0: zero accumulators + build tf32 W-fragments -----
__global__ void k_prep(const float* __restrict__ Wq, const float* __restrict__ Wk) {
    int idx = blockIdx.x * blockDim.x + threadIdx.x;      // 65536 threads
    if (idx < BB * CC * CQ) g_mpT[idx] = 0.f;
    if (idx < 16384) {
        int f    = idx & 3;
        int lane = (idx >> 2) & 31;
        int kk   = (idx >> 7) & 31;
        int wo   = idx >> 12;
        int gid = lane >> 2, tig = lane & 3;
        int o = (wo & 1) * 16 + gid + (f & 1) * 8;
        int c = kk * 8 + tig + (f >> 1) * 4;
        float v = (wo < 2) ? Wq[o * CC + c] : Wk[o * CC + c];
        g_WtF[idx] = f2tf(v);
    }
    if (idx < BB * CC) g_xsum[idx] = 0.f;
    if (idx < BB * CQ) g_S[idx] = 0.f;
}

// ---------------- kernel 1: Q+K proj (direct LDG), Qn frags, S, xsum, mpT --
__global__ void __launch_bounds__(256, 2)
k_pass1(const float* __restrict__ x, const float* __restrict__ bq,
        const float* __restrict__ bk) {
    __shared__ float kt[4 * CQ * STK];    // Kn tf32 bits, one slice per subtile
    __shared__ float qt[8 * 32 * 9];      // per-warp Qn transpose scratch
    uint32_t* ktu = (uint32_t*)kt;
    uint32_t* qtu = (uint32_t*)qt;

    const int b   = blockIdx.x >> 6;
    const int n0  = (blockIdx.x & 63) * T1;
    const int tid = threadIdx.x;
    const int w = tid >> 5, lane = tid & 31, gid = lane >> 2, tig = lane & 3;
    const float* xb = x + (size_t)b * CC * NN;

    const float bq0 = __ldg(&bq[gid]),      bq1 = __ldg(&bq[gid + 8]);
    const float bq2 = __ldg(&bq[gid + 16]), bq3 = __ldg(&bq[gid + 24]);
    const float bk0 = __ldg(&bk[gid]),      bk1 = __ldg(&bk[gid + 8]);
    const float bk2 = __ldg(&bk[gid + 16]), bk3 = __ldg(&bk[gid + 24]);

    float S_acc0 = 0.f, S_acc1 = 0.f, S_acc2 = 0.f, S_acc3 = 0.f;

    const uint4* Wt = (const uint4*)g_WtF + lane;

    // ---- phase A: per-warp Q+K proj for own 8 j of each subtile ----
    #pragma unroll 1
    for (int sub = 0; sub < 4; sub++) {
        const int jbase = n0 + sub * 64 + w * 8;      // global j of warp's 8 cols
        const float* xp = xb + (size_t)tig * NN + jbase + gid;

        float dq[2][4], dk[2][4];
        #pragma unroll
        for (int t = 0; t < 2; t++)
            #pragma unroll
            for (int q = 0; q < 4; q++) { dq[t][q] = 0.f; dk[t][q] = 0.f; }

        #pragma unroll 4
        for (int kk = 0; kk < 32; kk++) {
            uint32_t b0 = f2tf(__ldg(xp + (size_t)(8 * kk) * NN));
            uint32_t b1 = f2tf(__ldg(xp + (size_t)(8 * kk + 4) * NN));
            uint4 a;
            a = Wt[kk * 32];
            mma_tf32(dq[0][0], dq[0][1], dq[0][2], dq[0][3], a.x, a.y, a.z, a.w, b0, b1);
            a = Wt[1024 + kk * 32];
            mma_tf32(dq[1][0], dq[1][1], dq[1][2], dq[1][3], a.x, a.y, a.z, a.w, b0, b1);
            a = Wt[2048 + kk * 32];
            mma_tf32(dk[0][0], dk[0][1], dk[0][2], dk[0][3], a.x, a.y, a.z, a.w, b0, b1);
            a = Wt[3072 + kk * 32];
            mma_tf32(dk[1][0], dk[1][1], dk[1][2], dk[1][3], a.x, a.y, a.z, a.w, b0, b1);
        }
        dq[0][0] += bq0; dq[0][1] += bq0; dq[0][2] += bq1; dq[0][3] += bq1;
        dq[1][0] += bq2; dq[1][1] += bq2; dq[1][2] += bq3; dq[1][3] += bq3;
        dk[0][0] += bk0; dk[0][1] += bk0; dk[0][2] += bk1; dk[0][3] += bk1;
        dk[1][0] += bk2; dk[1][1] += bk2; dk[1][2] += bk3; dk[1][3] += bk3;

        // column norms (butterfly over gid bits)
        float qe = dq[0][0]*dq[0][0] + dq[0][2]*dq[0][2] + dq[1][0]*dq[1][0] + dq[1][2]*dq[1][2];
        float qo = dq[0][1]*dq[0][1] + dq[0][3]*dq[0][3] + dq[1][1]*dq[1][1] + dq[1][3]*dq[1][3];
        float ke = dk[0][0]*dk[0][0] + dk[0][2]*dk[0][2] + dk[1][0]*dk[1][0] + dk[1][2]*dk[1][2];
        float ko = dk[0][1]*dk[0][1] + dk[0][3]*dk[0][3] + dk[1][1]*dk[1][1] + dk[1][3]*dk[1][3];
        #pragma unroll
        for (int off = 4; off <= 16; off <<= 1) {
            qe += __shfl_xor_sync(0xffffffffu, qe, off);
            qo += __shfl_xor_sync(0xffffffffu, qo, off);
            ke += __shfl_xor_sync(0xffffffffu, ke, off);
            ko += __shfl_xor_sync(0xffffffffu, ko, off);
        }
        const float rqe = rsqrtf(qe), rqo = rsqrtf(qo);
        const float rke = rsqrtf(ke), rko = rsqrtf(ko);

        // Kn values; S partials (sum over own j)
        float k00 = dk[0][0]*rke, k01 = dk[0][1]*rko, k02 = dk[0][2]*rke, k03 = dk[0][3]*rko;
        float k10 = dk[1][0]*rke, k11 = dk[1][1]*rko, k12 = dk[1][2]*rke, k13 = dk[1][3]*rko;
        float s0 = k00 + k01, s1 = k02 + k03, s2 = k10 + k11, s3 = k12 + k13;
        s0 += __shfl_xor_sync(0xffffffffu, s0, 1); s0 += __shfl_xor_sync(0xffffffffu, s0, 2);
        s1 += __shfl_xor_sync(0xffffffffu, s1, 1); s1 += __shfl_xor_sync(0xffffffffu, s1, 2);
        s2 += __shfl_xor_sync(0xffffffffu, s2, 1); s2 += __shfl_xor_sync(0xffffffffu, s2, 2);
        s3 += __shfl_xor_sync(0xffffffffu, s3, 1); s3 += __shfl_xor_sync(0xffffffffu, s3, 2);
        S_acc0 += s0; S_acc1 += s1; S_acc2 += s2; S_acc3 += s3;

        // Kn (tf32) -> kt slice for this subtile
        {
            uint32_t* K = ktu + sub * CQ * STK;
            const int jj = w * 8 + 2 * tig;
            K[(gid)      * STK + jj]     = f2tf(k00);
            K[(gid)      * STK + jj + 1] = f2tf(k01);
            K[(gid + 8)  * STK + jj]     = f2tf(k02);
            K[(gid + 8)  * STK + jj + 1] = f2tf(k03);
            K[(gid + 16) * STK + jj]     = f2tf(k10);
            K[(gid + 16) * STK + jj + 1] = f2tf(k11);
            K[(gid + 24) * STK + jj]     = f2tf(k12);
            K[(gid + 24) * STK + jj + 1] = f2tf(k13);
        }

        // Qn -> per-warp transpose slice -> B-frags -> global
        {
            uint32_t* Q = qtu + w * 288;
            const int jl = 2 * tig;
            Q[(gid)      * 9 + jl]     = f2tf(dq[0][0] * rqe);
            Q[(gid)      * 9 + jl + 1] = f2tf(dq[0][1] * rqo);
            Q[(gid + 8)  * 9 + jl]     = f2tf(dq[0][2] * rqe);
            Q[(gid + 8)  * 9 + jl + 1] = f2tf(dq[0][3] * rqo);
            Q[(gid + 16) * 9 + jl]     = f2tf(dq[1][0] * rqe);
            Q[(gid + 16) * 9 + jl + 1] = f2tf(dq[1][1] * rqo);
            Q[(gid + 24) * 9 + jl]     = f2tf(dq[1][2] * rqe);
            Q[(gid + 24) * 9 + jl + 1] = f2tf(dq[1][3] * rqo);
            __syncwarp();
            uint4 B0v, B1v;
            B0v.x = Q[(tig)      * 9 + gid];
            B0v.y = Q[(8 + tig)  * 9 + gid];
            B0v.z = Q[(16 + tig) * 9 + gid];
            B0v.w = Q[(24 + tig) * 9 + gid];
            B1v.x = Q[(4 + tig)  * 9 + gid];
            B1v.y = Q[(12 + tig) * 9 + gid];
            B1v.z = Q[(20 + tig) * 9 + gid];
            B1v.w = Q[(28 + tig) * 9 + gid];
            const int jt = jbase >> 3;
            uint4* dst = g_qfrag + ((size_t)(b * 2048 + jt) * 32 + lane) * 2;
            dst[0] = B0v;
            dst[1] = B1v;
            __syncwarp();   // protect Q slice before next subtile rewrites it
        }
    }
    __syncthreads();        // all kt slices ready

    // S atomics
    if (tig == 0) {
        atomicAdd(&g_S[b * CQ + gid],      S_acc0);
        atomicAdd(&g_S[b * CQ + gid + 8],  S_acc1);
        atomicAdd(&g_S[b * CQ + gid + 16], S_acc2);
        atomicAdd(&g_S[b * CQ + gid + 24], S_acc3);
    }

    // ---- phase B: mpT[c][m] += x @ Kn^T over k = 256 j; fused xsum ----
    float e[2][4][4];
    #pragma unroll
    for (int ct = 0; ct < 2; ct++)
        #pragma unroll
        for (int mt = 0; mt < 4; mt++)
            #pragma unroll
            for (int q = 0; q < 4; q++) e[ct][mt][q] = 0.f;
    float sx[2][2] = {{0.f, 0.f}, {0.f, 0.f}};

    #pragma unroll 2
    for (int kk = 0; kk < 32; kk++) {
        const int sub = kk >> 3;
        const int j0  = (kk & 7) * 8;
        const uint32_t* K = ktu + sub * CQ * STK;
        uint32_t bb0[4], bb1[4];
        #pragma unroll
        for (int mt = 0; mt < 4; mt++) {
            bb0[mt] = K[(mt * 8 + gid) * STK + j0 + tig];
            bb1[mt] = K[(mt * 8 + gid) * STK + j0 + 4 + tig];
        }
        const int jg = n0 + sub * 64 + j0;
        #pragma unroll
        for (int ct = 0; ct < 2; ct++) {
            const int c0 = (2 * w + ct) * 16;
            float xa0 = __ldg(xb + (size_t)(c0 + gid)     * NN + jg + tig);
            float xa1 = __ldg(xb + (size_t)(c0 + 8 + gid) * NN + jg + tig);
            float xa2 = __ldg(xb + (size_t)(c0 + gid)     * NN + jg + 4 + tig);
            float xa3 = __ldg(xb + (size_t)(c0 + 8 + gid) * NN + jg + 4 + tig);
            sx[ct][0] += xa0 + xa2;
            sx[ct][1] += xa1 + xa3;
            uint32_t a0 = f2tf(xa0), a1 = f2tf(xa1), a2 = f2tf(xa2), a3 = f2tf(xa3);
            #pragma unroll
            for (int mt = 0; mt < 4; mt++)
                mma_tf32(e[ct][mt][0], e[ct][mt][1], e[ct][mt][2], e[ct][mt][3],
                         a0, a1, a2, a3, bb0[mt], bb1[mt]);
        }
    }

    // xsum butterflies + atomics
    #pragma unroll
    for (int ct = 0; ct < 2; ct++) {
        float v0 = sx[ct][0], v1 = sx[ct][1];
        v0 += __shfl_xor_sync(0xffffffffu, v0, 1); v0 += __shfl_xor_sync(0xffffffffu, v0, 2);
        v1 += __shfl_xor_sync(0xffffffffu, v1, 1); v1 += __shfl_xor_sync(0xffffffffu, v1, 2);
        if (tig == 0) {
            const int c0 = (2 * w + ct) * 16;
            atomicAdd(&g_xsum[b * CC + c0 + gid],     v0);
            atomicAdd(&g_xsum[b * CC + c0 + 8 + gid], v1);
        }
    }
    // mpT atomics
    float* mpb = &g_mpT[b * CC * CQ];
    #pragma unroll
    for (int ct = 0; ct < 2; ct++) {
        const int c0 = (2 * w + ct) * 16;
        #pragma unroll
        for (int mt = 0; mt < 4; mt++) {
            const int m0 = mt * 8 + 2 * tig;
            atomicAdd(&mpb[(c0 + gid) * CQ + m0],         e[ct][mt][0]);
            atomicAdd(&mpb[(c0 + gid) * CQ + m0 + 1],     e[ct][mt][1]);
            atomicAdd(&mpb[(c0 + 8 + gid) * CQ + m0],     e[ct][mt][2]);
            atomicAdd(&mpb[(c0 + 8 + gid) * CQ + m0 + 1], e[ct][mt][3]);
        }
    }
}

// ---------------- kernel 2: matrix = mp @ Wv^T + bv (x) S ; vsum; fragments -
__global__ void __launch_bounds__(256)
k_mat(const float* __restrict__ Wv, const float* __restrict__ bv) {
    __shared__ float mpT[CC * CQ];   // [c][m]
    __shared__ float xs_s[CC];
    __shared__ float S_s[CQ];
    const int b = blockIdx.x, tid = threadIdx.x;

    for (int idx = tid; idx < CC * CQ; idx += 256)
        mpT[idx] = g_mpT[b * CC * CQ + idx];
    xs_s[tid] = g_xsum[b * CC + tid];
    if (tid < 32) S_s[tid] = g_S[b * CQ + tid];
    __syncthreads();

    const int cp = tid;
    float bvv = __ldg(&bv[cp]);
    float accm[32];
    #pragma unroll
    for (int m = 0; m < 32; m++) accm[m] = bvv * S_s[m];
    float vs = (float)NN * bvv;

    const float* wrow = Wv + cp * CC;
    for (int c = 0; c < CC; ++c) {
        float wv = __ldg(&wrow[c]);
        vs += wv * xs_s[c];
        const float4* mr = (const float4*)&mpT[c * CQ];
        #pragma unroll
        for (int q = 0; q < 8; q++) {
            float4 v = mr[q];
            accm[q * 4 + 0] += v.x * wv; accm[q * 4 + 1] += v.y * wv;
            accm[q * 4 + 2] += v.z * wv; accm[q * 4 + 3] += v.w * wv;
        }
    }
    g_vsum[b * CC + cp] = vs;

    const int ct = cp >> 4, cl = cp & 15;
    const int gid = cl & 7, hi = cl >> 3;
    #pragma unroll
    for (int m = 0; m < 32; m++) {
        int kk = m >> 3, tig = m & 3, half = (m >> 2) & 1;
        int elem = hi + 2 * half;
        g_mfrag[((((b * 16 + ct) * 4 + kk) * 32) + gid * 4 + tig) * 4 + elem] = f2tf(accm[m]);
    }
}

// ---------------- kernel 3: streaming epilogue (no smem, no barriers) -------
__global__ void __launch_bounds__(256)
k_pass2(const float* __restrict__ x, const float* __restrict__ gamma,
        float* __restrict__ out) {
    const int tid = threadIdx.x;
    const int w = tid >> 5, lane = tid & 31, gid = lane >> 2, tig = lane & 3;
    const int b  = blockIdx.x >> 8;
    const int jt = (blockIdx.x & 255) * 8 + w;
    const int n0 = jt * 8;
    const float gm = __ldg(&gamma[0]);

    // Qn B-frags (precomputed by pass1)
    const uint4* qf = g_qfrag + ((size_t)(b * 2048 + jt) * 32 + lane) * 2;
    uint4 B0v = __ldg(qf);
    uint4 B1v = __ldg(qf + 1);
    uint32_t B0[4] = {B0v.x, B0v.y, B0v.z, B0v.w};
    uint32_t B1[4] = {B1v.x, B1v.y, B1v.z, B1v.w};

    // tailor: tl(j=gid) = sum_m Qn[m][j] * (S[m]+eps)
    float tl = 0.f;
    #pragma unroll
    for (int kk = 0; kk < 4; kk++) {
        float se0 = __ldg(&g_S[b * CQ + 8 * kk + tig])     + EPSV;
        float se1 = __ldg(&g_S[b * CQ + 8 * kk + 4 + tig]) + EPSV;
        tl += __uint_as_float(B0[kk]) * se0 + __uint_as_float(B1[kk]) * se1;
    }
    tl += __shfl_xor_sync(0xffffffffu, tl, 1);
    tl += __shfl_xor_sync(0xffffffffu, tl, 2);
    const float gt_l = gm / (16384.f + tl);
    const float gt_e = __shfl_sync(0xffffffffu, gt_l, 8 * tig);      // j = 2*tig
    const float gt_o = __shfl_sync(0xffffffffu, gt_l, 8 * tig + 4);  // j = 2*tig+1

    const float* xp = x   + (size_t)b * CC * NN + n0;
    float*       op = out + (size_t)b * CC * NN + n0;
    const uint4* mf = (const uint4*)g_mfrag + (size_t)b * 16 * 4 * 32 + lane;
    const float* vs = g_vsum + b * CC;
    const int jj = 2 * tig;

    #pragma unroll 4
    for (int ct = 0; ct < 16; ct++) {
        const uint4* base = mf + ct * 128;
        uint4 A0 = __ldg(base);
        uint4 A1 = __ldg(base + 32);
        uint4 A2 = __ldg(base + 64);
        uint4 A3 = __ldg(base + 96);
        float e0 = 0.f, e1 = 0.f, e2 = 0.f, e3 = 0.f;
        mma_tf32(e0, e1, e2, e3, A0.x, A0.y, A0.z, A0.w, B0[0], B1[0]);
        mma_tf32(e0, e1, e2, e3, A1.x, A1.y, A1.z, A1.w, B0[1], B1[1]);
        mma_tf32(e0, e1, e2, e3, A2.x, A2.y, A2.z, A2.w, B0[2], B1[2]);
        mma_tf32(e0, e1, e2, e3, A3.x, A3.y, A3.z, A3.w, B0[3], B1[3]);

        const int c1 = ct * 16 + gid;
        const int c2 = c1 + 8;
        float2 x1 = *(const float2*)(xp + (size_t)c1 * NN + jj);
        float2 x2 = *(const float2*)(xp + (size_t)c2 * NN + jj);
        const float v1 = __ldg(&vs[c1]), v2 = __ldg(&vs[c2]);
        float2 o1, o2;
        o1.x = x1.x + gt_e * (v1 + e0);
        o1.y = x1.y + gt_o * (v1 + e1);
        o2.x = x2.x + gt_e * (v2 + e2);
        o2.y = x2.y + gt_o * (v2 + e3);
        *(float2*)(op + (size_t)c1 * NN + jj) = o1;
        *(float2*)(op + (size_t)c2 * NN + jj) = o2;
    }
}

// ---------------- launch --------------------------------------------------
extern "C" void kernel_launch(void* const* d_in, const int* in_sizes, int n_in,
                              void* d_out, int out_size) {
    const float* x     = (const float*)d_in[0];
    const float* Wq    = (const float*)d_in[1];
    const float* bq    = (const float*)d_in[2];
    const float* Wk    = (const float*)d_in[3];
    const float* bk    = (const float*)d_in[4];
    const float* Wv    = (const float*)d_in[5];
    const float* bv    = (const float*)d_in[6];
    const float* gamma = (const float*)d_in[7];
    float* out = (float*)d_out;

    k_prep<<<256, 256>>>(Wq, Wk);
    k_pass1<<<BB * (NN / T1), 256>>>(x, bq, bk);       // 512 blocks
    k_mat<<<BB, 256>>>(Wv, bv);
    k_pass2<<<BB * 256, 256>>>(x, gamma, out);          // 2048 blocks, warp-per-8j
}

// round 8
// speedup vs baseline: 1.0549x; 1.0549x over previous
#include <cuda_runtime.h>
#include <cstdint>

#define BB   8
#define CC   256
#define CQ   32
#define NN   16384
#define EPSV 1e-6f
#define ST   36             // stride mod 32 = 4: conflict-free A-frag (gid*4+tig) patterns
#define CH   32             // j per chunk
#define T1   128            // pass1 j per block

// ---------------- scratch (device globals) ---------------------------------
__device__ __align__(16) uint32_t g_WtF[4 * 32 * 32 * 4];   // tf32 A-frags; 0-1 = Wq, 2-3 = Wk
__device__ float g_mpT[BB * CC * CQ];                       // (Kn @ x^T)^T : [b][c][m]
__device__ float g_S[BB * CQ];                              // sum_n Kn
__device__ float g_xsum[BB * CC];                           // sum_n x
__device__ __align__(16) uint32_t g_mfrag[BB * 16 * 4 * 32 * 4]; // matT tf32 A-frags
__device__ float g_vsum[BB * CC];                           // value_sum
__device__ __align__(16) uint4 g_qfrag[(size_t)BB * 2048 * 32 * 2]; // Qn B-frags [b][jt][lane][2]

__device__ __forceinline__ uint32_t f2tf(float f) {
    uint32_t r; asm("cvt.rna.tf32.f32 %0, %1;" : "=r"(r) : "f"(f)); return r;
}

__device__ __forceinline__ void mma_tf32(float& d0, float& d1, float& d2, float& d3,
                                         uint32_t a0, uint32_t a1, uint32_t a2, uint32_t a3,
                                         uint32_t b0, uint32_t b1) {
    asm volatile(
        "mma.sync.aligned.m16n8k8.row.col.f32.tf32.tf32.f32 "
        "{%0,%1,%2,%3},{%4,%5,%6,%7},{%8,%9},{%0,%1,%2,%3};"
        : "+f"(d0), "+f"(d1), "+f"(d2), "+f"(d3)
        : "r"(a0), "r"(a1), "r"(a2), "r"(a3), "r"(b0), "r"(b1));
}

__device__ __forceinline__ void cp16(float* dst, const float* src) {
    uint32_t d = (uint32_t)__cvta_generic_to_shared(dst);
    asm volatile("cp.async.cg.shared.global [%0], [%1], 16;" :: "r"(d), "l"(src));
}
__device__ __forceinline__ void cp_commit() { asm volatile("cp.async.commit_group;"); }
__device__ __forceinline__ void cp_wait0()  { asm volatile("cp.async.wait_group 0;"); }

// stage one 32-j chunk (256 c x 32 j fp32): 8 x 16B per thread
__device__ __forceinline__ void stage_issue(float* buf, const float* xb, int nb, int tid) {
    #pragma unroll
    for (int it = 0; it < 8; it++) {
        int idx = tid + it * 256;
        int c = idx >> 3, q = idx & 7;
        cp16(&buf[c * ST + 4 * q], xb + (size_t)c * NN + nb + 4 * q);
    }
}

// ---------------- kernel 0: zero accumulators + build tf32 W-fragments -----
__global__ void k_prep(const float* __restrict__ Wq, const float* __restrict__ Wk) {
    int idx = blockIdx.x * blockDim.x + threadIdx.x;      // 65536 threads
    if (idx < BB * CC * CQ) g_mpT[idx] = 0.f;
    if (idx < 16384) {
        int f    = idx & 3;
        int lane = (idx >> 2) & 31;
        int kk   = (idx >> 7) & 31;
        int wo   = idx >> 12;
        int gid = lane >> 2, tig = lane & 3;
        int o = (wo & 1) * 16 + gid + (f & 1) * 8;
        int c = kk * 8 + tig + (f >> 1) * 4;
        float v = (wo < 2) ? Wq[o * CC + c] : Wk[o * CC + c];
        g_WtF[idx] = f2tf(v);
    }
    if (idx < BB * CC) g_xsum[idx] = 0.f;
    if (idx < BB * CQ) g_S[idx] = 0.f;
}

// ---------------- kernel 1: staged Q+K proj + Qn frags + S + xsum + mpT ----
__global__ void __launch_bounds__(256, 2)
k_pass1(const float* __restrict__ x, const float* __restrict__ bq,
        const float* __restrict__ bk) {
    extern __shared__ float sh[];
    float* xsb[2] = { sh, sh + CC * ST };                 // 2 x 36,864 B
    float* ktb[2] = { sh + 2 * CC * ST, sh + 2 * CC * ST + CQ * ST }; // 2 x 4,608 B
    float* qt = sh + 2 * CC * ST + 2 * CQ * ST;           // 4 x 288 floats

    const int b   = blockIdx.x >> 7;
    const int n0  = (blockIdx.x & 127) * T1;
    const int tid = threadIdx.x;
    const int w = tid >> 5, lane = tid & 31, gid = lane >> 2, tig = lane & 3;
    const int jgrp = w & 3;          // which 8-j group within the chunk
    const int isK  = w >> 2;         // 0: Q-warp, 1: K-warp
    const int jw   = jgrp * 8;
    const float* xb = x + (size_t)b * CC * NN;

    const float* bias = isK ? bk : bq;
    const float bi0 = __ldg(&bias[gid]),      bi1 = __ldg(&bias[gid + 8]);
    const float bi2 = __ldg(&bias[gid + 16]), bi3 = __ldg(&bias[gid + 24]);

    const uint4* Wt = (const uint4*)g_WtF + (isK ? 2048 : 0) + lane;

    float e[2][4][4];
    #pragma unroll
    for (int ct = 0; ct < 2; ct++)
        #pragma unroll
        for (int mt = 0; mt < 4; mt++)
            #pragma unroll
            for (int q = 0; q < 4; q++) e[ct][mt][q] = 0.f;
    float sx[2][2] = {{0.f, 0.f}, {0.f, 0.f}};
    float S_acc0 = 0.f, S_acc1 = 0.f, S_acc2 = 0.f, S_acc3 = 0.f;

    stage_issue(xsb[0], xb, n0, tid);
    cp_commit();

    #pragma unroll 1
    for (int ch = 0; ch < 4; ch++) {
        cp_wait0();
        __syncthreads();                       // xs[ch&1] ready; buffers free
        if (ch < 3) {
            stage_issue(xsb[(ch + 1) & 1], xb, n0 + (ch + 1) * CH, tid);
            cp_commit();
        }
        const float* X = xsb[ch & 1];
        uint32_t* K = (uint32_t*)ktb[ch & 1];

        // ---- proj: this warp's 8 j, 32 o rows, Q or K ----
        float d[2][4];
        #pragma unroll
        for (int t = 0; t < 2; t++)
            #pragma unroll
            for (int q = 0; q < 4; q++) d[t][q] = 0.f;
        #pragma unroll 4
        for (int kk = 0; kk < 32; kk++) {
            const int c0 = kk * 8;
            uint32_t v0 = f2tf(X[(c0 + tig) * ST + jw + gid]);
            uint32_t v1 = f2tf(X[(c0 + 4 + tig) * ST + jw + gid]);
            uint4 a = Wt[kk * 32];
            mma_tf32(d[0][0], d[0][1], d[0][2], d[0][3], a.x, a.y, a.z, a.w, v0, v1);
            a = Wt[1024 + kk * 32];
            mma_tf32(d[1][0], d[1][1], d[1][2], d[1][3], a.x, a.y, a.z, a.w, v0, v1);
        }
        d[0][0] += bi0; d[0][1] += bi0; d[0][2] += bi1; d[0][3] += bi1;
        d[1][0] += bi2; d[1][1] += bi2; d[1][2] += bi3; d[1][3] += bi3;

        // column norms (butterfly over gid bits)
        float ss_e = d[0][0]*d[0][0] + d[0][2]*d[0][2] + d[1][0]*d[1][0] + d[1][2]*d[1][2];
        float ss_o = d[0][1]*d[0][1] + d[0][3]*d[0][3] + d[1][1]*d[1][1] + d[1][3]*d[1][3];
        #pragma unroll
        for (int off = 4; off <= 16; off <<= 1) {
            ss_e += __shfl_xor_sync(0xffffffffu, ss_e, off);
            ss_o += __shfl_xor_sync(0xffffffffu, ss_o, off);
        }
        const float rne = rsqrtf(ss_e), rno = rsqrtf(ss_o);

        if (isK) {
            // Kn values, S partials, write kt slice
            float k00 = d[0][0]*rne, k01 = d[0][1]*rno, k02 = d[0][2]*rne, k03 = d[0][3]*rno;
            float k10 = d[1][0]*rne, k11 = d[1][1]*rno, k12 = d[1][2]*rne, k13 = d[1][3]*rno;
            float s0 = k00 + k01, s1 = k02 + k03, s2 = k10 + k11, s3 = k12 + k13;
            s0 += __shfl_xor_sync(0xffffffffu, s0, 1); s0 += __shfl_xor_sync(0xffffffffu, s0, 2);
            s1 += __shfl_xor_sync(0xffffffffu, s1, 1); s1 += __shfl_xor_sync(0xffffffffu, s1, 2);
            s2 += __shfl_xor_sync(0xffffffffu, s2, 1); s2 += __shfl_xor_sync(0xffffffffu, s2, 2);
            s3 += __shfl_xor_sync(0xffffffffu, s3, 1); s3 += __shfl_xor_sync(0xffffffffu, s3, 2);
            S_acc0 += s0; S_acc1 += s1; S_acc2 += s2; S_acc3 += s3;

            const int jj = jw + 2 * tig;
            K[(gid)      * ST + jj]     = f2tf(k00);
            K[(gid)      * ST + jj + 1] = f2tf(k01);
            K[(gid + 8)  * ST + jj]     = f2tf(k02);
            K[(gid + 8)  * ST + jj + 1] = f2tf(k03);
            K[(gid + 16) * ST + jj]     = f2tf(k10);
            K[(gid + 16) * ST + jj + 1] = f2tf(k11);
            K[(gid + 24) * ST + jj]     = f2tf(k12);
            K[(gid + 24) * ST + jj + 1] = f2tf(k13);
        } else {
            // Qn -> transpose scratch -> B-frags -> global
            uint32_t* Q = (uint32_t*)(qt + w * 288);
            const int jl = 2 * tig;
            Q[(gid)      * 9 + jl]     = f2tf(d[0][0] * rne);
            Q[(gid)      * 9 + jl + 1] = f2tf(d[0][1] * rno);
            Q[(gid + 8)  * 9 + jl]     = f2tf(d[0][2] * rne);
            Q[(gid + 8)  * 9 + jl + 1] = f2tf(d[0][3] * rno);
            Q[(gid + 16) * 9 + jl]     = f2tf(d[1][0] * rne);
            Q[(gid + 16) * 9 + jl + 1] = f2tf(d[1][1] * rno);
            Q[(gid + 24) * 9 + jl]     = f2tf(d[1][2] * rne);
            Q[(gid + 24) * 9 + jl + 1] = f2tf(d[1][3] * rno);
            __syncwarp();
            uint4 B0v, B1v;
            B0v.x = Q[(tig)      * 9 + gid];
            B0v.y = Q[(8 + tig)  * 9 + gid];
            B0v.z = Q[(16 + tig) * 9 + gid];
            B0v.w = Q[(24 + tig) * 9 + gid];
            B1v.x = Q[(4 + tig)  * 9 + gid];
            B1v.y = Q[(12 + tig) * 9 + gid];
            B1v.z = Q[(20 + tig) * 9 + gid];
            B1v.w = Q[(28 + tig) * 9 + gid];
            const int jt = (n0 + ch * CH + jw) >> 3;
            uint4* dst = g_qfrag + ((size_t)(b * 2048 + jt) * 32 + lane) * 2;
            dst[0] = B0v;
            dst[1] = B1v;
        }
        __syncthreads();                       // kt slice complete

        // ---- mpT: e[c][m] += chunk @ Kn^T (k = 32); fused xsum ----
        #pragma unroll
        for (int kk = 0; kk < 4; kk++) {
            const int j0 = kk * 8;
            uint32_t bb0[4], bb1[4];
            #pragma unroll
            for (int mt = 0; mt < 4; mt++) {
                bb0[mt] = K[(mt * 8 + gid) * ST + j0 + tig];
                bb1[mt] = K[(mt * 8 + gid) * ST + j0 + 4 + tig];
            }
            #pragma unroll
            for (int ct = 0; ct < 2; ct++) {
                const int c0 = 32 * w + 16 * ct;
                float xa0 = X[(c0 + gid)     * ST + j0 + tig];
                float xa1 = X[(c0 + 8 + gid) * ST + j0 + tig];
                float xa2 = X[(c0 + gid)     * ST + j0 + 4 + tig];
                float xa3 = X[(c0 + 8 + gid) * ST + j0 + 4 + tig];
                sx[ct][0] += xa0 + xa2;
                sx[ct][1] += xa1 + xa3;
                uint32_t a0 = f2tf(xa0), a1 = f2tf(xa1), a2 = f2tf(xa2), a3 = f2tf(xa3);
                #pragma unroll
                for (int mt = 0; mt < 4; mt++)
                    mma_tf32(e[ct][mt][0], e[ct][mt][1], e[ct][mt][2], e[ct][mt][3],
                             a0, a1, a2, a3, bb0[mt], bb1[mt]);
            }
        }
        // no end sync: next top sync protects buffers
    }

    // ---- final global reductions ----
    if (isK && tig == 0) {
        atomicAdd(&g_S[b * CQ + gid],      S_acc0);
        atomicAdd(&g_S[b * CQ + gid + 8],  S_acc1);
        atomicAdd(&g_S[b * CQ + gid + 16], S_acc2);
        atomicAdd(&g_S[b * CQ + gid + 24], S_acc3);
    }
    #pragma unroll
    for (int ct = 0; ct < 2; ct++) {
        float v0 = sx[ct][0], v1 = sx[ct][1];
        v0 += __shfl_xor_sync(0xffffffffu, v0, 1); v0 += __shfl_xor_sync(0xffffffffu, v0, 2);
        v1 += __shfl_xor_sync(0xffffffffu, v1, 1); v1 += __shfl_xor_sync(0xffffffffu, v1, 2);
        if (tig == 0) {
            const int c0 = 32 * w + 16 * ct;
            atomicAdd(&g_xsum[b * CC + c0 + gid],     v0);
            atomicAdd(&g_xsum[b * CC + c0 + 8 + gid], v1);
        }
    }
    float* mpb = &g_mpT[b * CC * CQ];
    #pragma unroll
    for (int ct = 0; ct < 2; ct++) {
        const int c0 = 32 * w + 16 * ct;
        #pragma unroll
        for (int mt = 0; mt < 4; mt++) {
            const int m0 = mt * 8 + 2 * tig;
            atomicAdd(&mpb[(c0 + gid) * CQ + m0],         e[ct][mt][0]);
            atomicAdd(&mpb[(c0 + gid) * CQ + m0 + 1],     e[ct][mt][1]);
            atomicAdd(&mpb[(c0 + 8 + gid) * CQ + m0],     e[ct][mt][2]);
            atomicAdd(&mpb[(c0 + 8 + gid) * CQ + m0 + 1], e[ct][mt][3]);
        }
    }
}

// ---------------- kernel 2: matrix = mp @ Wv^T + bv (x) S ; vsum; fragments -
__global__ void __launch_bounds__(256)
k_mat(const float* __restrict__ Wv, const float* __restrict__ bv) {
    __shared__ float mpT[CC * CQ];   // [c][m]
    __shared__ float xs_s[CC];
    __shared__ float S_s[CQ];
    const int b = blockIdx.x, tid = threadIdx.x;

    for (int idx = tid; idx < CC * CQ; idx += 256)
        mpT[idx] = g_mpT[b * CC * CQ + idx];
    xs_s[tid] = g_xsum[b * CC + tid];
    if (tid < 32) S_s[tid] = g_S[b * CQ + tid];
    __syncthreads();

    const int cp = tid;
    float bvv = __ldg(&bv[cp]);
    float accm[32];
    #pragma unroll
    for (int m = 0; m < 32; m++) accm[m] = bvv * S_s[m];
    float vs = (float)NN * bvv;

    const float* wrow = Wv + cp * CC;
    for (int c = 0; c < CC; ++c) {
        float wv = __ldg(&wrow[c]);
        vs += wv * xs_s[c];
        const float4* mr = (const float4*)&mpT[c * CQ];
        #pragma unroll
        for (int q = 0; q < 8; q++) {
            float4 v = mr[q];
            accm[q * 4 + 0] += v.x * wv; accm[q * 4 + 1] += v.y * wv;
            accm[q * 4 + 2] += v.z * wv; accm[q * 4 + 3] += v.w * wv;
        }
    }
    g_vsum[b * CC + cp] = vs;

    const int ct = cp >> 4, cl = cp & 15;
    const int gid = cl & 7, hi = cl >> 3;
    #pragma unroll
    for (int m = 0; m < 32; m++) {
        int kk = m >> 3, tig = m & 3, half = (m >> 2) & 1;
        int elem = hi + 2 * half;
        g_mfrag[((((b * 16 + ct) * 4 + kk) * 32) + gid * 4 + tig) * 4 + elem] = f2tf(accm[m]);
    }
}

// ---------------- kernel 3: streaming epilogue, 2 j-tiles per warp ----------
__global__ void __launch_bounds__(256)
k_pass2(const float* __restrict__ x, const float* __restrict__ gamma,
        float* __restrict__ out) {
    const int tid = threadIdx.x;
    const int w = tid >> 5, lane = tid & 31, gid = lane >> 2, tig = lane & 3;
    const int b   = blockIdx.x >> 7;
    const int jt0 = (blockIdx.x & 127) * 16 + w * 2;
    const int n0  = jt0 * 8;
    const float gm = __ldg(&gamma[0]);

    // Qn B-frags for both j-tiles
    const uint4* qf = g_qfrag + ((size_t)(b * 2048 + jt0) * 32 + lane) * 2;
    uint4 P0 = __ldg(qf),      P1 = __ldg(qf + 1);
    uint4 R0 = __ldg(qf + 64), R1 = __ldg(qf + 65);
    uint32_t PB0[4] = {P0.x, P0.y, P0.z, P0.w};
    uint32_t PB1[4] = {P1.x, P1.y, P1.z, P1.w};
    uint32_t RB0[4] = {R0.x, R0.y, R0.z, R0.w};
    uint32_t RB1[4] = {R1.x, R1.y, R1.z, R1.w};

    // tailor for both tiles
    float tl0 = 0.f, tl1 = 0.f;
    #pragma unroll
    for (int kk = 0; kk < 4; kk++) {
        float se0 = __ldg(&g_S[b * CQ + 8 * kk + tig])     + EPSV;
        float se1 = __ldg(&g_S[b * CQ + 8 * kk + 4 + tig]) + EPSV;
        tl0 += __uint_as_float(PB0[kk]) * se0 + __uint_as_float(PB1[kk]) * se1;
        tl1 += __uint_as_float(RB0[kk]) * se0 + __uint_as_float(RB1[kk]) * se1;
    }
    tl0 += __shfl_xor_sync(0xffffffffu, tl0, 1);
    tl0 += __shfl_xor_sync(0xffffffffu, tl0, 2);
    tl1 += __shfl_xor_sync(0xffffffffu, tl1, 1);
    tl1 += __shfl_xor_sync(0xffffffffu, tl1, 2);
    const float g0 = gm / (16384.f + tl0);
    const float g1 = gm / (16384.f + tl1);
    const float gt0e = __shfl_sync(0xffffffffu, g0, 8 * tig);
    const float gt0o = __shfl_sync(0xffffffffu, g0, 8 * tig + 4);
    const float gt1e = __shfl_sync(0xffffffffu, g1, 8 * tig);
    const float gt1o = __shfl_sync(0xffffffffu, g1, 8 * tig + 4);

    const float* xp = x   + (size_t)b * CC * NN + n0;
    float*       op = out + (size_t)b * CC * NN + n0;
    const uint4* mf = (const uint4*)g_mfrag + (size_t)b * 16 * 4 * 32 + lane;
    const float* vs = g_vsum + b * CC;
    const int jj = 2 * tig;

    #pragma unroll 4
    for (int ct = 0; ct < 16; ct++) {
        const uint4* base = mf + ct * 128;
        uint4 A0 = __ldg(base);
        uint4 A1 = __ldg(base + 32);
        uint4 A2 = __ldg(base + 64);
        uint4 A3 = __ldg(base + 96);
        float e0 = 0.f, e1 = 0.f, e2 = 0.f, e3 = 0.f;   // tile0
        float f0 = 0.f, f1 = 0.f, f2 = 0.f, f3 = 0.f;   // tile1
        mma_tf32(e0, e1, e2, e3, A0.x, A0.y, A0.z, A0.w, PB0[0], PB1[0]);
        mma_tf32(f0, f1, f2, f3, A0.x, A0.y, A0.z, A0.w, RB0[0], RB1[0]);
        mma_tf32(e0, e1, e2, e3, A1.x, A1.y, A1.z, A1.w, PB0[1], PB1[1]);
        mma_tf32(f0, f1, f2, f3, A1.x, A1.y, A1.z, A1.w, RB0[1], RB1[1]);
        mma_tf32(e0, e1, e2, e3, A2.x, A2.y, A2.z, A2.w, PB0[2], PB1[2]);
        mma_tf32(f0, f1, f2, f3, A2.x, A2.y, A2.z, A2.w, RB0[2], RB1[2]);
        mma_tf32(e0, e1, e2, e3, A3.x, A3.y, A3.z, A3.w, PB0[3], PB1[3]);
        mma_tf32(f0, f1, f2, f3, A3.x, A3.y, A3.z, A3.w, RB0[3], RB1[3]);

        const int c1 = ct * 16 + gid;
        const int c2 = c1 + 8;
        const float v1 = __ldg(&vs[c1]), v2 = __ldg(&vs[c2]);
        float2 x10 = *(const float2*)(xp + (size_t)c1 * NN + jj);
        float2 x11 = *(const float2*)(xp + (size_t)c1 * NN + 8 + jj);
        float2 x20 = *(const float2*)(xp + (size_t)c2 * NN + jj);
        float2 x21 = *(const float2*)(xp + (size_t)c2 * NN + 8 + jj);
        float2 o10, o11, o20, o21;
        o10.x = x10.x + gt0e * (v1 + e0);
        o10.y = x10.y + gt0o * (v1 + e1);
        o11.x = x11.x + gt1e * (v1 + f0);
        o11.y = x11.y + gt1o * (v1 + f1);
        o20.x = x20.x + gt0e * (v1 * 0.f + v2 + e2);
        o20.y = x20.y + gt0o * (v2 + e3);
        o21.x = x21.x + gt1e * (v2 + f2);
        o21.y = x21.y + gt1o * (v2 + f3);
        __stcs((float2*)(op + (size_t)c1 * NN + jj),     o10);
        __stcs((float2*)(op + (size_t)c1 * NN + 8 + jj), o11);
        __stcs((float2*)(op + (size_t)c2 * NN + jj),     o20);
        __stcs((float2*)(op + (size_t)c2 * NN + 8 + jj), o21);
    }
}

// ---------------- launch --------------------------------------------------
extern "C" void kernel_launch(void* const* d_in, const int* in_sizes, int n_in,
                              void* d_out, int out_size) {
    const float* x     = (const float*)d_in[0];
    const float* Wq    = (const float*)d_in[1];
    const float* bq    = (const float*)d_in[2];
    const float* Wk    = (const float*)d_in[3];
    const float* bk    = (const float*)d_in[4];
    const float* Wv    = (const float*)d_in[5];
    const float* bv    = (const float*)d_in[6];
    const float* gamma = (const float*)d_in[7];
    float* out = (float*)d_out;

    const int sh1 = (2 * CC * ST + 2 * CQ * ST + 4 * 288) * (int)sizeof(float); // 87,552 B
    cudaFuncSetAttribute(k_pass1, cudaFuncAttributeMaxDynamicSharedMemorySize, sh1);

    k_prep<<<256, 256>>>(Wq, Wk);
    k_pass1<<<BB * (NN / T1), 256, sh1>>>(x, bq, bk);       // 1024 blocks
    k_mat<<<BB, 256>>>(Wv, bv);
    k_pass2<<<BB * 128, 256>>>(x, gamma, out);               // 1024 blocks, warp per 16 j
}

// round 9
// speedup vs baseline: 1.1446x; 1.0850x over previous
#include <cuda_runtime.h>
#include <cstdint>

#define BB   8
#define CC   256
#define CQ   32
#define NN   16384
#define EPSV 1e-6f

// ---------------- scratch (device globals) ---------------------------------
__device__ __align__(16) uint32_t g_WtF[4 * 32 * 32 * 4];   // tf32 A-frags; 0-1 = Wq, 2-3 = Wk
__device__ float g_mpT[BB * CC * CQ];                       // (Kn @ x^T)^T : [b][c][m]
__device__ float g_S[BB * CQ];                              // sum_n Kn
__device__ float g_xsum[BB * CC];                           // sum_n x
__device__ __align__(16) uint32_t g_mfrag[BB * 16 * 4 * 32 * 4]; // matT tf32 A-frags
__device__ float g_vsum[BB * CC];                           // value_sum
__device__ __align__(16) uint4 g_qfrag[(size_t)BB * 2048 * 32 * 2]; // Qn B-frags [b][jt][lane][2]
__device__ __align__(16) uint2 g_kfrag[(size_t)BB * 2048 * 4 * 32]; // Kn B-frags [b][jt][mt][lane]

__device__ __forceinline__ uint32_t f2tf(float f) {
    uint32_t r; asm("cvt.rna.tf32.f32 %0, %1;" : "=r"(r) : "f"(f)); return r;
}

__device__ __forceinline__ void mma_tf32(float& d0, float& d1, float& d2, float& d3,
                                         uint32_t a0, uint32_t a1, uint32_t a2, uint32_t a3,
                                         uint32_t b0, uint32_t b1) {
    asm volatile(
        "mma.sync.aligned.m16n8k8.row.col.f32.tf32.tf32.f32 "
        "{%0,%1,%2,%3},{%4,%5,%6,%7},{%8,%9},{%0,%1,%2,%3};"
        : "+f"(d0), "+f"(d1), "+f"(d2), "+f"(d3)
        : "r"(a0), "r"(a1), "r"(a2), "r"(a3), "r"(b0), "r"(b1));
}

// ---------------- kernel 0: zero accumulators + build tf32 W-fragments -----
__global__ void k_prep(const float* __restrict__ Wq, const float* __restrict__ Wk) {
    int idx = blockIdx.x * blockDim.x + threadIdx.x;      // 65536 threads
    if (idx < BB * CC * CQ) g_mpT[idx] = 0.f;
    if (idx < 16384) {
        int f    = idx & 3;
        int lane = (idx >> 2) & 31;
        int kk   = (idx >> 7) & 31;
        int wo   = idx >> 12;
        int gid = lane >> 2, tig = lane & 3;
        int o = (wo & 1) * 16 + gid + (f & 1) * 8;
        int c = kk * 8 + tig + (f >> 1) * 4;
        float v = (wo < 2) ? Wq[o * CC + c] : Wk[o * CC + c];
        g_WtF[idx] = f2tf(v);
    }
    if (idx < BB * CC) g_xsum[idx] = 0.f;
    if (idx < BB * CQ) g_S[idx] = 0.f;
}

// ---------------- kernel 1: Q+K proj, streaming, warp = 8 j -----------------
__global__ void __launch_bounds__(256)
k_qk(const float* __restrict__ x, const float* __restrict__ bq,
     const float* __restrict__ bk) {
    __shared__ float qts[8 * 288];       // per-warp transpose scratch (no block sync)

    const int tid = threadIdx.x;
    const int w = tid >> 5, lane = tid & 31, gid = lane >> 2, tig = lane & 3;
    const int b  = blockIdx.x >> 8;
    const int jbase = (blockIdx.x & 255) * 64 + w * 8;     // warp's 8 global j
    const int jt = jbase >> 3;
    const float* xb = x + (size_t)b * CC * NN;
    const float* xp = xb + (size_t)tig * NN + jbase + gid;

    const float bq0 = __ldg(&bq[gid]),      bq1 = __ldg(&bq[gid + 8]);
    const float bq2 = __ldg(&bq[gid + 16]), bq3 = __ldg(&bq[gid + 24]);
    const float bk0 = __ldg(&bk[gid]),      bk1 = __ldg(&bk[gid + 8]);
    const float bk2 = __ldg(&bk[gid + 16]), bk3 = __ldg(&bk[gid + 24]);

    const uint4* Wt = (const uint4*)g_WtF + lane;

    float dq[2][4], dk[2][4];
    #pragma unroll
    for (int t = 0; t < 2; t++)
        #pragma unroll
        for (int q = 0; q < 4; q++) { dq[t][q] = 0.f; dk[t][q] = 0.f; }

    #pragma unroll 4
    for (int kk = 0; kk < 32; kk++) {
        uint32_t b0 = f2tf(__ldg(xp + (size_t)(8 * kk) * NN));
        uint32_t b1 = f2tf(__ldg(xp + (size_t)(8 * kk + 4) * NN));
        uint4 a;
        a = Wt[kk * 32];
        mma_tf32(dq[0][0], dq[0][1], dq[0][2], dq[0][3], a.x, a.y, a.z, a.w, b0, b1);
        a = Wt[1024 + kk * 32];
        mma_tf32(dq[1][0], dq[1][1], dq[1][2], dq[1][3], a.x, a.y, a.z, a.w, b0, b1);
        a = Wt[2048 + kk * 32];
        mma_tf32(dk[0][0], dk[0][1], dk[0][2], dk[0][3], a.x, a.y, a.z, a.w, b0, b1);
        a = Wt[3072 + kk * 32];
        mma_tf32(dk[1][0], dk[1][1], dk[1][2], dk[1][3], a.x, a.y, a.z, a.w, b0, b1);
    }
    dq[0][0] += bq0; dq[0][1] += bq0; dq[0][2] += bq1; dq[0][3] += bq1;
    dq[1][0] += bq2; dq[1][1] += bq2; dq[1][2] += bq3; dq[1][3] += bq3;
    dk[0][0] += bk0; dk[0][1] += bk0; dk[0][2] += bk1; dk[0][3] += bk1;
    dk[1][0] += bk2; dk[1][1] += bk2; dk[1][2] += bk3; dk[1][3] += bk3;

    // column norms (butterfly over gid bits)
    float qe = dq[0][0]*dq[0][0] + dq[0][2]*dq[0][2] + dq[1][0]*dq[1][0] + dq[1][2]*dq[1][2];
    float qo = dq[0][1]*dq[0][1] + dq[0][3]*dq[0][3] + dq[1][1]*dq[1][1] + dq[1][3]*dq[1][3];
    float ke = dk[0][0]*dk[0][0] + dk[0][2]*dk[0][2] + dk[1][0]*dk[1][0] + dk[1][2]*dk[1][2];
    float ko = dk[0][1]*dk[0][1] + dk[0][3]*dk[0][3] + dk[1][1]*dk[1][1] + dk[1][3]*dk[1][3];
    #pragma unroll
    for (int off = 4; off <= 16; off <<= 1) {
        qe += __shfl_xor_sync(0xffffffffu, qe, off);
        qo += __shfl_xor_sync(0xffffffffu, qo, off);
        ke += __shfl_xor_sync(0xffffffffu, ke, off);
        ko += __shfl_xor_sync(0xffffffffu, ko, off);
    }
    const float rqe = rsqrtf(qe), rqo = rsqrtf(qo);
    const float rke = rsqrtf(ke), rko = rsqrtf(ko);

    // Kn values + S partials
    float k00 = dk[0][0]*rke, k01 = dk[0][1]*rko, k02 = dk[0][2]*rke, k03 = dk[0][3]*rko;
    float k10 = dk[1][0]*rke, k11 = dk[1][1]*rko, k12 = dk[1][2]*rke, k13 = dk[1][3]*rko;
    float s0 = k00 + k01, s1 = k02 + k03, s2 = k10 + k11, s3 = k12 + k13;
    s0 += __shfl_xor_sync(0xffffffffu, s0, 1); s0 += __shfl_xor_sync(0xffffffffu, s0, 2);
    s1 += __shfl_xor_sync(0xffffffffu, s1, 1); s1 += __shfl_xor_sync(0xffffffffu, s1, 2);
    s2 += __shfl_xor_sync(0xffffffffu, s2, 1); s2 += __shfl_xor_sync(0xffffffffu, s2, 2);
    s3 += __shfl_xor_sync(0xffffffffu, s3, 1); s3 += __shfl_xor_sync(0xffffffffu, s3, 2);
    if (tig == 0) {
        atomicAdd(&g_S[b * CQ + gid],      s0);
        atomicAdd(&g_S[b * CQ + gid + 8],  s1);
        atomicAdd(&g_S[b * CQ + gid + 16], s2);
        atomicAdd(&g_S[b * CQ + gid + 24], s3);
    }

    uint32_t* Q = (uint32_t*)(qts + w * 288);   // [32 o][9] slice
    const int jl = 2 * tig;

    // ---- Qn transpose -> qfrag ----
    Q[(gid)      * 9 + jl]     = f2tf(dq[0][0] * rqe);
    Q[(gid)      * 9 + jl + 1] = f2tf(dq[0][1] * rqo);
    Q[(gid + 8)  * 9 + jl]     = f2tf(dq[0][2] * rqe);
    Q[(gid + 8)  * 9 + jl + 1] = f2tf(dq[0][3] * rqo);
    Q[(gid + 16) * 9 + jl]     = f2tf(dq[1][0] * rqe);
    Q[(gid + 16) * 9 + jl + 1] = f2tf(dq[1][1] * rqo);
    Q[(gid + 24) * 9 + jl]     = f2tf(dq[1][2] * rqe);
    Q[(gid + 24) * 9 + jl + 1] = f2tf(dq[1][3] * rqo);
    __syncwarp();
    {
        uint4 B0v, B1v;
        B0v.x = Q[(tig)      * 9 + gid];
        B0v.y = Q[(8 + tig)  * 9 + gid];
        B0v.z = Q[(16 + tig) * 9 + gid];
        B0v.w = Q[(24 + tig) * 9 + gid];
        B1v.x = Q[(4 + tig)  * 9 + gid];
        B1v.y = Q[(12 + tig) * 9 + gid];
        B1v.z = Q[(20 + tig) * 9 + gid];
        B1v.w = Q[(28 + tig) * 9 + gid];
        uint4* dst = g_qfrag + ((size_t)(b * 2048 + jt) * 32 + lane) * 2;
        dst[0] = B0v;
        dst[1] = B1v;
    }
    __syncwarp();

    // ---- Kn transpose -> kfrag (mpT B-frag layout) ----
    Q[(gid)      * 9 + jl]     = f2tf(k00);
    Q[(gid)      * 9 + jl + 1] = f2tf(k01);
    Q[(gid + 8)  * 9 + jl]     = f2tf(k02);
    Q[(gid + 8)  * 9 + jl + 1] = f2tf(k03);
    Q[(gid + 16) * 9 + jl]     = f2tf(k10);
    Q[(gid + 16) * 9 + jl + 1] = f2tf(k11);
    Q[(gid + 24) * 9 + jl]     = f2tf(k12);
    Q[(gid + 24) * 9 + jl + 1] = f2tf(k13);
    __syncwarp();
    #pragma unroll
    for (int mt = 0; mt < 4; mt++) {
        uint2 kv;
        kv.x = Q[(8 * mt + gid) * 9 + tig];       // Kn[m0+gid][j0+tig]
        kv.y = Q[(8 * mt + gid) * 9 + 4 + tig];   // Kn[m0+gid][j0+4+tig]
        g_kfrag[((size_t)(b * 2048 + jt) * 4 + mt) * 32 + lane] = kv;
    }
}

// ---------------- kernel 2: mpT streaming: x @ Kn^T + xsum ------------------
__global__ void __launch_bounds__(256)
k_mp(const float* __restrict__ x) {
    const int tid = threadIdx.x;
    const int w = tid >> 5, lane = tid & 31, gid = lane >> 2, tig = lane & 3;
    const int b   = blockIdx.x >> 6;
    const int jsl = blockIdx.x & 63;       // 256-j slice
    const float* xb = x + (size_t)b * CC * NN;

    float e[2][4][4];
    #pragma unroll
    for (int ct = 0; ct < 2; ct++)
        #pragma unroll
        for (int mt = 0; mt < 4; mt++)
            #pragma unroll
            for (int q = 0; q < 4; q++) e[ct][mt][q] = 0.f;
    float sx[2][2] = {{0.f, 0.f}, {0.f, 0.f}};

    #pragma unroll 2
    for (int kk = 0; kk < 32; kk++) {
        const int jt = jsl * 32 + kk;
        const int jg = jt * 8;
        uint32_t bb0[4], bb1[4];
        #pragma unroll
        for (int mt = 0; mt < 4; mt++) {
            uint2 kv = __ldg(&g_kfrag[((size_t)(b * 2048 + jt) * 4 + mt) * 32 + lane]);
            bb0[mt] = kv.x; bb1[mt] = kv.y;
        }
        #pragma unroll
        for (int ct = 0; ct < 2; ct++) {
            const int c0 = 32 * w + 16 * ct;
            float xa0 = __ldg(xb + (size_t)(c0 + gid)     * NN + jg + tig);
            float xa1 = __ldg(xb + (size_t)(c0 + 8 + gid) * NN + jg + tig);
            float xa2 = __ldg(xb + (size_t)(c0 + gid)     * NN + jg + 4 + tig);
            float xa3 = __ldg(xb + (size_t)(c0 + 8 + gid) * NN + jg + 4 + tig);
            sx[ct][0] += xa0 + xa2;
            sx[ct][1] += xa1 + xa3;
            uint32_t a0 = f2tf(xa0), a1 = f2tf(xa1), a2 = f2tf(xa2), a3 = f2tf(xa3);
            #pragma unroll
            for (int mt = 0; mt < 4; mt++)
                mma_tf32(e[ct][mt][0], e[ct][mt][1], e[ct][mt][2], e[ct][mt][3],
                         a0, a1, a2, a3, bb0[mt], bb1[mt]);
        }
    }

    // xsum butterflies + atomics
    #pragma unroll
    for (int ct = 0; ct < 2; ct++) {
        float v0 = sx[ct][0], v1 = sx[ct][1];
        v0 += __shfl_xor_sync(0xffffffffu, v0, 1); v0 += __shfl_xor_sync(0xffffffffu, v0, 2);
        v1 += __shfl_xor_sync(0xffffffffu, v1, 1); v1 += __shfl_xor_sync(0xffffffffu, v1, 2);
        if (tig == 0) {
            const int c0 = 32 * w + 16 * ct;
            atomicAdd(&g_xsum[b * CC + c0 + gid],     v0);
            atomicAdd(&g_xsum[b * CC + c0 + 8 + gid], v1);
        }
    }
    // mpT atomics
    float* mpb = &g_mpT[b * CC * CQ];
    #pragma unroll
    for (int ct = 0; ct < 2; ct++) {
        const int c0 = 32 * w + 16 * ct;
        #pragma unroll
        for (int mt = 0; mt < 4; mt++) {
            const int m0 = mt * 8 + 2 * tig;
            atomicAdd(&mpb[(c0 + gid) * CQ + m0],         e[ct][mt][0]);
            atomicAdd(&mpb[(c0 + gid) * CQ + m0 + 1],     e[ct][mt][1]);
            atomicAdd(&mpb[(c0 + 8 + gid) * CQ + m0],     e[ct][mt][2]);
            atomicAdd(&mpb[(c0 + 8 + gid) * CQ + m0 + 1], e[ct][mt][3]);
        }
    }
}

// ---------------- kernel 3: matrix = mp @ Wv^T + bv (x) S ; vsum; fragments -
// 64 blocks: (b, 32-cp group). Dynamic smem.
__global__ void __launch_bounds__(256)
k_mat(const float* __restrict__ Wv, const float* __restrict__ bv) {
    extern __shared__ float shm[];
    float* mpT_s = shm;                 // [256 c][32 m]
    float* wv_s  = shm + CC * CQ;       // [32 cl][257]
    float* xs_s  = wv_s + 32 * 257;     // [256]
    float* S_s   = xs_s + CC;           // [32]

    const int b  = blockIdx.x >> 3;
    const int cg = (blockIdx.x & 7) * 32;
    const int tid = threadIdx.x;

    for (int idx = tid; idx < CC * CQ; idx += 256)
        mpT_s[idx] = g_mpT[b * CC * CQ + idx];
    for (int idx = tid; idx < 32 * CC; idx += 256) {
        int cl = idx >> 8, c = idx & 255;
        wv_s[cl * 257 + c] = Wv[(cg + cl) * CC + c];
    }
    xs_s[tid] = g_xsum[b * CC + tid];
    if (tid < 32) S_s[tid] = g_S[b * CQ + tid];
    __syncthreads();

    const int cl = tid & 31;            // local cp
    const int mg = tid >> 5;            // m group (4 m each)
    const int cp = cg + cl;
    const float bvv = __ldg(&bv[cp]);

    float acc[4];
    #pragma unroll
    for (int i = 0; i < 4; i++) acc[i] = bvv * S_s[mg * 4 + i];
    float vs = (float)NN * bvv;

    const float* wrow = &wv_s[cl * 257];
    #pragma unroll 4
    for (int c = 0; c < CC; ++c) {
        float wv = wrow[c];
        vs += wv * xs_s[c];
        const float4 mv = *(const float4*)&mpT_s[c * CQ + mg * 4];
        acc[0] += mv.x * wv; acc[1] += mv.y * wv;
        acc[2] += mv.z * wv; acc[3] += mv.w * wv;
    }
    if (mg == 0) g_vsum[b * CC + cp] = vs;

    // scatter into mfrag layout
    const int ct = cp >> 4, cl16 = cp & 15;
    const int gidf = cl16 & 7, hi = cl16 >> 3;
    #pragma unroll
    for (int i = 0; i < 4; i++) {
        const int m = mg * 4 + i;
        const int kk = m >> 3, tigf = m & 3, half = (m >> 2) & 1;
        const int elem = hi + 2 * half;
        g_mfrag[((((b * 16 + ct) * 4 + kk) * 32) + gidf * 4 + tigf) * 4 + elem] = f2tf(acc[i]);
    }
}

// ---------------- kernel 4: streaming epilogue, 2 j-tiles per warp ----------
__global__ void __launch_bounds__(256)
k_pass2(const float* __restrict__ x, const float* __restrict__ gamma,
        float* __restrict__ out) {
    const int tid = threadIdx.x;
    const int w = tid >> 5, lane = tid & 31, gid = lane >> 2, tig = lane & 3;
    const int b   = blockIdx.x >> 7;
    const int jt0 = (blockIdx.x & 127) * 16 + w * 2;
    const int n0  = jt0 * 8;
    const float gm = __ldg(&gamma[0]);

    const uint4* qf = g_qfrag + ((size_t)(b * 2048 + jt0) * 32 + lane) * 2;
    uint4 P0 = __ldg(qf),      P1 = __ldg(qf + 1);
    uint4 R0 = __ldg(qf + 64), R1 = __ldg(qf + 65);
    uint32_t PB0[4] = {P0.x, P0.y, P0.z, P0.w};
    uint32_t PB1[4] = {P1.x, P1.y, P1.z, P1.w};
    uint32_t RB0[4] = {R0.x, R0.y, R0.z, R0.w};
    uint32_t RB1[4] = {R1.x, R1.y, R1.z, R1.w};

    float tl0 = 0.f, tl1 = 0.f;
    #pragma unroll
    for (int kk = 0; kk < 4; kk++) {
        float se0 = __ldg(&g_S[b * CQ + 8 * kk + tig])     + EPSV;
        float se1 = __ldg(&g_S[b * CQ + 8 * kk + 4 + tig]) + EPSV;
        tl0 += __uint_as_float(PB0[kk]) * se0 + __uint_as_float(PB1[kk]) * se1;
        tl1 += __uint_as_float(RB0[kk]) * se0 + __uint_as_float(RB1[kk]) * se1;
    }
    tl0 += __shfl_xor_sync(0xffffffffu, tl0, 1);
    tl0 += __shfl_xor_sync(0xffffffffu, tl0, 2);
    tl1 += __shfl_xor_sync(0xffffffffu, tl1, 1);
    tl1 += __shfl_xor_sync(0xffffffffu, tl1, 2);
    const float g0 = gm / (16384.f + tl0);
    const float g1 = gm / (16384.f + tl1);
    const float gt0e = __shfl_sync(0xffffffffu, g0, 8 * tig);
    const float gt0o = __shfl_sync(0xffffffffu, g0, 8 * tig + 4);
    const float gt1e = __shfl_sync(0xffffffffu, g1, 8 * tig);
    const float gt1o = __shfl_sync(0xffffffffu, g1, 8 * tig + 4);

    const float* xp = x   + (size_t)b * CC * NN + n0;
    float*       op = out + (size_t)b * CC * NN + n0;
    const uint4* mf = (const uint4*)g_mfrag + (size_t)b * 16 * 4 * 32 + lane;
    const float* vs = g_vsum + b * CC;
    const int jj = 2 * tig;

    #pragma unroll 4
    for (int ct = 0; ct < 16; ct++) {
        const uint4* base = mf + ct * 128;
        uint4 A0 = __ldg(base);
        uint4 A1 = __ldg(base + 32);
        uint4 A2 = __ldg(base + 64);
        uint4 A3 = __ldg(base + 96);
        float e0 = 0.f, e1 = 0.f, e2 = 0.f, e3 = 0.f;
        float f0 = 0.f, f1 = 0.f, f2 = 0.f, f3 = 0.f;
        mma_tf32(e0, e1, e2, e3, A0.x, A0.y, A0.z, A0.w, PB0[0], PB1[0]);
        mma_tf32(f0, f1, f2, f3, A0.x, A0.y, A0.z, A0.w, RB0[0], RB1[0]);
        mma_tf32(e0, e1, e2, e3, A1.x, A1.y, A1.z, A1.w, PB0[1], PB1[1]);
        mma_tf32(f0, f1, f2, f3, A1.x, A1.y, A1.z, A1.w, RB0[1], RB1[1]);
        mma_tf32(e0, e1, e2, e3, A2.x, A2.y, A2.z, A2.w, PB0[2], PB1[2]);
        mma_tf32(f0, f1, f2, f3, A2.x, A2.y, A2.z, A2.w, RB0[2], RB1[2]);
        mma_tf32(e0, e1, e2, e3, A3.x, A3.y, A3.z, A3.w, PB0[3], PB1[3]);
        mma_tf32(f0, f1, f2, f3, A3.x, A3.y, A3.z, A3.w, RB0[3], RB1[3]);

        const int c1 = ct * 16 + gid;
        const int c2 = c1 + 8;
        const float v1 = __ldg(&vs[c1]), v2 = __ldg(&vs[c2]);
        float2 x10 = *(const float2*)(xp + (size_t)c1 * NN + jj);
        float2 x11 = *(const float2*)(xp + (size_t)c1 * NN + 8 + jj);
        float2 x20 = *(const float2*)(xp + (size_t)c2 * NN + jj);
        float2 x21 = *(const float2*)(xp + (size_t)c2 * NN + 8 + jj);
        float2 o10, o11, o20, o21;
        o10.x = x10.x + gt0e * (v1 + e0);
        o10.y = x10.y + gt0o * (v1 + e1);
        o11.x = x11.x + gt1e * (v1 + f0);
        o11.y = x11.y + gt1o * (v1 + f1);
        o20.x = x20.x + gt0e * (v2 + e2);
        o20.y = x20.y + gt0o * (v2 + e3);
        o21.x = x21.x + gt1e * (v2 + f2);
        o21.y = x21.y + gt1o * (v2 + f3);
        __stcs((float2*)(op + (size_t)c1 * NN + jj),     o10);
        __stcs((float2*)(op + (size_t)c1 * NN + 8 + jj), o11);
        __stcs((float2*)(op + (size_t)c2 * NN + jj),     o20);
        __stcs((float2*)(op + (size_t)c2 * NN + 8 + jj), o21);
    }
}

// ---------------- launch --------------------------------------------------
extern "C" void kernel_launch(void* const* d_in, const int* in_sizes, int n_in,
                              void* d_out, int out_size) {
    const float* x     = (const float*)d_in[0];
    const float* Wq    = (const float*)d_in[1];
    const float* bq    = (const float*)d_in[2];
    const float* Wk    = (const float*)d_in[3];
    const float* bk    = (const float*)d_in[4];
    const float* Wv    = (const float*)d_in[5];
    const float* bv    = (const float*)d_in[6];
    const float* gamma = (const float*)d_in[7];
    float* out = (float*)d_out;

    const int shMat = (CC * CQ + 32 * 257 + CC + CQ) * (int)sizeof(float); // 66,takKB
    cudaFuncSetAttribute(k_mat, cudaFuncAttributeMaxDynamicSharedMemorySize, shMat);

    k_prep<<<256, 256>>>(Wq, Wk);
    k_qk<<<BB * 256, 256>>>(x, bq, bk);        // 2048 blocks, warp = 8 j, Q+K
    k_mp<<<BB * 64, 256>>>(x);                 // 512 blocks, mpT stream
    k_mat<<<BB * 8, 256, shMat>>>(Wv, bv);     // 64 blocks
    k_pass2<<<BB * 128, 256>>>(x, gamma, out); // 1024 blocks, warp = 16 j
}

// round 10
// speedup vs baseline: 1.1680x; 1.0205x over previous
#include <cuda_runtime.h>
#include <cstdint>

#define BB   8
#define CC   256
#define CQ   32
#define NN   16384
#define EPSV 1e-6f

// ---------------- scratch (device globals) ---------------------------------
__device__ __align__(16) uint32_t g_WtF[4 * 32 * 32 * 4];   // tf32 A-frags; 0-1 = Wq, 2-3 = Wk
__device__ float g_mpT[BB * CC * CQ];                       // (Kn @ x^T)^T : [b][c][m]
__device__ float g_S[BB * CQ];                              // sum_n Kn
__device__ float g_xsum[BB * CC];                           // sum_n x
__device__ __align__(16) uint32_t g_mfrag[BB * 16 * 4 * 32 * 4]; // matT tf32 A-frags
__device__ float g_vsum[BB * CC];                           // value_sum
__device__ __align__(16) uint4 g_qfrag[(size_t)BB * 2048 * 32 * 2]; // Qn B-frags [b][jt][lane][2]

__device__ __forceinline__ uint32_t f2tf(float f) {
    uint32_t r; asm("cvt.rna.tf32.f32 %0, %1;" : "=r"(r) : "f"(f)); return r;
}

__device__ __forceinline__ void mma_tf32(float& d0, float& d1, float& d2, float& d3,
                                         uint32_t a0, uint32_t a1, uint32_t a2, uint32_t a3,
                                         uint32_t b0, uint32_t b1) {
    asm volatile(
        "mma.sync.aligned.m16n8k8.row.col.f32.tf32.tf32.f32 "
        "{%0,%1,%2,%3},{%4,%5,%6,%7},{%8,%9},{%0,%1,%2,%3};"
        : "+f"(d0), "+f"(d1), "+f"(d2), "+f"(d3)
        : "r"(a0), "r"(a1), "r"(a2), "r"(a3), "r"(b0), "r"(b1));
}

// ---------------- kernel 0: zero accumulators + build tf32 W-fragments -----
__global__ void k_prep(const float* __restrict__ Wq, const float* __restrict__ Wk) {
    int idx = blockIdx.x * blockDim.x + threadIdx.x;      // 65536 threads
    if (idx < BB * CC * CQ) g_mpT[idx] = 0.f;
    if (idx < 16384) {
        int f    = idx & 3;
        int lane = (idx >> 2) & 31;
        int kk   = (idx >> 7) & 31;
        int wo   = idx >> 12;
        int gid = lane >> 2, tig = lane & 3;
        int o = (wo & 1) * 16 + gid + (f & 1) * 8;
        int c = kk * 8 + tig + (f >> 1) * 4;
        float v = (wo < 2) ? Wq[o * CC + c] : Wk[o * CC + c];
        g_WtF[idx] = f2tf(v);
    }
    if (idx < BB * CC) g_xsum[idx] = 0.f;
    if (idx < BB * CQ) g_S[idx] = 0.f;
}

// ---------------- kernel 1: FUSED Q+K proj + Qn frags + S + xsum + mpT ------
// block = (b, 256-j slice). Phase A: proj (warp = 8 j x 4 subtiles), Kn->smem.
// Phase B: mpT mma over the same 256 j (x re-read hits L2).
__global__ void __launch_bounds__(256)
k_fused(const float* __restrict__ x, const float* __restrict__ bq,
        const float* __restrict__ bk) {
    __shared__ uint2 kf[32][4][32];      // Kn B-frags for 32 local j-tiles (32 KB)
    __shared__ float qts[8 * 288];       // per-warp transpose scratch (9 KB)

    const int tid = threadIdx.x;
    const int w = tid >> 5, lane = tid & 31, gid = lane >> 2, tig = lane & 3;
    const int b   = blockIdx.x >> 6;
    const int jsl = blockIdx.x & 63;                 // 256-j slice
    const float* xb = x + (size_t)b * CC * NN;

    const float bq0 = __ldg(&bq[gid]),      bq1 = __ldg(&bq[gid + 8]);
    const float bq2 = __ldg(&bq[gid + 16]), bq3 = __ldg(&bq[gid + 24]);
    const float bk0 = __ldg(&bk[gid]),      bk1 = __ldg(&bk[gid + 8]);
    const float bk2 = __ldg(&bk[gid + 16]), bk3 = __ldg(&bk[gid + 24]);

    const uint4* Wt = (const uint4*)g_WtF + lane;
    uint32_t* Q = (uint32_t*)(qts + w * 288);        // [32 o][9] slice
    const int jl = 2 * tig;

    float S0 = 0.f, S1 = 0.f, S2 = 0.f, S3 = 0.f;

    // ================= phase A: projections =================
    #pragma unroll 1
    for (int sub = 0; sub < 4; sub++) {
        const int jbase = jsl * 256 + sub * 64 + w * 8;   // warp's 8 global j
        const int jt = jbase >> 3;                        // global j-tile
        const int lt = sub * 8 + w;                       // local j-tile 0..31
        const float* xp = xb + (size_t)tig * NN + jbase + gid;

        float dq[2][4], dk[2][4];
        #pragma unroll
        for (int t = 0; t < 2; t++)
            #pragma unroll
            for (int q = 0; q < 4; q++) { dq[t][q] = 0.f; dk[t][q] = 0.f; }

        #pragma unroll 4
        for (int kk = 0; kk < 32; kk++) {
            uint32_t b0 = f2tf(__ldg(xp + (size_t)(8 * kk) * NN));
            uint32_t b1 = f2tf(__ldg(xp + (size_t)(8 * kk + 4) * NN));
            uint4 a;
            a = Wt[kk * 32];
            mma_tf32(dq[0][0], dq[0][1], dq[0][2], dq[0][3], a.x, a.y, a.z, a.w, b0, b1);
            a = Wt[1024 + kk * 32];
            mma_tf32(dq[1][0], dq[1][1], dq[1][2], dq[1][3], a.x, a.y, a.z, a.w, b0, b1);
            a = Wt[2048 + kk * 32];
            mma_tf32(dk[0][0], dk[0][1], dk[0][2], dk[0][3], a.x, a.y, a.z, a.w, b0, b1);
            a = Wt[3072 + kk * 32];
            mma_tf32(dk[1][0], dk[1][1], dk[1][2], dk[1][3], a.x, a.y, a.z, a.w, b0, b1);
        }
        dq[0][0] += bq0; dq[0][1] += bq0; dq[0][2] += bq1; dq[0][3] += bq1;
        dq[1][0] += bq2; dq[1][1] += bq2; dq[1][2] += bq3; dq[1][3] += bq3;
        dk[0][0] += bk0; dk[0][1] += bk0; dk[0][2] += bk1; dk[0][3] += bk1;
        dk[1][0] += bk2; dk[1][1] += bk2; dk[1][2] += bk3; dk[1][3] += bk3;

        // column norms
        float qe = dq[0][0]*dq[0][0] + dq[0][2]*dq[0][2] + dq[1][0]*dq[1][0] + dq[1][2]*dq[1][2];
        float qo = dq[0][1]*dq[0][1] + dq[0][3]*dq[0][3] + dq[1][1]*dq[1][1] + dq[1][3]*dq[1][3];
        float ke = dk[0][0]*dk[0][0] + dk[0][2]*dk[0][2] + dk[1][0]*dk[1][0] + dk[1][2]*dk[1][2];
        float ko = dk[0][1]*dk[0][1] + dk[0][3]*dk[0][3] + dk[1][1]*dk[1][1] + dk[1][3]*dk[1][3];
        #pragma unroll
        for (int off = 4; off <= 16; off <<= 1) {
            qe += __shfl_xor_sync(0xffffffffu, qe, off);
            qo += __shfl_xor_sync(0xffffffffu, qo, off);
            ke += __shfl_xor_sync(0xffffffffu, ke, off);
            ko += __shfl_xor_sync(0xffffffffu, ko, off);
        }
        const float rqe = rsqrtf(qe), rqo = rsqrtf(qo);
        const float rke = rsqrtf(ke), rko = rsqrtf(ko);

        float k00 = dk[0][0]*rke, k01 = dk[0][1]*rko, k02 = dk[0][2]*rke, k03 = dk[0][3]*rko;
        float k10 = dk[1][0]*rke, k11 = dk[1][1]*rko, k12 = dk[1][2]*rke, k13 = dk[1][3]*rko;
        float s0 = k00 + k01, s1 = k02 + k03, s2 = k10 + k11, s3 = k12 + k13;
        s0 += __shfl_xor_sync(0xffffffffu, s0, 1); s0 += __shfl_xor_sync(0xffffffffu, s0, 2);
        s1 += __shfl_xor_sync(0xffffffffu, s1, 1); s1 += __shfl_xor_sync(0xffffffffu, s1, 2);
        s2 += __shfl_xor_sync(0xffffffffu, s2, 1); s2 += __shfl_xor_sync(0xffffffffu, s2, 2);
        s3 += __shfl_xor_sync(0xffffffffu, s3, 1); s3 += __shfl_xor_sync(0xffffffffu, s3, 2);
        S0 += s0; S1 += s1; S2 += s2; S3 += s3;

        // Qn transpose -> qfrag (global, for pass2)
        Q[(gid)      * 9 + jl]     = f2tf(dq[0][0] * rqe);
        Q[(gid)      * 9 + jl + 1] = f2tf(dq[0][1] * rqo);
        Q[(gid + 8)  * 9 + jl]     = f2tf(dq[0][2] * rqe);
        Q[(gid + 8)  * 9 + jl + 1] = f2tf(dq[0][3] * rqo);
        Q[(gid + 16) * 9 + jl]     = f2tf(dq[1][0] * rqe);
        Q[(gid + 16) * 9 + jl + 1] = f2tf(dq[1][1] * rqo);
        Q[(gid + 24) * 9 + jl]     = f2tf(dq[1][2] * rqe);
        Q[(gid + 24) * 9 + jl + 1] = f2tf(dq[1][3] * rqo);
        __syncwarp();
        {
            uint4 B0v, B1v;
            B0v.x = Q[(tig)      * 9 + gid];
            B0v.y = Q[(8 + tig)  * 9 + gid];
            B0v.z = Q[(16 + tig) * 9 + gid];
            B0v.w = Q[(24 + tig) * 9 + gid];
            B1v.x = Q[(4 + tig)  * 9 + gid];
            B1v.y = Q[(12 + tig) * 9 + gid];
            B1v.z = Q[(20 + tig) * 9 + gid];
            B1v.w = Q[(28 + tig) * 9 + gid];
            uint4* dst = g_qfrag + ((size_t)(b * 2048 + jt) * 32 + lane) * 2;
            dst[0] = B0v;
            dst[1] = B1v;
        }
        __syncwarp();

        // Kn transpose -> smem kfrag slice (B-frag layout for phase B)
        Q[(gid)      * 9 + jl]     = f2tf(k00);
        Q[(gid)      * 9 + jl + 1] = f2tf(k01);
        Q[(gid + 8)  * 9 + jl]     = f2tf(k02);
        Q[(gid + 8)  * 9 + jl + 1] = f2tf(k03);
        Q[(gid + 16) * 9 + jl]     = f2tf(k10);
        Q[(gid + 16) * 9 + jl + 1] = f2tf(k11);
        Q[(gid + 24) * 9 + jl]     = f2tf(k12);
        Q[(gid + 24) * 9 + jl + 1] = f2tf(k13);
        __syncwarp();
        #pragma unroll
        for (int mt = 0; mt < 4; mt++) {
            uint2 kv;
            kv.x = Q[(8 * mt + gid) * 9 + tig];
            kv.y = Q[(8 * mt + gid) * 9 + 4 + tig];
            kf[lt][mt][lane] = kv;
        }
        __syncwarp();
    }

    if (tig == 0) {
        atomicAdd(&g_S[b * CQ + gid],      S0);
        atomicAdd(&g_S[b * CQ + gid + 8],  S1);
        atomicAdd(&g_S[b * CQ + gid + 16], S2);
        atomicAdd(&g_S[b * CQ + gid + 24], S3);
    }
    __syncthreads();         // all Kn slices visible

    // ================= phase B: mpT = x @ Kn^T over this slice ==============
    float e[2][4][4];
    #pragma unroll
    for (int ct = 0; ct < 2; ct++)
        #pragma unroll
        for (int mt = 0; mt < 4; mt++)
            #pragma unroll
            for (int q = 0; q < 4; q++) e[ct][mt][q] = 0.f;
    float sx[2][2] = {{0.f, 0.f}, {0.f, 0.f}};

    #pragma unroll 2
    for (int kk = 0; kk < 32; kk++) {
        const int jg = jsl * 256 + kk * 8;
        uint32_t bb0[4], bb1[4];
        #pragma unroll
        for (int mt = 0; mt < 4; mt++) {
            uint2 kv = kf[kk][mt][lane];
            bb0[mt] = kv.x; bb1[mt] = kv.y;
        }
        #pragma unroll
        for (int ct = 0; ct < 2; ct++) {
            const int c0 = 32 * w + 16 * ct;
            float xa0 = __ldg(xb + (size_t)(c0 + gid)     * NN + jg + tig);
            float xa1 = __ldg(xb + (size_t)(c0 + 8 + gid) * NN + jg + tig);
            float xa2 = __ldg(xb + (size_t)(c0 + gid)     * NN + jg + 4 + tig);
            float xa3 = __ldg(xb + (size_t)(c0 + 8 + gid) * NN + jg + 4 + tig);
            sx[ct][0] += xa0 + xa2;
            sx[ct][1] += xa1 + xa3;
            uint32_t a0 = f2tf(xa0), a1 = f2tf(xa1), a2 = f2tf(xa2), a3 = f2tf(xa3);
            #pragma unroll
            for (int mt = 0; mt < 4; mt++)
                mma_tf32(e[ct][mt][0], e[ct][mt][1], e[ct][mt][2], e[ct][mt][3],
                         a0, a1, a2, a3, bb0[mt], bb1[mt]);
        }
    }

    #pragma unroll
    for (int ct = 0; ct < 2; ct++) {
        float v0 = sx[ct][0], v1 = sx[ct][1];
        v0 += __shfl_xor_sync(0xffffffffu, v0, 1); v0 += __shfl_xor_sync(0xffffffffu, v0, 2);
        v1 += __shfl_xor_sync(0xffffffffu, v1, 1); v1 += __shfl_xor_sync(0xffffffffu, v1, 2);
        if (tig == 0) {
            const int c0 = 32 * w + 16 * ct;
            atomicAdd(&g_xsum[b * CC + c0 + gid],     v0);
            atomicAdd(&g_xsum[b * CC + c0 + 8 + gid], v1);
        }
    }
    float* mpb = &g_mpT[b * CC * CQ];
    #pragma unroll
    for (int ct = 0; ct < 2; ct++) {
        const int c0 = 32 * w + 16 * ct;
        #pragma unroll
        for (int mt = 0; mt < 4; mt++) {
            const int m0 = mt * 8 + 2 * tig;
            atomicAdd(&mpb[(c0 + gid) * CQ + m0],         e[ct][mt][0]);
            atomicAdd(&mpb[(c0 + gid) * CQ + m0 + 1],     e[ct][mt][1]);
            atomicAdd(&mpb[(c0 + 8 + gid) * CQ + m0],     e[ct][mt][2]);
            atomicAdd(&mpb[(c0 + 8 + gid) * CQ + m0 + 1], e[ct][mt][3]);
        }
    }
}

// ---------------- kernel 2: matrix = mp @ Wv^T + bv (x) S ; vsum; fragments -
// 128 blocks: (b, 16-cp group). 256 threads = 16 cl x 16 mg (2 m each).
__global__ void __launch_bounds__(256)
k_mat(const float* __restrict__ Wv, const float* __restrict__ bv) {
    extern __shared__ float shm[];
    float* mpT_s = shm;                 // [256 c][32 m]
    float* wv_s  = shm + CC * CQ;       // [16 cl][257]
    float* xs_s  = wv_s + 16 * 257;     // [256]
    float* S_s   = xs_s + CC;           // [32]

    const int b  = blockIdx.x >> 4;
    const int cg = (blockIdx.x & 15) * 16;
    const int tid = threadIdx.x;

    for (int idx = tid; idx < CC * CQ; idx += 256)
        mpT_s[idx] = g_mpT[b * CC * CQ + idx];
    for (int idx = tid; idx < 16 * CC; idx += 256) {
        int cl = idx >> 8, c = idx & 255;
        wv_s[cl * 257 + c] = Wv[(cg + cl) * CC + c];
    }
    xs_s[tid] = g_xsum[b * CC + tid];
    if (tid < 32) S_s[tid] = g_S[b * CQ + tid];
    __syncthreads();

    const int cl = tid & 15;            // local cp
    const int mg = tid >> 4;            // m group (2 m each)
    const int cp = cg + cl;
    const float bvv = __ldg(&bv[cp]);

    float acc0 = bvv * S_s[mg * 2];
    float acc1 = bvv * S_s[mg * 2 + 1];
    float vs = (float)NN * bvv;

    const float* wrow = &wv_s[cl * 257];
    #pragma unroll 8
    for (int c = 0; c < CC; ++c) {
        float wv = wrow[c];
        vs += wv * xs_s[c];
        const float2 mv = *(const float2*)&mpT_s[c * CQ + mg * 2];
        acc0 += mv.x * wv;
        acc1 += mv.y * wv;
    }
    if (mg == 0) g_vsum[b * CC + cp] = vs;

    // scatter into mfrag layout
    const int ct = cp >> 4, cl16 = cp & 15;
    const int gidf = cl16 & 7, hi = cl16 >> 3;
    #pragma unroll
    for (int i = 0; i < 2; i++) {
        const int m = mg * 2 + i;
        const int kk = m >> 3, tigf = m & 3, half = (m >> 2) & 1;
        const int elem = hi + 2 * half;
        g_mfrag[((((b * 16 + ct) * 4 + kk) * 32) + gidf * 4 + tigf) * 4 + elem] =
            f2tf(i == 0 ? acc0 : acc1);
    }
}

// ---------------- kernel 3: streaming epilogue, 2 j-tiles per warp ----------
__global__ void __launch_bounds__(256)
k_pass2(const float* __restrict__ x, const float* __restrict__ gamma,
        float* __restrict__ out) {
    const int tid = threadIdx.x;
    const int w = tid >> 5, lane = tid & 31, gid = lane >> 2, tig = lane & 3;
    const int b   = blockIdx.x >> 7;
    const int jt0 = (blockIdx.x & 127) * 16 + w * 2;
    const int n0  = jt0 * 8;
    const float gm = __ldg(&gamma[0]);

    const uint4* qf = g_qfrag + ((size_t)(b * 2048 + jt0) * 32 + lane) * 2;
    uint4 P0 = __ldg(qf),      P1 = __ldg(qf + 1);
    uint4 R0 = __ldg(qf + 64), R1 = __ldg(qf + 65);
    uint32_t PB0[4] = {P0.x, P0.y, P0.z, P0.w};
    uint32_t PB1[4] = {P1.x, P1.y, P1.z, P1.w};
    uint32_t RB0[4] = {R0.x, R0.y, R0.z, R0.w};
    uint32_t RB1[4] = {R1.x, R1.y, R1.z, R1.w};

    float tl0 = 0.f, tl1 = 0.f;
    #pragma unroll
    for (int kk = 0; kk < 4; kk++) {
        float se0 = __ldg(&g_S[b * CQ + 8 * kk + tig])     + EPSV;
        float se1 = __ldg(&g_S[b * CQ + 8 * kk + 4 + tig]) + EPSV;
        tl0 += __uint_as_float(PB0[kk]) * se0 + __uint_as_float(PB1[kk]) * se1;
        tl1 += __uint_as_float(RB0[kk]) * se0 + __uint_as_float(RB1[kk]) * se1;
    }
    tl0 += __shfl_xor_sync(0xffffffffu, tl0, 1);
    tl0 += __shfl_xor_sync(0xffffffffu, tl0, 2);
    tl1 += __shfl_xor_sync(0xffffffffu, tl1, 1);
    tl1 += __shfl_xor_sync(0xffffffffu, tl1, 2);
    const float g0 = gm / (16384.f + tl0);
    const float g1 = gm / (16384.f + tl1);
    const float gt0e = __shfl_sync(0xffffffffu, g0, 8 * tig);
    const float gt0o = __shfl_sync(0xffffffffu, g0, 8 * tig + 4);
    const float gt1e = __shfl_sync(0xffffffffu, g1, 8 * tig);
    const float gt1o = __shfl_sync(0xffffffffu, g1, 8 * tig + 4);

    const float* xp = x   + (size_t)b * CC * NN + n0;
    float*       op = out + (size_t)b * CC * NN + n0;
    const uint4* mf = (const uint4*)g_mfrag + (size_t)b * 16 * 4 * 32 + lane;
    const float* vs = g_vsum + b * CC;
    const int jj = 2 * tig;

    #pragma unroll 4
    for (int ct = 0; ct < 16; ct++) {
        const uint4* base = mf + ct * 128;
        uint4 A0 = __ldg(base);
        uint4 A1 = __ldg(base + 32);
        uint4 A2 = __ldg(base + 64);
        uint4 A3 = __ldg(base + 96);
        float e0 = 0.f, e1 = 0.f, e2 = 0.f, e3 = 0.f;
        float f0 = 0.f, f1 = 0.f, f2 = 0.f, f3 = 0.f;
        mma_tf32(e0, e1, e2, e3, A0.x, A0.y, A0.z, A0.w, PB0[0], PB1[0]);
        mma_tf32(f0, f1, f2, f3, A0.x, A0.y, A0.z, A0.w, RB0[0], RB1[0]);
        mma_tf32(e0, e1, e2, e3, A1.x, A1.y, A1.z, A1.w, PB0[1], PB1[1]);
        mma_tf32(f0, f1, f2, f3, A1.x, A1.y, A1.z, A1.w, RB0[1], RB1[1]);
        mma_tf32(e0, e1, e2, e3, A2.x, A2.y, A2.z, A2.w, PB0[2], PB1[2]);
        mma_tf32(f0, f1, f2, f3, A2.x, A2.y, A2.z, A2.w, RB0[2], RB1[2]);
        mma_tf32(e0, e1, e2, e3, A3.x, A3.y, A3.z, A3.w, PB0[3], PB1[3]);
        mma_tf32(f0, f1, f2, f3, A3.x, A3.y, A3.z, A3.w, RB0[3], RB1[3]);

        const int c1 = ct * 16 + gid;
        const int c2 = c1 + 8;
        const float v1 = __ldg(&vs[c1]), v2 = __ldg(&vs[c2]);
        float2 x10 = *(const float2*)(xp + (size_t)c1 * NN + jj);
        float2 x11 = *(const float2*)(xp + (size_t)c1 * NN + 8 + jj);
        float2 x20 = *(const float2*)(xp + (size_t)c2 * NN + jj);
        float2 x21 = *(const float2*)(xp + (size_t)c2 * NN + 8 + jj);
        float2 o10, o11, o20, o21;
        o10.x = x10.x + gt0e * (v1 + e0);
        o10.y = x10.y + gt0o * (v1 + e1);
        o11.x = x11.x + gt1e * (v1 + f0);
        o11.y = x11.y + gt1o * (v1 + f1);
        o20.x = x20.x + gt0e * (v2 + e2);
        o20.y = x20.y + gt0o * (v2 + e3);
        o21.x = x21.x + gt1e * (v2 + f2);
        o21.y = x21.y + gt1o * (v2 + f3);
        __stcs((float2*)(op + (size_t)c1 * NN + jj),     o10);
        __stcs((float2*)(op + (size_t)c1 * NN + 8 + jj), o11);
        __stcs((float2*)(op + (size_t)c2 * NN + jj),     o20);
        __stcs((float2*)(op + (size_t)c2 * NN + 8 + jj), o21);
    }
}

// ---------------- launch --------------------------------------------------
extern "C" void kernel_launch(void* const* d_in, const int* in_sizes, int n_in,
                              void* d_out, int out_size) {
    const float* x     = (const float*)d_in[0];
    const float* Wq    = (const float*)d_in[1];
    const float* bq    = (const float*)d_in[2];
    const float* Wk    = (const float*)d_in[3];
    const float* bk    = (const float*)d_in[4];
    const float* Wv    = (const float*)d_in[5];
    const float* bv    = (const float*)d_in[6];
    const float* gamma = (const float*)d_in[7];
    float* out = (float*)d_out;

    const int shMat = (CC * CQ + 16 * 257 + CC + CQ) * (int)sizeof(float); // ~50 KB
    cudaFuncSetAttribute(k_mat, cudaFuncAttributeMaxDynamicSharedMemorySize, shMat);

    k_prep<<<256, 256>>>(Wq, Wk);
    k_fused<<<BB * 64, 256>>>(x, bq, bk);      // 512 blocks: proj + mpT, x read ~once
    k_mat<<<BB * 16, 256, shMat>>>(Wv, bv);    // 128 blocks
    k_pass2<<<BB * 128, 256>>>(x, gamma, out); // 1024 blocks, warp = 16 j
}

// round 11
// speedup vs baseline: 1.2226x; 1.0467x over previous
#include <cuda_runtime.h>
#include <cstdint>

#define BB   8
#define CC   256
#define CQ   32
#define NN   16384
#define EPSV 1e-6f

// ---------------- scratch (device globals) ---------------------------------
__device__ __align__(16) uint32_t g_WtF[4 * 16 * 32 * 4];   // bf16 A-frags; wo 0-1 = Wq, 2-3 = Wk
__device__ float g_mpT[BB * CC * CQ];                       // (Kn @ x^T)^T : [b][c][m]
__device__ float g_S[BB * CQ];                              // sum_n Kn
__device__ float g_xsum[BB * CC];                           // sum_n x
__device__ __align__(16) uint32_t g_mfrag[BB * 16 * 2 * 32 * 4]; // matT bf16 A-frags
__device__ float g_vsum[BB * CC];                           // value_sum
__device__ __align__(16) uint4 g_qfrag[(size_t)BB * 2048 * 32]; // Qn bf16 B-frags [b][jt][lane]

// pack two fp32 -> bf16x2 (lo in bits 0-15, hi in bits 16-31)
__device__ __forceinline__ uint32_t f2bf2(float lo, float hi) {
    uint32_t r;
    asm("cvt.rn.bf16x2.f32 %0, %1, %2;" : "=r"(r) : "f"(hi), "f"(lo));
    return r;
}
__device__ __forceinline__ float bf_lo(uint32_t v) { return __uint_as_float(v << 16); }
__device__ __forceinline__ float bf_hi(uint32_t v) { return __uint_as_float(v & 0xffff0000u); }

__device__ __forceinline__ void mma_bf16(float& d0, float& d1, float& d2, float& d3,
                                         uint32_t a0, uint32_t a1, uint32_t a2, uint32_t a3,
                                         uint32_t b0, uint32_t b1) {
    asm volatile(
        "mma.sync.aligned.m16n8k16.row.col.f32.bf16.bf16.f32 "
        "{%0,%1,%2,%3},{%4,%5,%6,%7},{%8,%9},{%0,%1,%2,%3};"
        : "+f"(d0), "+f"(d1), "+f"(d2), "+f"(d3)
        : "r"(a0), "r"(a1), "r"(a2), "r"(a3), "r"(b0), "r"(b1));
}

// ---------------- kernel 0: zero accumulators + build bf16 W-fragments -----
__global__ void k_prep(const float* __restrict__ Wq, const float* __restrict__ Wk) {
    int idx = blockIdx.x * blockDim.x + threadIdx.x;      // 65536 threads
    if (idx < BB * CC * CQ) g_mpT[idx] = 0.f;
    if (idx < 8192) {
        int f    = idx & 3;           // a0..a3
        int lane = (idx >> 2) & 31;
        int kk   = (idx >> 7) & 15;
        int wo   = (idx >> 11) & 3;
        int gid = lane >> 2, tig = lane & 3;
        int o = (wo & 1) * 16 + gid + (f & 1) * 8;
        int c = kk * 16 + 2 * tig + (f >> 1) * 8;
        const float* W = (wo < 2) ? Wq : Wk;
        g_WtF[idx] = f2bf2(W[o * CC + c], W[o * CC + c + 1]);
    }
    if (idx < BB * CC) g_xsum[idx] = 0.f;
    if (idx < BB * CQ) g_S[idx] = 0.f;
}

// ---------------- kernel 1: FUSED Q+K proj + Qn frags + S + xsum + mpT ------
// block = (b, 256-j slice). Phase A: proj (warp = 8 j x 4 subtiles), Kn (bf16 pairs)->smem.
// Phase B: mpT mma over the same 256 j (x re-read hits L2), all bf16 k16.
__global__ void __launch_bounds__(256)
k_fused(const float* __restrict__ x, const float* __restrict__ bq,
        const float* __restrict__ bk) {
    __shared__ uint32_t kb[32][132];     // Kn bf16x2 j-pairs: [m][jpair], pad->conflict-free
    __shared__ float qts[8 * 288];       // per-warp Qn fp32 transpose scratch

    const int tid = threadIdx.x;
    const int w = tid >> 5, lane = tid & 31, gid = lane >> 2, tig = lane & 3;
    const int b   = blockIdx.x >> 6;
    const int jsl = blockIdx.x & 63;                 // 256-j slice
    const float* xb = x + (size_t)b * CC * NN;

    const float bq0 = __ldg(&bq[gid]),      bq1 = __ldg(&bq[gid + 8]);
    const float bq2 = __ldg(&bq[gid + 16]), bq3 = __ldg(&bq[gid + 24]);
    const float bk0 = __ldg(&bk[gid]),      bk1 = __ldg(&bk[gid + 8]);
    const float bk2 = __ldg(&bk[gid + 16]), bk3 = __ldg(&bk[gid + 24]);

    const uint4* Wt = (const uint4*)g_WtF + lane;
    float* Qf = qts + w * 288;                       // [32 o][9] fp32 slice

    float S0 = 0.f, S1 = 0.f, S2 = 0.f, S3 = 0.f;

    // ================= phase A: projections =================
    #pragma unroll 1
    for (int sub = 0; sub < 4; sub++) {
        const int jbase = jsl * 256 + sub * 64 + w * 8;   // warp's 8 global j
        const int jt = jbase >> 3;
        const float* xp = xb + (size_t)(2 * tig) * NN + jbase + gid;

        float dq[2][4], dk[2][4];
        #pragma unroll
        for (int t = 0; t < 2; t++)
            #pragma unroll
            for (int q = 0; q < 4; q++) { dq[t][q] = 0.f; dk[t][q] = 0.f; }

        #pragma unroll 4
        for (int kk = 0; kk < 16; kk++) {
            const size_t r0 = (size_t)(16 * kk) * NN;
            float v0 = __ldg(xp + r0);
            float v1 = __ldg(xp + r0 + NN);
            float v2 = __ldg(xp + r0 + 8 * NN);
            float v3 = __ldg(xp + r0 + 9 * NN);
            uint32_t b0 = f2bf2(v0, v1);
            uint32_t b1 = f2bf2(v2, v3);
            uint4 a;
            a = Wt[kk * 32];
            mma_bf16(dq[0][0], dq[0][1], dq[0][2], dq[0][3], a.x, a.y, a.z, a.w, b0, b1);
            a = Wt[512 + kk * 32];
            mma_bf16(dq[1][0], dq[1][1], dq[1][2], dq[1][3], a.x, a.y, a.z, a.w, b0, b1);
            a = Wt[1024 + kk * 32];
            mma_bf16(dk[0][0], dk[0][1], dk[0][2], dk[0][3], a.x, a.y, a.z, a.w, b0, b1);
            a = Wt[1536 + kk * 32];
            mma_bf16(dk[1][0], dk[1][1], dk[1][2], dk[1][3], a.x, a.y, a.z, a.w, b0, b1);
        }
        dq[0][0] += bq0; dq[0][1] += bq0; dq[0][2] += bq1; dq[0][3] += bq1;
        dq[1][0] += bq2; dq[1][1] += bq2; dq[1][2] += bq3; dq[1][3] += bq3;
        dk[0][0] += bk0; dk[0][1] += bk0; dk[0][2] += bk1; dk[0][3] += bk1;
        dk[1][0] += bk2; dk[1][1] += bk2; dk[1][2] += bk3; dk[1][3] += bk3;

        // column norms (butterfly over gid bits): even j = d0/d2, odd j = d1/d3
        float qe = dq[0][0]*dq[0][0] + dq[0][2]*dq[0][2] + dq[1][0]*dq[1][0] + dq[1][2]*dq[1][2];
        float qo = dq[0][1]*dq[0][1] + dq[0][3]*dq[0][3] + dq[1][1]*dq[1][1] + dq[1][3]*dq[1][3];
        float ke = dk[0][0]*dk[0][0] + dk[0][2]*dk[0][2] + dk[1][0]*dk[1][0] + dk[1][2]*dk[1][2];
        float ko = dk[0][1]*dk[0][1] + dk[0][3]*dk[0][3] + dk[1][1]*dk[1][1] + dk[1][3]*dk[1][3];
        #pragma unroll
        for (int off = 4; off <= 16; off <<= 1) {
            qe += __shfl_xor_sync(0xffffffffu, qe, off);
            qo += __shfl_xor_sync(0xffffffffu, qo, off);
            ke += __shfl_xor_sync(0xffffffffu, ke, off);
            ko += __shfl_xor_sync(0xffffffffu, ko, off);
        }
        const float rqe = rsqrtf(qe), rqo = rsqrtf(qo);
        const float rke = rsqrtf(ke), rko = rsqrtf(ko);

        // Kn values + S partials
        float k00 = dk[0][0]*rke, k01 = dk[0][1]*rko, k02 = dk[0][2]*rke, k03 = dk[0][3]*rko;
        float k10 = dk[1][0]*rke, k11 = dk[1][1]*rko, k12 = dk[1][2]*rke, k13 = dk[1][3]*rko;
        float s0 = k00 + k01, s1 = k02 + k03, s2 = k10 + k11, s3 = k12 + k13;
        s0 += __shfl_xor_sync(0xffffffffu, s0, 1); s0 += __shfl_xor_sync(0xffffffffu, s0, 2);
        s1 += __shfl_xor_sync(0xffffffffu, s1, 1); s1 += __shfl_xor_sync(0xffffffffu, s1, 2);
        s2 += __shfl_xor_sync(0xffffffffu, s2, 1); s2 += __shfl_xor_sync(0xffffffffu, s2, 2);
        s3 += __shfl_xor_sync(0xffffffffu, s3, 1); s3 += __shfl_xor_sync(0xffffffffu, s3, 2);
        S0 += s0; S1 += s1; S2 += s2; S3 += s3;

        // Kn bf16 j-pairs -> kb  (pair index = global_j/2 within slice)
        {
            const int jp = sub * 32 + w * 4 + tig;
            kb[gid][jp]      = f2bf2(k00, k01);
            kb[gid + 8][jp]  = f2bf2(k02, k03);
            kb[gid + 16][jp] = f2bf2(k10, k11);
            kb[gid + 24][jp] = f2bf2(k12, k13);
        }

        // Qn fp32 -> scratch -> bf16 B-frags -> qfrag
        const int jl = 2 * tig;
        Qf[(gid)      * 9 + jl]     = dq[0][0] * rqe;
        Qf[(gid)      * 9 + jl + 1] = dq[0][1] * rqo;
        Qf[(gid + 8)  * 9 + jl]     = dq[0][2] * rqe;
        Qf[(gid + 8)  * 9 + jl + 1] = dq[0][3] * rqo;
        Qf[(gid + 16) * 9 + jl]     = dq[1][0] * rqe;
        Qf[(gid + 16) * 9 + jl + 1] = dq[1][1] * rqo;
        Qf[(gid + 24) * 9 + jl]     = dq[1][2] * rqe;
        Qf[(gid + 24) * 9 + jl + 1] = dq[1][3] * rqo;
        __syncwarp();
        {
            uint4 Bv;
            Bv.x = f2bf2(Qf[(2 * tig)      * 9 + gid], Qf[(2 * tig + 1)  * 9 + gid]);
            Bv.y = f2bf2(Qf[(2 * tig + 8)  * 9 + gid], Qf[(2 * tig + 9)  * 9 + gid]);
            Bv.z = f2bf2(Qf[(2 * tig + 16) * 9 + gid], Qf[(2 * tig + 17) * 9 + gid]);
            Bv.w = f2bf2(Qf[(2 * tig + 24) * 9 + gid], Qf[(2 * tig + 25) * 9 + gid]);
            g_qfrag[(size_t)(b * 2048 + jt) * 32 + lane] = Bv;
        }
        __syncwarp();
    }

    if (tig == 0) {
        atomicAdd(&g_S[b * CQ + gid],      S0);
        atomicAdd(&g_S[b * CQ + gid + 8],  S1);
        atomicAdd(&g_S[b * CQ + gid + 16], S2);
        atomicAdd(&g_S[b * CQ + gid + 24], S3);
    }
    __syncthreads();         // all Kn pairs visible

    // ================= phase B: mpT = x @ Kn^T over this slice (k16) ========
    float e[2][4][4];
    #pragma unroll
    for (int ct = 0; ct < 2; ct++)
        #pragma unroll
        for (int mt = 0; mt < 4; mt++)
            #pragma unroll
            for (int q = 0; q < 4; q++) e[ct][mt][q] = 0.f;
    float sx[2][2] = {{0.f, 0.f}, {0.f, 0.f}};

    #pragma unroll 2
    for (int kk = 0; kk < 16; kk++) {
        const int jg = jsl * 256 + kk * 16;
        uint32_t bb0[4], bb1[4];
        #pragma unroll
        for (int mt = 0; mt < 4; mt++) {
            bb0[mt] = kb[8 * mt + gid][8 * kk + tig];
            bb1[mt] = kb[8 * mt + gid][8 * kk + 4 + tig];
        }
        #pragma unroll
        for (int ct = 0; ct < 2; ct++) {
            const int c0 = 32 * w + 16 * ct;
            float2 v0 = *(const float2*)(xb + (size_t)(c0 + gid)     * NN + jg + 2 * tig);
            float2 v1 = *(const float2*)(xb + (size_t)(c0 + 8 + gid) * NN + jg + 2 * tig);
            float2 v2 = *(const float2*)(xb + (size_t)(c0 + gid)     * NN + jg + 8 + 2 * tig);
            float2 v3 = *(const float2*)(xb + (size_t)(c0 + 8 + gid) * NN + jg + 8 + 2 * tig);
            sx[ct][0] += v0.x + v0.y + v2.x + v2.y;
            sx[ct][1] += v1.x + v1.y + v3.x + v3.y;
            uint32_t a0 = f2bf2(v0.x, v0.y);
            uint32_t a1 = f2bf2(v1.x, v1.y);
            uint32_t a2 = f2bf2(v2.x, v2.y);
            uint32_t a3 = f2bf2(v3.x, v3.y);
            #pragma unroll
            for (int mt = 0; mt < 4; mt++)
                mma_bf16(e[ct][mt][0], e[ct][mt][1], e[ct][mt][2], e[ct][mt][3],
                         a0, a1, a2, a3, bb0[mt], bb1[mt]);
        }
    }

    #pragma unroll
    for (int ct = 0; ct < 2; ct++) {
        float v0 = sx[ct][0], v1 = sx[ct][1];
        v0 += __shfl_xor_sync(0xffffffffu, v0, 1); v0 += __shfl_xor_sync(0xffffffffu, v0, 2);
        v1 += __shfl_xor_sync(0xffffffffu, v1, 1); v1 += __shfl_xor_sync(0xffffffffu, v1, 2);
        if (tig == 0) {
            const int c0 = 32 * w + 16 * ct;
            atomicAdd(&g_xsum[b * CC + c0 + gid],     v0);
            atomicAdd(&g_xsum[b * CC + c0 + 8 + gid], v1);
        }
    }
    float* mpb = &g_mpT[b * CC * CQ];
    #pragma unroll
    for (int ct = 0; ct < 2; ct++) {
        const int c0 = 32 * w + 16 * ct;
        #pragma unroll
        for (int mt = 0; mt < 4; mt++) {
            const int m0 = mt * 8 + 2 * tig;
            atomicAdd(&mpb[(c0 + gid) * CQ + m0],         e[ct][mt][0]);
            atomicAdd(&mpb[(c0 + gid) * CQ + m0 + 1],     e[ct][mt][1]);
            atomicAdd(&mpb[(c0 + 8 + gid) * CQ + m0],     e[ct][mt][2]);
            atomicAdd(&mpb[(c0 + 8 + gid) * CQ + m0 + 1], e[ct][mt][3]);
        }
    }
}

// ---------------- kernel 2: matrix = mp @ Wv^T + bv (x) S ; vsum; fragments -
// 128 blocks: (b, 16-cp group). 256 threads = 16 cl x 16 mg (2 m each).
__global__ void __launch_bounds__(256)
k_mat(const float* __restrict__ Wv, const float* __restrict__ bv) {
    extern __shared__ float shm[];
    float* mpT_s = shm;                 // [256 c][32 m]
    float* wv_s  = shm + CC * CQ;       // [16 cl][257]
    float* xs_s  = wv_s + 16 * 257;     // [256]
    float* S_s   = xs_s + CC;           // [32]

    const int b  = blockIdx.x >> 4;
    const int cg = (blockIdx.x & 15) * 16;
    const int tid = threadIdx.x;

    for (int idx = tid; idx < CC * CQ; idx += 256)
        mpT_s[idx] = g_mpT[b * CC * CQ + idx];
    for (int idx = tid; idx < 16 * CC; idx += 256) {
        int cl = idx >> 8, c = idx & 255;
        wv_s[cl * 257 + c] = Wv[(cg + cl) * CC + c];
    }
    xs_s[tid] = g_xsum[b * CC + tid];
    if (tid < 32) S_s[tid] = g_S[b * CQ + tid];
    __syncthreads();

    const int cl = tid & 15;            // local cp
    const int mg = tid >> 4;            // m pair index (m = 2mg, 2mg+1)
    const int cp = cg + cl;
    const float bvv = __ldg(&bv[cp]);

    float acc0 = bvv * S_s[mg * 2];
    float acc1 = bvv * S_s[mg * 2 + 1];
    float vs = (float)NN * bvv;

    const float* wrow = &wv_s[cl * 257];
    #pragma unroll 8
    for (int c = 0; c < CC; ++c) {
        float wv = wrow[c];
        vs += wv * xs_s[c];
        const float2 mv = *(const float2*)&mpT_s[c * CQ + mg * 2];
        acc0 += mv.x * wv;
        acc1 += mv.y * wv;
    }
    if (mg == 0) g_vsum[b * CC + cp] = vs;

    // scatter into bf16 mfrag A-layout: pair (2mg, 2mg+1) is one bf16x2 element
    const int ct = cp >> 4, cl16 = cp & 15;
    const int gidf = cl16 & 7, hi_row = cl16 >> 3;
    const int kk = mg >> 3, tigf = mg & 3, half = (mg >> 2) & 1;
    const int elem = hi_row + 2 * half;
    g_mfrag[((((b * 16 + ct) * 2 + kk) * 32) + gidf * 4 + tigf) * 4 + elem] = f2bf2(acc0, acc1);
}

// ---------------- kernel 3: streaming epilogue, 2 j-tiles per warp (bf16) ---
__global__ void __launch_bounds__(256)
k_pass2(const float* __restrict__ x, const float* __restrict__ gamma,
        float* __restrict__ out) {
    const int tid = threadIdx.x;
    const int w = tid >> 5, lane = tid & 31, gid = lane >> 2, tig = lane & 3;
    const int b   = blockIdx.x >> 7;
    const int jt0 = (blockIdx.x & 127) * 16 + w * 2;
    const int n0  = jt0 * 8;
    const float gm = __ldg(&gamma[0]);

    const uint4* qf = g_qfrag + (size_t)(b * 2048 + jt0) * 32 + lane;
    uint4 P = __ldg(qf);          // tile 0: {b0k0, b1k0, b0k1, b1k1}
    uint4 R = __ldg(qf + 32);     // tile 1

    // tailor: per-lane m coverage {2tig,2tig+1, +8, +16, +24 pairs}
    const int mt2 = 2 * tig;
    float se[8];
    #pragma unroll
    for (int i = 0; i < 4; i++) {
        se[2 * i]     = __ldg(&g_S[b * CQ + 8 * i + mt2])     + EPSV;
        se[2 * i + 1] = __ldg(&g_S[b * CQ + 8 * i + mt2 + 1]) + EPSV;
    }
    float tl0 = bf_lo(P.x) * se[0] + bf_hi(P.x) * se[1]
              + bf_lo(P.y) * se[2] + bf_hi(P.y) * se[3]
              + bf_lo(P.z) * se[4] + bf_hi(P.z) * se[5]
              + bf_lo(P.w) * se[6] + bf_hi(P.w) * se[7];
    float tl1 = bf_lo(R.x) * se[0] + bf_hi(R.x) * se[1]
              + bf_lo(R.y) * se[2] + bf_hi(R.y) * se[3]
              + bf_lo(R.z) * se[4] + bf_hi(R.z) * se[5]
              + bf_lo(R.w) * se[6] + bf_hi(R.w) * se[7];
    tl0 += __shfl_xor_sync(0xffffffffu, tl0, 1);
    tl0 += __shfl_xor_sync(0xffffffffu, tl0, 2);
    tl1 += __shfl_xor_sync(0xffffffffu, tl1, 1);
    tl1 += __shfl_xor_sync(0xffffffffu, tl1, 2);
    const float g0 = gm / (16384.f + tl0);
    const float g1 = gm / (16384.f + tl1);
    const float gt0e = __shfl_sync(0xffffffffu, g0, 8 * tig);      // j = 2tig
    const float gt0o = __shfl_sync(0xffffffffu, g0, 8 * tig + 4);  // j = 2tig+1
    const float gt1e = __shfl_sync(0xffffffffu, g1, 8 * tig);
    const float gt1o = __shfl_sync(0xffffffffu, g1, 8 * tig + 4);

    const float* xp = x   + (size_t)b * CC * NN + n0;
    float*       op = out + (size_t)b * CC * NN + n0;
    const uint4* mf = (const uint4*)g_mfrag + (size_t)b * 16 * 2 * 32 + lane;
    const float* vs = g_vsum + b * CC;
    const int jj = 2 * tig;

    #pragma unroll 4
    for (int ct = 0; ct < 16; ct++) {
        const uint4* base = mf + ct * 64;
        uint4 A0 = __ldg(base);         // kk = 0 (m 0..15)
        uint4 A1 = __ldg(base + 32);    // kk = 1 (m 16..31)
        float e0 = 0.f, e1 = 0.f, e2 = 0.f, e3 = 0.f;   // tile0
        float f0 = 0.f, f1 = 0.f, f2 = 0.f, f3 = 0.f;   // tile1
        mma_bf16(e0, e1, e2, e3, A0.x, A0.y, A0.z, A0.w, P.x, P.y);
        mma_bf16(f0, f1, f2, f3, A0.x, A0.y, A0.z, A0.w, R.x, R.y);
        mma_bf16(e0, e1, e2, e3, A1.x, A1.y, A1.z, A1.w, P.z, P.w);
        mma_bf16(f0, f1, f2, f3, A1.x, A1.y, A1.z, A1.w, R.z, R.w);

        const int c1 = ct * 16 + gid;
        const int c2 = c1 + 8;
        const float v1 = __ldg(&vs[c1]), v2 = __ldg(&vs[c2]);
        float2 x10 = *(const float2*)(xp + (size_t)c1 * NN + jj);
        float2 x11 = *(const float2*)(xp + (size_t)c1 * NN + 8 + jj);
        float2 x20 = *(const float2*)(xp + (size_t)c2 * NN + jj);
        float2 x21 = *(const float2*)(xp + (size_t)c2 * NN + 8 + jj);
        float2 o10, o11, o20, o21;
        o10.x = x10.x + gt0e * (v1 + e0);
        o10.y = x10.y + gt0o * (v1 + e1);
        o11.x = x11.x + gt1e * (v1 + f0);
        o11.y = x11.y + gt1o * (v1 + f1);
        o20.x = x20.x + gt0e * (v2 + e2);
        o20.y = x20.y + gt0o * (v2 + e3);
        o21.x = x21.x + gt1e * (v2 + f2);
        o21.y = x21.y + gt1o * (v2 + f3);
        __stcs((float2*)(op + (size_t)c1 * NN + jj),     o10);
        __stcs((float2*)(op + (size_t)c1 * NN + 8 + jj), o11);
        __stcs((float2*)(op + (size_t)c2 * NN + jj),     o20);
        __stcs((float2*)(op + (size_t)c2 * NN + 8 + jj), o21);
    }
}

// ---------------- launch --------------------------------------------------
extern "C" void kernel_launch(void* const* d_in, const int* in_sizes, int n_in,
                              void* d_out, int out_size) {
    const float* x     = (const float*)d_in[0];
    const float* Wq    = (const float*)d_in[1];
    const float* bq    = (const float*)d_in[2];
    const float* Wk    = (const float*)d_in[3];
    const float* bk    = (const float*)d_in[4];
    const float* Wv    = (const float*)d_in[5];
    const float* bv    = (const float*)d_in[6];
    const float* gamma = (const float*)d_in[7];
    float* out = (float*)d_out;

    const int shMat = (CC * CQ + 16 * 257 + CC + CQ) * (int)sizeof(float);
    cudaFuncSetAttribute(k_mat, cudaFuncAttributeMaxDynamicSharedMemorySize, shMat);

    k_prep<<<256, 256>>>(Wq, Wk);
    k_fused<<<BB * 64, 256>>>(x, bq, bk);      // 512 blocks: proj + mpT
    k_mat<<<BB * 16, 256, shMat>>>(Wv, bv);    // 128 blocks
    k_pass2<<<BB * 128, 256>>>(x, gamma, out); // 1024 blocks, warp = 16 j
}

// round 12
// speedup vs baseline: 1.5761x; 1.2892x over previous
#include <cuda_runtime.h>
#include <cstdint>

#define BB   8
#define CC   256
#define CQ   32
#define NN   16384
#define EPSV 1e-6f

// ---------------- scratch (device globals) ---------------------------------
__device__ __align__(16) uint32_t g_WtF[4 * 16 * 32 * 4];   // bf16 A-frags; wo 0-1 = Wq, 2-3 = Wk
__device__ float g_mpT[BB * CC * CQ];                       // (Kn @ x^T)^T : [b][c][m]
__device__ float g_S[BB * CQ];                              // sum_n Kn
__device__ float g_xsum[BB * CC];                           // sum_n x
__device__ __align__(16) uint32_t g_mfrag[BB * 16 * 2 * 32 * 4]; // matT bf16 A-frags
__device__ float g_vsum[BB * CC];                           // value_sum
__device__ __align__(16) uint4 g_qfrag[(size_t)BB * 2048 * 32]; // Qn bf16 B-frags [b][jt][lane]

// pack two fp32 -> bf16x2 (lo in bits 0-15, hi in bits 16-31)
__device__ __forceinline__ uint32_t f2bf2(float lo, float hi) {
    uint32_t r;
    asm("cvt.rn.bf16x2.f32 %0, %1, %2;" : "=r"(r) : "f"(hi), "f"(lo));
    return r;
}
__device__ __forceinline__ float bf_lo(uint32_t v) { return __uint_as_float(v << 16); }
__device__ __forceinline__ float bf_hi(uint32_t v) { return __uint_as_float(v & 0xffff0000u); }

__device__ __forceinline__ void mma_bf16(float& d0, float& d1, float& d2, float& d3,
                                         uint32_t a0, uint32_t a1, uint32_t a2, uint32_t a3,
                                         uint32_t b0, uint32_t b1) {
    asm volatile(
        "mma.sync.aligned.m16n8k16.row.col.f32.bf16.bf16.f32 "
        "{%0,%1,%2,%3},{%4,%5,%6,%7},{%8,%9},{%0,%1,%2,%3};"
        : "+f"(d0), "+f"(d1), "+f"(d2), "+f"(d3)
        : "r"(a0), "r"(a1), "r"(a2), "r"(a3), "r"(b0), "r"(b1));
}

// ---------------- kernel 0: zero accumulators + build bf16 W-fragments -----
__global__ void k_prep(const float* __restrict__ Wq, const float* __restrict__ Wk) {
    int idx = blockIdx.x * blockDim.x + threadIdx.x;      // 65536 threads
    if (idx < BB * CC * CQ) g_mpT[idx] = 0.f;
    if (idx < 8192) {
        int f    = idx & 3;           // a0..a3
        int lane = (idx >> 2) & 31;
        int kk   = (idx >> 7) & 15;
        int wo   = (idx >> 11) & 3;
        int gid = lane >> 2, tig = lane & 3;
        int o = (wo & 1) * 16 + gid + (f & 1) * 8;
        int c = kk * 16 + 2 * tig + (f >> 1) * 8;
        const float* W = (wo < 2) ? Wq : Wk;
        g_WtF[idx] = f2bf2(W[o * CC + c], W[o * CC + c + 1]);
    }
    if (idx < BB * CC) g_xsum[idx] = 0.f;
    if (idx < BB * CQ) g_S[idx] = 0.f;
}

// ---------------- kernel 1: FUSED Q+K proj + Qn frags + S + xsum + mpT ------
// block = (b, 256-j slice). Phase A: proj with 2 subtiles interleaved per warp
// (8 indep LDG + 8 indep mma chains per kk). Phase B: mpT mma (x re-read, L2).
__global__ void __launch_bounds__(256)
k_fused(const float* __restrict__ x, const float* __restrict__ bq,
        const float* __restrict__ bk) {
    __shared__ uint32_t kb[32][132];     // Kn bf16x2 j-pairs: [m][jpair]
    __shared__ float qts[8 * 288];       // per-warp Qn fp32 transpose scratch

    const int tid = threadIdx.x;
    const int w = tid >> 5, lane = tid & 31, gid = lane >> 2, tig = lane & 3;
    const int b   = blockIdx.x >> 6;
    const int jsl = blockIdx.x & 63;                 // 256-j slice
    const float* xb = x + (size_t)b * CC * NN;

    const float bq0 = __ldg(&bq[gid]),      bq1 = __ldg(&bq[gid + 8]);
    const float bq2 = __ldg(&bq[gid + 16]), bq3 = __ldg(&bq[gid + 24]);
    const float bk0 = __ldg(&bk[gid]),      bk1 = __ldg(&bk[gid + 8]);
    const float bk2 = __ldg(&bk[gid + 16]), bk3 = __ldg(&bk[gid + 24]);

    const uint4* Wt = (const uint4*)g_WtF + lane;
    float* Qf = qts + w * 288;                       // [32 o][9] fp32 slice

    float S0 = 0.f, S1 = 0.f, S2 = 0.f, S3 = 0.f;

    // ================= phase A: projections, 2 subtiles per iteration ========
    #pragma unroll 1
    for (int sp = 0; sp < 2; sp++) {
        const int jb0 = jsl * 256 + (2 * sp) * 64 + w * 8;  // subtile 2sp
        const float* xp0 = xb + (size_t)(2 * tig) * NN + jb0 + gid;
        const float* xp1 = xp0 + 64;                        // subtile 2sp+1

        float dq[2][2][4], dk[2][2][4];    // [tile][o-half][quad]
        #pragma unroll
        for (int t = 0; t < 2; t++)
            #pragma unroll
            for (int h = 0; h < 2; h++)
                #pragma unroll
                for (int q = 0; q < 4; q++) { dq[t][h][q] = 0.f; dk[t][h][q] = 0.f; }

        #pragma unroll 4
        for (int kk = 0; kk < 16; kk++) {
            const size_t r0 = (size_t)(16 * kk) * NN;
            // tile 0 loads (4 indep) + tile 1 loads (4 indep)
            float u0 = __ldg(xp0 + r0);
            float u1 = __ldg(xp0 + r0 + NN);
            float u2 = __ldg(xp0 + r0 + 8 * NN);
            float u3 = __ldg(xp0 + r0 + 9 * NN);
            float v0 = __ldg(xp1 + r0);
            float v1 = __ldg(xp1 + r0 + NN);
            float v2 = __ldg(xp1 + r0 + 8 * NN);
            float v3 = __ldg(xp1 + r0 + 9 * NN);
            uint32_t ub0 = f2bf2(u0, u1), ub1 = f2bf2(u2, u3);
            uint32_t vb0 = f2bf2(v0, v1), vb1 = f2bf2(v2, v3);
            uint4 a;
            a = Wt[kk * 32];
            mma_bf16(dq[0][0][0], dq[0][0][1], dq[0][0][2], dq[0][0][3], a.x, a.y, a.z, a.w, ub0, ub1);
            mma_bf16(dq[1][0][0], dq[1][0][1], dq[1][0][2], dq[1][0][3], a.x, a.y, a.z, a.w, vb0, vb1);
            a = Wt[512 + kk * 32];
            mma_bf16(dq[0][1][0], dq[0][1][1], dq[0][1][2], dq[0][1][3], a.x, a.y, a.z, a.w, ub0, ub1);
            mma_bf16(dq[1][1][0], dq[1][1][1], dq[1][1][2], dq[1][1][3], a.x, a.y, a.z, a.w, vb0, vb1);
            a = Wt[1024 + kk * 32];
            mma_bf16(dk[0][0][0], dk[0][0][1], dk[0][0][2], dk[0][0][3], a.x, a.y, a.z, a.w, ub0, ub1);
            mma_bf16(dk[1][0][0], dk[1][0][1], dk[1][0][2], dk[1][0][3], a.x, a.y, a.z, a.w, vb0, vb1);
            a = Wt[1536 + kk * 32];
            mma_bf16(dk[0][1][0], dk[0][1][1], dk[0][1][2], dk[0][1][3], a.x, a.y, a.z, a.w, ub0, ub1);
            mma_bf16(dk[1][1][0], dk[1][1][1], dk[1][1][2], dk[1][1][3], a.x, a.y, a.z, a.w, vb0, vb1);
        }

        // ---- per-tile epilogue (norms, S, kb, qfrag) ----
        #pragma unroll
        for (int t = 0; t < 2; t++) {
            const int sub = 2 * sp + t;
            const int jbase = jb0 + 64 * t;
            const int jt = jbase >> 3;

            float q00 = dq[t][0][0] + bq0, q01 = dq[t][0][1] + bq0;
            float q02 = dq[t][0][2] + bq1, q03 = dq[t][0][3] + bq1;
            float q10 = dq[t][1][0] + bq2, q11 = dq[t][1][1] + bq2;
            float q12 = dq[t][1][2] + bq3, q13 = dq[t][1][3] + bq3;
            float c00 = dk[t][0][0] + bk0, c01 = dk[t][0][1] + bk0;
            float c02 = dk[t][0][2] + bk1, c03 = dk[t][0][3] + bk1;
            float c10 = dk[t][1][0] + bk2, c11 = dk[t][1][1] + bk2;
            float c12 = dk[t][1][2] + bk3, c13 = dk[t][1][3] + bk3;

            float qe = q00*q00 + q02*q02 + q10*q10 + q12*q12;
            float qo = q01*q01 + q03*q03 + q11*q11 + q13*q13;
            float ke = c00*c00 + c02*c02 + c10*c10 + c12*c12;
            float ko = c01*c01 + c03*c03 + c11*c11 + c13*c13;
            #pragma unroll
            for (int off = 4; off <= 16; off <<= 1) {
                qe += __shfl_xor_sync(0xffffffffu, qe, off);
                qo += __shfl_xor_sync(0xffffffffu, qo, off);
                ke += __shfl_xor_sync(0xffffffffu, ke, off);
                ko += __shfl_xor_sync(0xffffffffu, ko, off);
            }
            const float rqe = rsqrtf(qe), rqo = rsqrtf(qo);
            const float rke = rsqrtf(ke), rko = rsqrtf(ko);

            float k00 = c00*rke, k01 = c01*rko, k02 = c02*rke, k03 = c03*rko;
            float k10 = c10*rke, k11 = c11*rko, k12 = c12*rke, k13 = c13*rko;
            float s0 = k00 + k01, s1 = k02 + k03, s2 = k10 + k11, s3 = k12 + k13;
            s0 += __shfl_xor_sync(0xffffffffu, s0, 1); s0 += __shfl_xor_sync(0xffffffffu, s0, 2);
            s1 += __shfl_xor_sync(0xffffffffu, s1, 1); s1 += __shfl_xor_sync(0xffffffffu, s1, 2);
            s2 += __shfl_xor_sync(0xffffffffu, s2, 1); s2 += __shfl_xor_sync(0xffffffffu, s2, 2);
            s3 += __shfl_xor_sync(0xffffffffu, s3, 1); s3 += __shfl_xor_sync(0xffffffffu, s3, 2);
            S0 += s0; S1 += s1; S2 += s2; S3 += s3;

            // Kn bf16 j-pairs -> kb
            {
                const int jp = sub * 32 + w * 4 + tig;
                kb[gid][jp]      = f2bf2(k00, k01);
                kb[gid + 8][jp]  = f2bf2(k02, k03);
                kb[gid + 16][jp] = f2bf2(k10, k11);
                kb[gid + 24][jp] = f2bf2(k12, k13);
            }

            // Qn -> scratch -> bf16 B-frags -> qfrag
            const int jl = 2 * tig;
            Qf[(gid)      * 9 + jl]     = q00 * rqe;
            Qf[(gid)      * 9 + jl + 1] = q01 * rqo;
            Qf[(gid + 8)  * 9 + jl]     = q02 * rqe;
            Qf[(gid + 8)  * 9 + jl + 1] = q03 * rqo;
            Qf[(gid + 16) * 9 + jl]     = q10 * rqe;
            Qf[(gid + 16) * 9 + jl + 1] = q11 * rqo;
            Qf[(gid + 24) * 9 + jl]     = q12 * rqe;
            Qf[(gid + 24) * 9 + jl + 1] = q13 * rqo;
            __syncwarp();
            {
                uint4 Bv;
                Bv.x = f2bf2(Qf[(2 * tig)      * 9 + gid], Qf[(2 * tig + 1)  * 9 + gid]);
                Bv.y = f2bf2(Qf[(2 * tig + 8)  * 9 + gid], Qf[(2 * tig + 9)  * 9 + gid]);
                Bv.z = f2bf2(Qf[(2 * tig + 16) * 9 + gid], Qf[(2 * tig + 17) * 9 + gid]);
                Bv.w = f2bf2(Qf[(2 * tig + 24) * 9 + gid], Qf[(2 * tig + 25) * 9 + gid]);
                g_qfrag[(size_t)(b * 2048 + jt) * 32 + lane] = Bv;
            }
            __syncwarp();
        }
    }

    if (tig == 0) {
        atomicAdd(&g_S[b * CQ + gid],      S0);
        atomicAdd(&g_S[b * CQ + gid + 8],  S1);
        atomicAdd(&g_S[b * CQ + gid + 16], S2);
        atomicAdd(&g_S[b * CQ + gid + 24], S3);
    }
    __syncthreads();         // all Kn pairs visible

    // ================= phase B: mpT = x @ Kn^T over this slice (k16) ========
    float e[2][4][4];
    #pragma unroll
    for (int ct = 0; ct < 2; ct++)
        #pragma unroll
        for (int mt = 0; mt < 4; mt++)
            #pragma unroll
            for (int q = 0; q < 4; q++) e[ct][mt][q] = 0.f;
    float sx[2][2] = {{0.f, 0.f}, {0.f, 0.f}};

    #pragma unroll 2
    for (int kk = 0; kk < 16; kk++) {
        const int jg = jsl * 256 + kk * 16;
        uint32_t bb0[4], bb1[4];
        #pragma unroll
        for (int mt = 0; mt < 4; mt++) {
            bb0[mt] = kb[8 * mt + gid][8 * kk + tig];
            bb1[mt] = kb[8 * mt + gid][8 * kk + 4 + tig];
        }
        #pragma unroll
        for (int ct = 0; ct < 2; ct++) {
            const int c0 = 32 * w + 16 * ct;
            float2 v0 = *(const float2*)(xb + (size_t)(c0 + gid)     * NN + jg + 2 * tig);
            float2 v1 = *(const float2*)(xb + (size_t)(c0 + 8 + gid) * NN + jg + 2 * tig);
            float2 v2 = *(const float2*)(xb + (size_t)(c0 + gid)     * NN + jg + 8 + 2 * tig);
            float2 v3 = *(const float2*)(xb + (size_t)(c0 + 8 + gid) * NN + jg + 8 + 2 * tig);
            sx[ct][0] += v0.x + v0.y + v2.x + v2.y;
            sx[ct][1] += v1.x + v1.y + v3.x + v3.y;
            uint32_t a0 = f2bf2(v0.x, v0.y);
            uint32_t a1 = f2bf2(v1.x, v1.y);
            uint32_t a2 = f2bf2(v2.x, v2.y);
            uint32_t a3 = f2bf2(v3.x, v3.y);
            #pragma unroll
            for (int mt = 0; mt < 4; mt++)
                mma_bf16(e[ct][mt][0], e[ct][mt][1], e[ct][mt][2], e[ct][mt][3],
                         a0, a1, a2, a3, bb0[mt], bb1[mt]);
        }
    }

    #pragma unroll
    for (int ct = 0; ct < 2; ct++) {
        float v0 = sx[ct][0], v1 = sx[ct][1];
        v0 += __shfl_xor_sync(0xffffffffu, v0, 1); v0 += __shfl_xor_sync(0xffffffffu, v0, 2);
        v1 += __shfl_xor_sync(0xffffffffu, v1, 1); v1 += __shfl_xor_sync(0xffffffffu, v1, 2);
        if (tig == 0) {
            const int c0 = 32 * w + 16 * ct;
            atomicAdd(&g_xsum[b * CC + c0 + gid],     v0);
            atomicAdd(&g_xsum[b * CC + c0 + 8 + gid], v1);
        }
    }
    float* mpb = &g_mpT[b * CC * CQ];
    #pragma unroll
    for (int ct = 0; ct < 2; ct++) {
        const int c0 = 32 * w + 16 * ct;
        #pragma unroll
        for (int mt = 0; mt < 4; mt++) {
            const int m0 = mt * 8 + 2 * tig;
            atomicAdd(&mpb[(c0 + gid) * CQ + m0],         e[ct][mt][0]);
            atomicAdd(&mpb[(c0 + gid) * CQ + m0 + 1],     e[ct][mt][1]);
            atomicAdd(&mpb[(c0 + 8 + gid) * CQ + m0],     e[ct][mt][2]);
            atomicAdd(&mpb[(c0 + 8 + gid) * CQ + m0 + 1], e[ct][mt][3]);
        }
    }
}

// ---------------- kernel 2: matrix = mp @ Wv^T + bv (x) S ; vsum; fragments -
__global__ void __launch_bounds__(256)
k_mat(const float* __restrict__ Wv, const float* __restrict__ bv) {
    extern __shared__ float shm[];
    float* mpT_s = shm;                 // [256 c][32 m]
    float* wv_s  = shm + CC * CQ;       // [16 cl][257]
    float* xs_s  = wv_s + 16 * 257;     // [256]
    float* S_s   = xs_s + CC;           // [32]

    const int b  = blockIdx.x >> 4;
    const int cg = (blockIdx.x & 15) * 16;
    const int tid = threadIdx.x;

    for (int idx = tid; idx < CC * CQ; idx += 256)
        mpT_s[idx] = g_mpT[b * CC * CQ + idx];
    for (int idx = tid; idx < 16 * CC; idx += 256) {
        int cl = idx >> 8, c = idx & 255;
        wv_s[cl * 257 + c] = Wv[(cg + cl) * CC + c];
    }
    xs_s[tid] = g_xsum[b * CC + tid];
    if (tid < 32) S_s[tid] = g_S[b * CQ + tid];
    __syncthreads();

    const int cl = tid & 15;            // local cp
    const int mg = tid >> 4;            // m pair index (m = 2mg, 2mg+1)
    const int cp = cg + cl;
    const float bvv = __ldg(&bv[cp]);

    float acc0 = bvv * S_s[mg * 2];
    float acc1 = bvv * S_s[mg * 2 + 1];
    float vs = (float)NN * bvv;

    const float* wrow = &wv_s[cl * 257];
    #pragma unroll 8
    for (int c = 0; c < CC; ++c) {
        float wv = wrow[c];
        vs += wv * xs_s[c];
        const float2 mv = *(const float2*)&mpT_s[c * CQ + mg * 2];
        acc0 += mv.x * wv;
        acc1 += mv.y * wv;
    }
    if (mg == 0) g_vsum[b * CC + cp] = vs;

    // scatter into bf16 mfrag A-layout
    const int ct = cp >> 4, cl16 = cp & 15;
    const int gidf = cl16 & 7, hi_row = cl16 >> 3;
    const int kk = mg >> 3, tigf = mg & 3, half = (mg >> 2) & 1;
    const int elem = hi_row + 2 * half;
    g_mfrag[((((b * 16 + ct) * 2 + kk) * 32) + gidf * 4 + tigf) * 4 + elem] = f2bf2(acc0, acc1);
}

// ---------------- kernel 3: streaming epilogue, 2 j-tiles per warp (bf16) ---
__global__ void __launch_bounds__(256)
k_pass2(const float* __restrict__ x, const float* __restrict__ gamma,
        float* __restrict__ out) {
    const int tid = threadIdx.x;
    const int w = tid >> 5, lane = tid & 31, gid = lane >> 2, tig = lane & 3;
    const int b   = blockIdx.x >> 7;
    const int jt0 = (blockIdx.x & 127) * 16 + w * 2;
    const int n0  = jt0 * 8;
    const float gm = __ldg(&gamma[0]);

    const uint4* qf = g_qfrag + (size_t)(b * 2048 + jt0) * 32 + lane;
    uint4 P = __ldg(qf);          // tile 0
    uint4 R = __ldg(qf + 32);     // tile 1

    const int mt2 = 2 * tig;
    float se[8];
    #pragma unroll
    for (int i = 0; i < 4; i++) {
        se[2 * i]     = __ldg(&g_S[b * CQ + 8 * i + mt2])     + EPSV;
        se[2 * i + 1] = __ldg(&g_S[b * CQ + 8 * i + mt2 + 1]) + EPSV;
    }
    float tl0 = bf_lo(P.x) * se[0] + bf_hi(P.x) * se[1]
              + bf_lo(P.y) * se[2] + bf_hi(P.y) * se[3]
              + bf_lo(P.z) * se[4] + bf_hi(P.z) * se[5]
              + bf_lo(P.w) * se[6] + bf_hi(P.w) * se[7];
    float tl1 = bf_lo(R.x) * se[0] + bf_hi(R.x) * se[1]
              + bf_lo(R.y) * se[2] + bf_hi(R.y) * se[3]
              + bf_lo(R.z) * se[4] + bf_hi(R.z) * se[5]
              + bf_lo(R.w) * se[6] + bf_hi(R.w) * se[7];
    tl0 += __shfl_xor_sync(0xffffffffu, tl0, 1);
    tl0 += __shfl_xor_sync(0xffffffffu, tl0, 2);
    tl1 += __shfl_xor_sync(0xffffffffu, tl1, 1);
    tl1 += __shfl_xor_sync(0xffffffffu, tl1, 2);
    const float g0 = gm / (16384.f + tl0);
    const float g1 = gm / (16384.f + tl1);
    const float gt0e = __shfl_sync(0xffffffffu, g0, 8 * tig);
    const float gt0o = __shfl_sync(0xffffffffu, g0, 8 * tig + 4);
    const float gt1e = __shfl_sync(0xffffffffu, g1, 8 * tig);
    const float gt1o = __shfl_sync(0xffffffffu, g1, 8 * tig + 4);

    const float* xp = x   + (size_t)b * CC * NN + n0;
    float*       op = out + (size_t)b * CC * NN + n0;
    const uint4* mf = (const uint4*)g_mfrag + (size_t)b * 16 * 2 * 32 + lane;
    const float* vs = g_vsum + b * CC;
    const int jj = 2 * tig;

    #pragma unroll 4
    for (int ct = 0; ct < 16; ct++) {
        const uint4* base = mf + ct * 64;
        uint4 A0 = __ldg(base);         // kk = 0 (m 0..15)
        uint4 A1 = __ldg(base + 32);    // kk = 1 (m 16..31)
        float e0 = 0.f, e1 = 0.f, e2 = 0.f, e3 = 0.f;
        float f0 = 0.f, f1 = 0.f, f2 = 0.f, f3 = 0.f;
        mma_bf16(e0, e1, e2, e3, A0.x, A0.y, A0.z, A0.w, P.x, P.y);
        mma_bf16(f0, f1, f2, f3, A0.x, A0.y, A0.z, A0.w, R.x, R.y);
        mma_bf16(e0, e1, e2, e3, A1.x, A1.y, A1.z, A1.w, P.z, P.w);
        mma_bf16(f0, f1, f2, f3, A1.x, A1.y, A1.z, A1.w, R.z, R.w);

        const int c1 = ct * 16 + gid;
        const int c2 = c1 + 8;
        const float v1 = __ldg(&vs[c1]), v2 = __ldg(&vs[c2]);
        float2 x10 = *(const float2*)(xp + (size_t)c1 * NN + jj);
        float2 x11 = *(const float2*)(xp + (size_t)c1 * NN + 8 + jj);
        float2 x20 = *(const float2*)(xp + (size_t)c2 * NN + jj);
        float2 x21 = *(const float2*)(xp + (size_t)c2 * NN + 8 + jj);
        float2 o10, o11, o20, o21;
        o10.x = x10.x + gt0e * (v1 + e0);
        o10.y = x10.y + gt0o * (v1 + e1);
        o11.x = x11.x + gt1e * (v1 + f0);
        o11.y = x11.y + gt1o * (v1 + f1);
        o20.x = x20.x + gt0e * (v2 + e2);
        o20.y = x20.y + gt0o * (v2 + e3);
        o21.x = x21.x + gt1e * (v2 + f2);
        o21.y = x21.y + gt1o * (v2 + f3);
        __stcs((float2*)(op + (size_t)c1 * NN + jj),     o10);
        __stcs((float2*)(op + (size_t)c1 * NN + 8 + jj), o11);
        __stcs((float2*)(op + (size_t)c2 * NN + jj),     o20);
        __stcs((float2*)(op + (size_t)c2 * NN + 8 + jj), o21);
    }
}

// ---------------- launch --------------------------------------------------
extern "C" void kernel_launch(void* const* d_in, const int* in_sizes, int n_in,
                              void* d_out, int out_size) {
    const float* x     = (const float*)d_in[0];
    const float* Wq    = (const float*)d_in[1];
    const float* bq    = (const float*)d_in[2];
    const float* Wk    = (const float*)d_in[3];
    const float* bk    = (const float*)d_in[4];
    const float* Wv    = (const float*)d_in[5];
    const float* bv    = (const float*)d_in[6];
    const float* gamma = (const float*)d_in[7];
    float* out = (float*)d_out;

    const int shMat = (CC * CQ + 16 * 257 + CC + CQ) * (int)sizeof(float);
    cudaFuncSetAttribute(k_mat, cudaFuncAttributeMaxDynamicSharedMemorySize, shMat);

    k_prep<<<256, 256>>>(Wq, Wk);
    k_fused<<<BB * 64, 256>>>(x, bq, bk);      // 512 blocks: proj(2-tile ILP) + mpT
    k_mat<<<BB * 16, 256, shMat>>>(Wv, bv);    // 128 blocks
    k_pass2<<<BB * 128, 256>>>(x, gamma, out); // 1024 blocks, warp = 16 j
}

// round 13
// speedup vs baseline: 1.6772x; 1.0641x over previous
#include <cuda_runtime.h>
#include <cstdint>

#define BB   8
#define CC   256
#define CQ   32
#define NN   16384
#define EPSV 1e-6f

// ---------------- scratch (device globals) ---------------------------------
__device__ __align__(16) uint32_t g_WtF[4 * 16 * 32 * 4];   // bf16 A-frags; wo 0-1 = Wq, 2-3 = Wk
__device__ float g_mpT[BB * CC * CQ];                       // (Kn @ x^T)^T : [b][c][m]
__device__ float g_S[BB * CQ];                              // sum_n Kn
__device__ float g_xsum[BB * CC];                           // sum_n x
__device__ __align__(16) uint32_t g_mfrag[BB * 16 * 2 * 32 * 4]; // matT bf16 A-frags
__device__ float g_vsum[BB * CC];                           // value_sum
__device__ __align__(16) uint4 g_qfrag[(size_t)BB * 2048 * 32]; // Qn bf16 B-frags [b][jt][lane]

// pack two fp32 -> bf16x2 (lo in bits 0-15, hi in bits 16-31)
__device__ __forceinline__ uint32_t f2bf2(float lo, float hi) {
    uint32_t r;
    asm("cvt.rn.bf16x2.f32 %0, %1, %2;" : "=r"(r) : "f"(hi), "f"(lo));
    return r;
}
__device__ __forceinline__ float bf_lo(uint32_t v) { return __uint_as_float(v << 16); }
__device__ __forceinline__ float bf_hi(uint32_t v) { return __uint_as_float(v & 0xffff0000u); }

__device__ __forceinline__ void mma_bf16(float& d0, float& d1, float& d2, float& d3,
                                         uint32_t a0, uint32_t a1, uint32_t a2, uint32_t a3,
                                         uint32_t b0, uint32_t b1) {
    asm volatile(
        "mma.sync.aligned.m16n8k16.row.col.f32.bf16.bf16.f32 "
        "{%0,%1,%2,%3},{%4,%5,%6,%7},{%8,%9},{%0,%1,%2,%3};"
        : "+f"(d0), "+f"(d1), "+f"(d2), "+f"(d3)
        : "r"(a0), "r"(a1), "r"(a2), "r"(a3), "r"(b0), "r"(b1));
}

// ---------------- kernel 0: zero accumulators + build bf16 W-fragments -----
__global__ void k_prep(const float* __restrict__ Wq, const float* __restrict__ Wk) {
    int idx = blockIdx.x * blockDim.x + threadIdx.x;      // 65536 threads
    if (idx < BB * CC * CQ) g_mpT[idx] = 0.f;
    if (idx < 8192) {
        int f    = idx & 3;           // a0..a3
        int lane = (idx >> 2) & 31;
        int kk   = (idx >> 7) & 15;
        int wo   = (idx >> 11) & 3;
        int gid = lane >> 2, tig = lane & 3;
        int o = (wo & 1) * 16 + gid + (f & 1) * 8;
        int c = kk * 16 + 2 * tig + (f >> 1) * 8;
        const float* W = (wo < 2) ? Wq : Wk;
        g_WtF[idx] = f2bf2(W[o * CC + c], W[o * CC + c + 1]);
    }
    if (idx < BB * CC) g_xsum[idx] = 0.f;
    if (idx < BB * CQ) g_S[idx] = 0.f;
}

// ---------------- kernel 1: FUSED Q+K proj + Qn frags + S + xsum + mpT ------
// block = (b, 256-j slice). Phase A: proj with 4 subtiles interleaved per warp
// (16 indep LDG + 16 indep mma chains per kk). Phase B: mpT mma (x re-read, L2).
__global__ void __launch_bounds__(256)
k_fused(const float* __restrict__ x, const float* __restrict__ bq,
        const float* __restrict__ bk) {
    __shared__ uint32_t kb[32][132];     // Kn bf16x2 j-pairs: [m][jpair]
    __shared__ float qts[8 * 288];       // per-warp Qn fp32 transpose scratch

    const int tid = threadIdx.x;
    const int w = tid >> 5, lane = tid & 31, gid = lane >> 2, tig = lane & 3;
    const int b   = blockIdx.x >> 6;
    const int jsl = blockIdx.x & 63;                 // 256-j slice
    const float* xb = x + (size_t)b * CC * NN;

    const float bq0 = __ldg(&bq[gid]),      bq1 = __ldg(&bq[gid + 8]);
    const float bq2 = __ldg(&bq[gid + 16]), bq3 = __ldg(&bq[gid + 24]);
    const float bk0 = __ldg(&bk[gid]),      bk1 = __ldg(&bk[gid + 8]);
    const float bk2 = __ldg(&bk[gid + 16]), bk3 = __ldg(&bk[gid + 24]);

    const uint4* Wt = (const uint4*)g_WtF + lane;
    float* Qf = qts + w * 288;                       // [32 o][9] fp32 slice

    float S0 = 0.f, S1 = 0.f, S2 = 0.f, S3 = 0.f;

    // ================= phase A: projections, 4 subtiles interleaved ==========
    {
        const int jb = jsl * 256 + w * 8;            // tile t at jb + 64*t
        const float* xp = xb + (size_t)(2 * tig) * NN + jb + gid;

        float dq[4][2][4], dk[4][2][4];    // [tile][o-half][quad]
        #pragma unroll
        for (int t = 0; t < 4; t++)
            #pragma unroll
            for (int h = 0; h < 2; h++)
                #pragma unroll
                for (int q = 0; q < 4; q++) { dq[t][h][q] = 0.f; dk[t][h][q] = 0.f; }

        #pragma unroll 2
        for (int kk = 0; kk < 16; kk++) {
            const size_t r0 = (size_t)(16 * kk) * NN;
            uint32_t pb[4][2];
            #pragma unroll
            for (int t = 0; t < 4; t++) {
                const float* p = xp + 64 * t + r0;
                float u0 = __ldg(p);
                float u1 = __ldg(p + NN);
                float u2 = __ldg(p + 8 * NN);
                float u3 = __ldg(p + 9 * NN);
                pb[t][0] = f2bf2(u0, u1);
                pb[t][1] = f2bf2(u2, u3);
            }
            uint4 a0 = Wt[kk * 32];
            uint4 a1 = Wt[512 + kk * 32];
            uint4 a2 = Wt[1024 + kk * 32];
            uint4 a3 = Wt[1536 + kk * 32];
            #pragma unroll
            for (int t = 0; t < 4; t++) {
                mma_bf16(dq[t][0][0], dq[t][0][1], dq[t][0][2], dq[t][0][3],
                         a0.x, a0.y, a0.z, a0.w, pb[t][0], pb[t][1]);
                mma_bf16(dq[t][1][0], dq[t][1][1], dq[t][1][2], dq[t][1][3],
                         a1.x, a1.y, a1.z, a1.w, pb[t][0], pb[t][1]);
                mma_bf16(dk[t][0][0], dk[t][0][1], dk[t][0][2], dk[t][0][3],
                         a2.x, a2.y, a2.z, a2.w, pb[t][0], pb[t][1]);
                mma_bf16(dk[t][1][0], dk[t][1][1], dk[t][1][2], dk[t][1][3],
                         a3.x, a3.y, a3.z, a3.w, pb[t][0], pb[t][1]);
            }
        }

        // ---- per-tile epilogue (norms, S, kb, qfrag) ----
        #pragma unroll
        for (int t = 0; t < 4; t++) {
            const int jbase = jb + 64 * t;
            const int jt = jbase >> 3;

            float q00 = dq[t][0][0] + bq0, q01 = dq[t][0][1] + bq0;
            float q02 = dq[t][0][2] + bq1, q03 = dq[t][0][3] + bq1;
            float q10 = dq[t][1][0] + bq2, q11 = dq[t][1][1] + bq2;
            float q12 = dq[t][1][2] + bq3, q13 = dq[t][1][3] + bq3;
            float c00 = dk[t][0][0] + bk0, c01 = dk[t][0][1] + bk0;
            float c02 = dk[t][0][2] + bk1, c03 = dk[t][0][3] + bk1;
            float c10 = dk[t][1][0] + bk2, c11 = dk[t][1][1] + bk2;
            float c12 = dk[t][1][2] + bk3, c13 = dk[t][1][3] + bk3;

            float qe = q00*q00 + q02*q02 + q10*q10 + q12*q12;
            float qo = q01*q01 + q03*q03 + q11*q11 + q13*q13;
            float ke = c00*c00 + c02*c02 + c10*c10 + c12*c12;
            float ko = c01*c01 + c03*c03 + c11*c11 + c13*c13;
            #pragma unroll
            for (int off = 4; off <= 16; off <<= 1) {
                qe += __shfl_xor_sync(0xffffffffu, qe, off);
                qo += __shfl_xor_sync(0xffffffffu, qo, off);
                ke += __shfl_xor_sync(0xffffffffu, ke, off);
                ko += __shfl_xor_sync(0xffffffffu, ko, off);
            }
            const float rqe = rsqrtf(qe), rqo = rsqrtf(qo);
            const float rke = rsqrtf(ke), rko = rsqrtf(ko);

            float k00 = c00*rke, k01 = c01*rko, k02 = c02*rke, k03 = c03*rko;
            float k10 = c10*rke, k11 = c11*rko, k12 = c12*rke, k13 = c13*rko;
            float s0 = k00 + k01, s1 = k02 + k03, s2 = k10 + k11, s3 = k12 + k13;
            s0 += __shfl_xor_sync(0xffffffffu, s0, 1); s0 += __shfl_xor_sync(0xffffffffu, s0, 2);
            s1 += __shfl_xor_sync(0xffffffffu, s1, 1); s1 += __shfl_xor_sync(0xffffffffu, s1, 2);
            s2 += __shfl_xor_sync(0xffffffffu, s2, 1); s2 += __shfl_xor_sync(0xffffffffu, s2, 2);
            s3 += __shfl_xor_sync(0xffffffffu, s3, 1); s3 += __shfl_xor_sync(0xffffffffu, s3, 2);
            S0 += s0; S1 += s1; S2 += s2; S3 += s3;

            // Kn bf16 j-pairs -> kb  (pair index = local j / 2)
            {
                const int jp = 32 * t + 4 * w + tig;
                kb[gid][jp]      = f2bf2(k00, k01);
                kb[gid + 8][jp]  = f2bf2(k02, k03);
                kb[gid + 16][jp] = f2bf2(k10, k11);
                kb[gid + 24][jp] = f2bf2(k12, k13);
            }

            // Qn -> scratch -> bf16 B-frags -> qfrag
            const int jl = 2 * tig;
            Qf[(gid)      * 9 + jl]     = q00 * rqe;
            Qf[(gid)      * 9 + jl + 1] = q01 * rqo;
            Qf[(gid + 8)  * 9 + jl]     = q02 * rqe;
            Qf[(gid + 8)  * 9 + jl + 1] = q03 * rqo;
            Qf[(gid + 16) * 9 + jl]     = q10 * rqe;
            Qf[(gid + 16) * 9 + jl + 1] = q11 * rqo;
            Qf[(gid + 24) * 9 + jl]     = q12 * rqe;
            Qf[(gid + 24) * 9 + jl + 1] = q13 * rqo;
            __syncwarp();
            {
                uint4 Bv;
                Bv.x = f2bf2(Qf[(2 * tig)      * 9 + gid], Qf[(2 * tig + 1)  * 9 + gid]);
                Bv.y = f2bf2(Qf[(2 * tig + 8)  * 9 + gid], Qf[(2 * tig + 9)  * 9 + gid]);
                Bv.z = f2bf2(Qf[(2 * tig + 16) * 9 + gid], Qf[(2 * tig + 17) * 9 + gid]);
                Bv.w = f2bf2(Qf[(2 * tig + 24) * 9 + gid], Qf[(2 * tig + 25) * 9 + gid]);
                g_qfrag[(size_t)(b * 2048 + jt) * 32 + lane] = Bv;
            }
            __syncwarp();
        }
    }

    if (tig == 0) {
        atomicAdd(&g_S[b * CQ + gid],      S0);
        atomicAdd(&g_S[b * CQ + gid + 8],  S1);
        atomicAdd(&g_S[b * CQ + gid + 16], S2);
        atomicAdd(&g_S[b * CQ + gid + 24], S3);
    }
    __syncthreads();         // all Kn pairs visible

    // ================= phase B: mpT = x @ Kn^T over this slice (k16) ========
    float e[2][4][4];
    #pragma unroll
    for (int ct = 0; ct < 2; ct++)
        #pragma unroll
        for (int mt = 0; mt < 4; mt++)
            #pragma unroll
            for (int q = 0; q < 4; q++) e[ct][mt][q] = 0.f;
    float sx[2][2] = {{0.f, 0.f}, {0.f, 0.f}};

    #pragma unroll 2
    for (int kk = 0; kk < 16; kk++) {
        const int jg = jsl * 256 + kk * 16;
        uint32_t bb0[4], bb1[4];
        #pragma unroll
        for (int mt = 0; mt < 4; mt++) {
            bb0[mt] = kb[8 * mt + gid][8 * kk + tig];
            bb1[mt] = kb[8 * mt + gid][8 * kk + 4 + tig];
        }
        #pragma unroll
        for (int ct = 0; ct < 2; ct++) {
            const int c0 = 32 * w + 16 * ct;
            float2 v0 = *(const float2*)(xb + (size_t)(c0 + gid)     * NN + jg + 2 * tig);
            float2 v1 = *(const float2*)(xb + (size_t)(c0 + 8 + gid) * NN + jg + 2 * tig);
            float2 v2 = *(const float2*)(xb + (size_t)(c0 + gid)     * NN + jg + 8 + 2 * tig);
            float2 v3 = *(const float2*)(xb + (size_t)(c0 + 8 + gid) * NN + jg + 8 + 2 * tig);
            sx[ct][0] += v0.x + v0.y + v2.x + v2.y;
            sx[ct][1] += v1.x + v1.y + v3.x + v3.y;
            uint32_t a0 = f2bf2(v0.x, v0.y);
            uint32_t a1 = f2bf2(v1.x, v1.y);
            uint32_t a2 = f2bf2(v2.x, v2.y);
            uint32_t a3 = f2bf2(v3.x, v3.y);
            #pragma unroll
            for (int mt = 0; mt < 4; mt++)
                mma_bf16(e[ct][mt][0], e[ct][mt][1], e[ct][mt][2], e[ct][mt][3],
                         a0, a1, a2, a3, bb0[mt], bb1[mt]);
        }
    }

    #pragma unroll
    for (int ct = 0; ct < 2; ct++) {
        float v0 = sx[ct][0], v1 = sx[ct][1];
        v0 += __shfl_xor_sync(0xffffffffu, v0, 1); v0 += __shfl_xor_sync(0xffffffffu, v0, 2);
        v1 += __shfl_xor_sync(0xffffffffu, v1, 1); v1 += __shfl_xor_sync(0xffffffffu, v1, 2);
        if (tig == 0) {
            const int c0 = 32 * w + 16 * ct;
            atomicAdd(&g_xsum[b * CC + c0 + gid],     v0);
            atomicAdd(&g_xsum[b * CC + c0 + 8 + gid], v1);
        }
    }
    float* mpb = &g_mpT[b * CC * CQ];
    #pragma unroll
    for (int ct = 0; ct < 2; ct++) {
        const int c0 = 32 * w + 16 * ct;
        #pragma unroll
        for (int mt = 0; mt < 4; mt++) {
            const int m0 = mt * 8 + 2 * tig;
            atomicAdd(&mpb[(c0 + gid) * CQ + m0],         e[ct][mt][0]);
            atomicAdd(&mpb[(c0 + gid) * CQ + m0 + 1],     e[ct][mt][1]);
            atomicAdd(&mpb[(c0 + 8 + gid) * CQ + m0],     e[ct][mt][2]);
            atomicAdd(&mpb[(c0 + 8 + gid) * CQ + m0 + 1], e[ct][mt][3]);
        }
    }
}

// ---------------- kernel 2: matrix = mp @ Wv^T + bv (x) S ; vsum; fragments -
__global__ void __launch_bounds__(256)
k_mat(const float* __restrict__ Wv, const float* __restrict__ bv) {
    extern __shared__ float shm[];
    float* mpT_s = shm;                 // [256 c][32 m]
    float* wv_s  = shm + CC * CQ;       // [16 cl][257]
    float* xs_s  = wv_s + 16 * 257;     // [256]
    float* S_s   = xs_s + CC;           // [32]

    const int b  = blockIdx.x >> 4;
    const int cg = (blockIdx.x & 15) * 16;
    const int tid = threadIdx.x;

    for (int idx = tid; idx < CC * CQ; idx += 256)
        mpT_s[idx] = g_mpT[b * CC * CQ + idx];
    for (int idx = tid; idx < 16 * CC; idx += 256) {
        int cl = idx >> 8, c = idx & 255;
        wv_s[cl * 257 + c] = Wv[(cg + cl) * CC + c];
    }
    xs_s[tid] = g_xsum[b * CC + tid];
    if (tid < 32) S_s[tid] = g_S[b * CQ + tid];
    __syncthreads();

    const int cl = tid & 15;            // local cp
    const int mg = tid >> 4;            // m pair index (m = 2mg, 2mg+1)
    const int cp = cg + cl;
    const float bvv = __ldg(&bv[cp]);

    float acc0 = bvv * S_s[mg * 2];
    float acc1 = bvv * S_s[mg * 2 + 1];
    float vs = (float)NN * bvv;

    const float* wrow = &wv_s[cl * 257];
    #pragma unroll 8
    for (int c = 0; c < CC; ++c) {
        float wv = wrow[c];
        vs += wv * xs_s[c];
        const float2 mv = *(const float2*)&mpT_s[c * CQ + mg * 2];
        acc0 += mv.x * wv;
        acc1 += mv.y * wv;
    }
    if (mg == 0) g_vsum[b * CC + cp] = vs;

    // scatter into bf16 mfrag A-layout
    const int ct = cp >> 4, cl16 = cp & 15;
    const int gidf = cl16 & 7, hi_row = cl16 >> 3;
    const int kk = mg >> 3, tigf = mg & 3, half = (mg >> 2) & 1;
    const int elem = hi_row + 2 * half;
    g_mfrag[((((b * 16 + ct) * 2 + kk) * 32) + gidf * 4 + tigf) * 4 + elem] = f2bf2(acc0, acc1);
}

// ---------------- kernel 3: streaming epilogue, 4 j-tiles per warp (bf16) ---
__global__ void __launch_bounds__(256)
k_pass2(const float* __restrict__ x, const float* __restrict__ gamma,
        float* __restrict__ out) {
    const int tid = threadIdx.x;
    const int w = tid >> 5, lane = tid & 31, gid = lane >> 2, tig = lane & 3;
    const int b   = blockIdx.x >> 6;
    const int jt0 = (blockIdx.x & 63) * 32 + w * 4;
    const int n0  = jt0 * 8;
    const float gm = __ldg(&gamma[0]);

    const uint4* qf = g_qfrag + (size_t)(b * 2048 + jt0) * 32 + lane;
    uint4 B[4];
    #pragma unroll
    for (int tt = 0; tt < 4; tt++) B[tt] = __ldg(qf + 32 * tt);

    // tailor: per-lane m coverage {2tig,2tig+1} + {8,16,24} offsets
    const int mt2 = 2 * tig;
    float se[8];
    #pragma unroll
    for (int i = 0; i < 4; i++) {
        se[2 * i]     = __ldg(&g_S[b * CQ + 8 * i + mt2])     + EPSV;
        se[2 * i + 1] = __ldg(&g_S[b * CQ + 8 * i + mt2 + 1]) + EPSV;
    }
    float gte[4], gto[4];
    #pragma unroll
    for (int tt = 0; tt < 4; tt++) {
        float tl = bf_lo(B[tt].x) * se[0] + bf_hi(B[tt].x) * se[1]
                 + bf_lo(B[tt].y) * se[2] + bf_hi(B[tt].y) * se[3]
                 + bf_lo(B[tt].z) * se[4] + bf_hi(B[tt].z) * se[5]
                 + bf_lo(B[tt].w) * se[6] + bf_hi(B[tt].w) * se[7];
        tl += __shfl_xor_sync(0xffffffffu, tl, 1);
        tl += __shfl_xor_sync(0xffffffffu, tl, 2);
        float g = gm / (16384.f + tl);
        gte[tt] = __shfl_sync(0xffffffffu, g, 8 * tig);      // j = 2tig
        gto[tt] = __shfl_sync(0xffffffffu, g, 8 * tig + 4);  // j = 2tig+1
    }

    const float* xp = x   + (size_t)b * CC * NN + n0;
    float*       op = out + (size_t)b * CC * NN + n0;
    const uint4* mf = (const uint4*)g_mfrag + (size_t)b * 16 * 2 * 32 + lane;
    const float* vs = g_vsum + b * CC;
    const int jj = 2 * tig;

    #pragma unroll 2
    for (int ct = 0; ct < 16; ct++) {
        const uint4* base = mf + ct * 64;
        uint4 A0 = __ldg(base);         // kk = 0 (m 0..15)
        uint4 A1 = __ldg(base + 32);    // kk = 1 (m 16..31)
        float e[4][4];
        #pragma unroll
        for (int tt = 0; tt < 4; tt++) {
            e[tt][0] = 0.f; e[tt][1] = 0.f; e[tt][2] = 0.f; e[tt][3] = 0.f;
            mma_bf16(e[tt][0], e[tt][1], e[tt][2], e[tt][3],
                     A0.x, A0.y, A0.z, A0.w, B[tt].x, B[tt].y);
            mma_bf16(e[tt][0], e[tt][1], e[tt][2], e[tt][3],
                     A1.x, A1.y, A1.z, A1.w, B[tt].z, B[tt].w);
        }

        const int c1 = ct * 16 + gid;
        const int c2 = c1 + 8;
        const float v1 = __ldg(&vs[c1]), v2 = __ldg(&vs[c2]);
        const float* xr1 = xp + (size_t)c1 * NN + jj;
        const float* xr2 = xp + (size_t)c2 * NN + jj;
        float*       or1 = op + (size_t)c1 * NN + jj;
        float*       or2 = op + (size_t)c2 * NN + jj;
        #pragma unroll
        for (int tt = 0; tt < 4; tt++) {
            float2 x1 = *(const float2*)(xr1 + 8 * tt);
            float2 x2 = *(const float2*)(xr2 + 8 * tt);
            float2 o1, o2;
            o1.x = x1.x + gte[tt] * (v1 + e[tt][0]);
            o1.y = x1.y + gto[tt] * (v1 + e[tt][1]);
            o2.x = x2.x + gte[tt] * (v2 + e[tt][2]);
            o2.y = x2.y + gto[tt] * (v2 + e[tt][3]);
            __stcs((float2*)(or1 + 8 * tt), o1);
            __stcs((float2*)(or2 + 8 * tt), o2);
        }
    }
}

// ---------------- launch --------------------------------------------------
extern "C" void kernel_launch(void* const* d_in, const int* in_sizes, int n_in,
                              void* d_out, int out_size) {
    const float* x     = (const float*)d_in[0];
    const float* Wq    = (const float*)d_in[1];
    const float* bq    = (const float*)d_in[2];
    const float* Wk    = (const float*)d_in[3];
    const float* bk    = (const float*)d_in[4];
    const float* Wv    = (const float*)d_in[5];
    const float* bv    = (const float*)d_in[6];
    const float* gamma = (const float*)d_in[7];
    float* out = (float*)d_out;

    const int shMat = (CC * CQ + 16 * 257 + CC + CQ) * (int)sizeof(float);
    cudaFuncSetAttribute(k_mat, cudaFuncAttributeMaxDynamicSharedMemorySize, shMat);

    k_prep<<<256, 256>>>(Wq, Wk);
    k_fused<<<BB * 64, 256>>>(x, bq, bk);      // 512 blocks: proj(4-tile ILP) + mpT
    k_mat<<<BB * 16, 256, shMat>>>(Wv, bv);    // 128 blocks
    k_pass2<<<BB * 64, 256>>>(x, gamma, out);  // 512 blocks, warp = 32 j
}

// round 14
// speedup vs baseline: 1.7318x; 1.0326x over previous
#include <cuda_runtime.h>
#include <cstdint>

#define BB   8
#define CC   256
#define CQ   32
#define NN   16384
#define EPSV 1e-6f

// ---------------- scratch (device globals) ---------------------------------
__device__ __align__(16) uint32_t g_WtF[4 * 16 * 32 * 4];   // bf16 A-frags; wo 0-1 = Wq, 2-3 = Wk
__device__ float g_mpT[BB * CC * CQ];                       // (Kn @ x^T)^T : [b][c][m]
__device__ float g_S[BB * CQ];                              // sum_n Kn
__device__ float g_xsum[BB * CC];                           // sum_n x
__device__ __align__(16) uint32_t g_mfrag[BB * 16 * 2 * 32 * 4]; // matT bf16 A-frags
__device__ float g_vsum[BB * CC];                           // value_sum
__device__ __align__(16) uint4 g_qfrag[(size_t)BB * 2048 * 32]; // Qn bf16 B-frags [b][jt][lane]

// pack two fp32 -> bf16x2 (lo in bits 0-15, hi in bits 16-31)
__device__ __forceinline__ uint32_t f2bf2(float lo, float hi) {
    uint32_t r;
    asm("cvt.rn.bf16x2.f32 %0, %1, %2;" : "=r"(r) : "f"(hi), "f"(lo));
    return r;
}
__device__ __forceinline__ float bf_lo(uint32_t v) { return __uint_as_float(v << 16); }
__device__ __forceinline__ float bf_hi(uint32_t v) { return __uint_as_float(v & 0xffff0000u); }

__device__ __forceinline__ void mma_bf16(float& d0, float& d1, float& d2, float& d3,
                                         uint32_t a0, uint32_t a1, uint32_t a2, uint32_t a3,
                                         uint32_t b0, uint32_t b1) {
    asm volatile(
        "mma.sync.aligned.m16n8k16.row.col.f32.bf16.bf16.f32 "
        "{%0,%1,%2,%3},{%4,%5,%6,%7},{%8,%9},{%0,%1,%2,%3};"
        : "+f"(d0), "+f"(d1), "+f"(d2), "+f"(d3)
        : "r"(a0), "r"(a1), "r"(a2), "r"(a3), "r"(b0), "r"(b1));
}

// ---------------- kernel 0: zero accumulators + build bf16 W-fragments -----
__global__ void k_prep(const float* __restrict__ Wq, const float* __restrict__ Wk) {
    int idx = blockIdx.x * blockDim.x + threadIdx.x;      // 65536 threads
    if (idx < BB * CC * CQ) g_mpT[idx] = 0.f;
    if (idx < 8192) {
        int f    = idx & 3;           // a0..a3
        int lane = (idx >> 2) & 31;
        int kk   = (idx >> 7) & 15;
        int wo   = (idx >> 11) & 3;
        int gid = lane >> 2, tig = lane & 3;
        int o = (wo & 1) * 16 + gid + (f & 1) * 8;
        int c = kk * 16 + 2 * tig + (f >> 1) * 8;
        const float* W = (wo < 2) ? Wq : Wk;
        g_WtF[idx] = f2bf2(W[o * CC + c], W[o * CC + c + 1]);
    }
    if (idx < BB * CC) g_xsum[idx] = 0.f;
    if (idx < BB * CQ) g_S[idx] = 0.f;
}

// ---------------- kernel 1: FUSED Q+K proj + Qn frags + S + xsum + mpT ------
// block = (b, 256-j slice). Phase A: proj with 4 subtiles interleaved per warp.
// Phase B: mpT mma (x re-read, L2).
__global__ void __launch_bounds__(256)
k_fused(const float* __restrict__ x, const float* __restrict__ bq,
        const float* __restrict__ bk) {
    __shared__ uint32_t kb[32][132];     // Kn bf16x2 j-pairs: [m][jpair]
    __shared__ float qts[8 * 288];       // per-warp Qn fp32 transpose scratch

    const int tid = threadIdx.x;
    const int w = tid >> 5, lane = tid & 31, gid = lane >> 2, tig = lane & 3;
    const int b   = blockIdx.x >> 6;
    const int jsl = blockIdx.x & 63;                 // 256-j slice
    const float* xb = x + (size_t)b * CC * NN;

    const float bq0 = __ldg(&bq[gid]),      bq1 = __ldg(&bq[gid + 8]);
    const float bq2 = __ldg(&bq[gid + 16]), bq3 = __ldg(&bq[gid + 24]);
    const float bk0 = __ldg(&bk[gid]),      bk1 = __ldg(&bk[gid + 8]);
    const float bk2 = __ldg(&bk[gid + 16]), bk3 = __ldg(&bk[gid + 24]);

    const uint4* Wt = (const uint4*)g_WtF + lane;
    float* Qf = qts + w * 288;                       // [32 o][9] fp32 slice

    float S0 = 0.f, S1 = 0.f, S2 = 0.f, S3 = 0.f;

    // ================= phase A: projections, 4 subtiles interleaved ==========
    {
        const int jb = jsl * 256 + w * 8;            // tile t at jb + 64*t
        const float* xp = xb + (size_t)(2 * tig) * NN + jb + gid;

        float dq[4][2][4], dk[4][2][4];    // [tile][o-half][quad]
        #pragma unroll
        for (int t = 0; t < 4; t++)
            #pragma unroll
            for (int h = 0; h < 2; h++)
                #pragma unroll
                for (int q = 0; q < 4; q++) { dq[t][h][q] = 0.f; dk[t][h][q] = 0.f; }

        #pragma unroll 2
        for (int kk = 0; kk < 16; kk++) {
            const size_t r0 = (size_t)(16 * kk) * NN;
            uint32_t pb[4][2];
            #pragma unroll
            for (int t = 0; t < 4; t++) {
                const float* p = xp + 64 * t + r0;
                float u0 = __ldg(p);
                float u1 = __ldg(p + NN);
                float u2 = __ldg(p + 8 * NN);
                float u3 = __ldg(p + 9 * NN);
                pb[t][0] = f2bf2(u0, u1);
                pb[t][1] = f2bf2(u2, u3);
            }
            uint4 a0 = Wt[kk * 32];
            uint4 a1 = Wt[512 + kk * 32];
            uint4 a2 = Wt[1024 + kk * 32];
            uint4 a3 = Wt[1536 + kk * 32];
            #pragma unroll
            for (int t = 0; t < 4; t++) {
                mma_bf16(dq[t][0][0], dq[t][0][1], dq[t][0][2], dq[t][0][3],
                         a0.x, a0.y, a0.z, a0.w, pb[t][0], pb[t][1]);
                mma_bf16(dq[t][1][0], dq[t][1][1], dq[t][1][2], dq[t][1][3],
                         a1.x, a1.y, a1.z, a1.w, pb[t][0], pb[t][1]);
                mma_bf16(dk[t][0][0], dk[t][0][1], dk[t][0][2], dk[t][0][3],
                         a2.x, a2.y, a2.z, a2.w, pb[t][0], pb[t][1]);
                mma_bf16(dk[t][1][0], dk[t][1][1], dk[t][1][2], dk[t][1][3],
                         a3.x, a3.y, a3.z, a3.w, pb[t][0], pb[t][1]);
            }
        }

        // ---- per-tile epilogue (norms, S, kb, qfrag) ----
        #pragma unroll
        for (int t = 0; t < 4; t++) {
            const int jbase = jb + 64 * t;
            const int jt = jbase >> 3;

            float q00 = dq[t][0][0] + bq0, q01 = dq[t][0][1] + bq0;
            float q02 = dq[t][0][2] + bq1, q03 = dq[t][0][3] + bq1;
            float q10 = dq[t][1][0] + bq2, q11 = dq[t][1][1] + bq2;
            float q12 = dq[t][1][2] + bq3, q13 = dq[t][1][3] + bq3;
            float c00 = dk[t][0][0] + bk0, c01 = dk[t][0][1] + bk0;
            float c02 = dk[t][0][2] + bk1, c03 = dk[t][0][3] + bk1;
            float c10 = dk[t][1][0] + bk2, c11 = dk[t][1][1] + bk2;
            float c12 = dk[t][1][2] + bk3, c13 = dk[t][1][3] + bk3;

            float qe = q00*q00 + q02*q02 + q10*q10 + q12*q12;
            float qo = q01*q01 + q03*q03 + q11*q11 + q13*q13;
            float ke = c00*c00 + c02*c02 + c10*c10 + c12*c12;
            float ko = c01*c01 + c03*c03 + c11*c11 + c13*c13;
            #pragma unroll
            for (int off = 4; off <= 16; off <<= 1) {
                qe += __shfl_xor_sync(0xffffffffu, qe, off);
                qo += __shfl_xor_sync(0xffffffffu, qo, off);
                ke += __shfl_xor_sync(0xffffffffu, ke, off);
                ko += __shfl_xor_sync(0xffffffffu, ko, off);
            }
            const float rqe = rsqrtf(qe), rqo = rsqrtf(qo);
            const float rke = rsqrtf(ke), rko = rsqrtf(ko);

            float k00 = c00*rke, k01 = c01*rko, k02 = c02*rke, k03 = c03*rko;
            float k10 = c10*rke, k11 = c11*rko, k12 = c12*rke, k13 = c13*rko;
            float s0 = k00 + k01, s1 = k02 + k03, s2 = k10 + k11, s3 = k12 + k13;
            s0 += __shfl_xor_sync(0xffffffffu, s0, 1); s0 += __shfl_xor_sync(0xffffffffu, s0, 2);
            s1 += __shfl_xor_sync(0xffffffffu, s1, 1); s1 += __shfl_xor_sync(0xffffffffu, s1, 2);
            s2 += __shfl_xor_sync(0xffffffffu, s2, 1); s2 += __shfl_xor_sync(0xffffffffu, s2, 2);
            s3 += __shfl_xor_sync(0xffffffffu, s3, 1); s3 += __shfl_xor_sync(0xffffffffu, s3, 2);
            S0 += s0; S1 += s1; S2 += s2; S3 += s3;

            // Kn bf16 j-pairs -> kb  (pair index = local j / 2)
            {
                const int jp = 32 * t + 4 * w + tig;
                kb[gid][jp]      = f2bf2(k00, k01);
                kb[gid + 8][jp]  = f2bf2(k02, k03);
                kb[gid + 16][jp] = f2bf2(k10, k11);
                kb[gid + 24][jp] = f2bf2(k12, k13);
            }

            // Qn -> scratch -> bf16 B-frags -> qfrag
            const int jl = 2 * tig;
            Qf[(gid)      * 9 + jl]     = q00 * rqe;
            Qf[(gid)      * 9 + jl + 1] = q01 * rqo;
            Qf[(gid + 8)  * 9 + jl]     = q02 * rqe;
            Qf[(gid + 8)  * 9 + jl + 1] = q03 * rqo;
            Qf[(gid + 16) * 9 + jl]     = q10 * rqe;
            Qf[(gid + 16) * 9 + jl + 1] = q11 * rqo;
            Qf[(gid + 24) * 9 + jl]     = q12 * rqe;
            Qf[(gid + 24) * 9 + jl + 1] = q13 * rqo;
            __syncwarp();
            {
                uint4 Bv;
                Bv.x = f2bf2(Qf[(2 * tig)      * 9 + gid], Qf[(2 * tig + 1)  * 9 + gid]);
                Bv.y = f2bf2(Qf[(2 * tig + 8)  * 9 + gid], Qf[(2 * tig + 9)  * 9 + gid]);
                Bv.z = f2bf2(Qf[(2 * tig + 16) * 9 + gid], Qf[(2 * tig + 17) * 9 + gid]);
                Bv.w = f2bf2(Qf[(2 * tig + 24) * 9 + gid], Qf[(2 * tig + 25) * 9 + gid]);
                g_qfrag[(size_t)(b * 2048 + jt) * 32 + lane] = Bv;
            }
            __syncwarp();
        }
    }

    if (tig == 0) {
        atomicAdd(&g_S[b * CQ + gid],      S0);
        atomicAdd(&g_S[b * CQ + gid + 8],  S1);
        atomicAdd(&g_S[b * CQ + gid + 16], S2);
        atomicAdd(&g_S[b * CQ + gid + 24], S3);
    }
    __syncthreads();         // all Kn pairs visible

    // ================= phase B: mpT = x @ Kn^T over this slice (k16) ========
    float e[2][4][4];
    #pragma unroll
    for (int ct = 0; ct < 2; ct++)
        #pragma unroll
        for (int mt = 0; mt < 4; mt++)
            #pragma unroll
            for (int q = 0; q < 4; q++) e[ct][mt][q] = 0.f;
    float sx[2][2] = {{0.f, 0.f}, {0.f, 0.f}};

    #pragma unroll 4
    for (int kk = 0; kk < 16; kk++) {
        const int jg = jsl * 256 + kk * 16;
        uint32_t bb0[4], bb1[4];
        #pragma unroll
        for (int mt = 0; mt < 4; mt++) {
            bb0[mt] = kb[8 * mt + gid][8 * kk + tig];
            bb1[mt] = kb[8 * mt + gid][8 * kk + 4 + tig];
        }
        #pragma unroll
        for (int ct = 0; ct < 2; ct++) {
            const int c0 = 32 * w + 16 * ct;
            float2 v0 = *(const float2*)(xb + (size_t)(c0 + gid)     * NN + jg + 2 * tig);
            float2 v1 = *(const float2*)(xb + (size_t)(c0 + 8 + gid) * NN + jg + 2 * tig);
            float2 v2 = *(const float2*)(xb + (size_t)(c0 + gid)     * NN + jg + 8 + 2 * tig);
            float2 v3 = *(const float2*)(xb + (size_t)(c0 + 8 + gid) * NN + jg + 8 + 2 * tig);
            sx[ct][0] += v0.x + v0.y + v2.x + v2.y;
            sx[ct][1] += v1.x + v1.y + v3.x + v3.y;
            uint32_t a0 = f2bf2(v0.x, v0.y);
            uint32_t a1 = f2bf2(v1.x, v1.y);
            uint32_t a2 = f2bf2(v2.x, v2.y);
            uint32_t a3 = f2bf2(v3.x, v3.y);
            #pragma unroll
            for (int mt = 0; mt < 4; mt++)
                mma_bf16(e[ct][mt][0], e[ct][mt][1], e[ct][mt][2], e[ct][mt][3],
                         a0, a1, a2, a3, bb0[mt], bb1[mt]);
        }
    }

    #pragma unroll
    for (int ct = 0; ct < 2; ct++) {
        float v0 = sx[ct][0], v1 = sx[ct][1];
        v0 += __shfl_xor_sync(0xffffffffu, v0, 1); v0 += __shfl_xor_sync(0xffffffffu, v0, 2);
        v1 += __shfl_xor_sync(0xffffffffu, v1, 1); v1 += __shfl_xor_sync(0xffffffffu, v1, 2);
        if (tig == 0) {
            const int c0 = 32 * w + 16 * ct;
            atomicAdd(&g_xsum[b * CC + c0 + gid],     v0);
            atomicAdd(&g_xsum[b * CC + c0 + 8 + gid], v1);
        }
    }
    float* mpb = &g_mpT[b * CC * CQ];
    #pragma unroll
    for (int ct = 0; ct < 2; ct++) {
        const int c0 = 32 * w + 16 * ct;
        #pragma unroll
        for (int mt = 0; mt < 4; mt++) {
            const int m0 = mt * 8 + 2 * tig;
            atomicAdd(&mpb[(c0 + gid) * CQ + m0],         e[ct][mt][0]);
            atomicAdd(&mpb[(c0 + gid) * CQ + m0 + 1],     e[ct][mt][1]);
            atomicAdd(&mpb[(c0 + 8 + gid) * CQ + m0],     e[ct][mt][2]);
            atomicAdd(&mpb[(c0 + 8 + gid) * CQ + m0 + 1], e[ct][mt][3]);
        }
    }
}

// ---------------- kernel 2: matrix = mp @ Wv^T + bv (x) S ; vsum; fragments -
__global__ void __launch_bounds__(256)
k_mat(const float* __restrict__ Wv, const float* __restrict__ bv) {
    extern __shared__ float shm[];
    float* mpT_s = shm;                 // [256 c][32 m]
    float* wv_s  = shm + CC * CQ;       // [16 cl][257]
    float* xs_s  = wv_s + 16 * 257;     // [256]
    float* S_s   = xs_s + CC;           // [32]

    const int b  = blockIdx.x >> 4;
    const int cg = (blockIdx.x & 15) * 16;
    const int tid = threadIdx.x;

    for (int idx = tid; idx < CC * CQ; idx += 256)
        mpT_s[idx] = g_mpT[b * CC * CQ + idx];
    for (int idx = tid; idx < 16 * CC; idx += 256) {
        int cl = idx >> 8, c = idx & 255;
        wv_s[cl * 257 + c] = Wv[(cg + cl) * CC + c];
    }
    xs_s[tid] = g_xsum[b * CC + tid];
    if (tid < 32) S_s[tid] = g_S[b * CQ + tid];
    __syncthreads();

    const int cl = tid & 15;            // local cp
    const int mg = tid >> 4;            // m pair index (m = 2mg, 2mg+1)
    const int cp = cg + cl;
    const float bvv = __ldg(&bv[cp]);

    float acc0 = bvv * S_s[mg * 2];
    float acc1 = bvv * S_s[mg * 2 + 1];
    float vs = (float)NN * bvv;

    const float* wrow = &wv_s[cl * 257];
    #pragma unroll 8
    for (int c = 0; c < CC; ++c) {
        float wv = wrow[c];
        vs += wv * xs_s[c];
        const float2 mv = *(const float2*)&mpT_s[c * CQ + mg * 2];
        acc0 += mv.x * wv;
        acc1 += mv.y * wv;
    }
    if (mg == 0) g_vsum[b * CC + cp] = vs;

    // scatter into bf16 mfrag A-layout
    const int ct = cp >> 4, cl16 = cp & 15;
    const int gidf = cl16 & 7, hi_row = cl16 >> 3;
    const int kk = mg >> 3, tigf = mg & 3, half = (mg >> 2) & 1;
    const int elem = hi_row + 2 * half;
    g_mfrag[((((b * 16 + ct) * 2 + kk) * 32) + gidf * 4 + tigf) * 4 + elem] = f2bf2(acc0, acc1);
}

// ---------------- kernel 3: streaming epilogue, 2 j-tiles per warp (bf16) ---
// (R12 configuration: measured optimum — 1024 blocks, 48 regs, occ ~48%)
__global__ void __launch_bounds__(256)
k_pass2(const float* __restrict__ x, const float* __restrict__ gamma,
        float* __restrict__ out) {
    const int tid = threadIdx.x;
    const int w = tid >> 5, lane = tid & 31, gid = lane >> 2, tig = lane & 3;
    const int b   = blockIdx.x >> 7;
    const int jt0 = (blockIdx.x & 127) * 16 + w * 2;
    const int n0  = jt0 * 8;
    const float gm = __ldg(&gamma[0]);

    const uint4* qf = g_qfrag + (size_t)(b * 2048 + jt0) * 32 + lane;
    uint4 P = __ldg(qf);          // tile 0
    uint4 R = __ldg(qf + 32);     // tile 1

    const int mt2 = 2 * tig;
    float se[8];
    #pragma unroll
    for (int i = 0; i < 4; i++) {
        se[2 * i]     = __ldg(&g_S[b * CQ + 8 * i + mt2])     + EPSV;
        se[2 * i + 1] = __ldg(&g_S[b * CQ + 8 * i + mt2 + 1]) + EPSV;
    }
    float tl0 = bf_lo(P.x) * se[0] + bf_hi(P.x) * se[1]
              + bf_lo(P.y) * se[2] + bf_hi(P.y) * se[3]
              + bf_lo(P.z) * se[4] + bf_hi(P.z) * se[5]
              + bf_lo(P.w) * se[6] + bf_hi(P.w) * se[7];
    float tl1 = bf_lo(R.x) * se[0] + bf_hi(R.x) * se[1]
              + bf_lo(R.y) * se[2] + bf_hi(R.y) * se[3]
              + bf_lo(R.z) * se[4] + bf_hi(R.z) * se[5]
              + bf_lo(R.w) * se[6] + bf_hi(R.w) * se[7];
    tl0 += __shfl_xor_sync(0xffffffffu, tl0, 1);
    tl0 += __shfl_xor_sync(0xffffffffu, tl0, 2);
    tl1 += __shfl_xor_sync(0xffffffffu, tl1, 1);
    tl1 += __shfl_xor_sync(0xffffffffu, tl1, 2);
    const float g0 = gm / (16384.f + tl0);
    const float g1 = gm / (16384.f + tl1);
    const float gt0e = __shfl_sync(0xffffffffu, g0, 8 * tig);
    const float gt0o = __shfl_sync(0xffffffffu, g0, 8 * tig + 4);
    const float gt1e = __shfl_sync(0xffffffffu, g1, 8 * tig);
    const float gt1o = __shfl_sync(0xffffffffu, g1, 8 * tig + 4);

    const float* xp = x   + (size_t)b * CC * NN + n0;
    float*       op = out + (size_t)b * CC * NN + n0;
    const uint4* mf = (const uint4*)g_mfrag + (size_t)b * 16 * 2 * 32 + lane;
    const float* vs = g_vsum + b * CC;
    const int jj = 2 * tig;

    #pragma unroll 4
    for (int ct = 0; ct < 16; ct++) {
        const uint4* base = mf + ct * 64;
        uint4 A0 = __ldg(base);         // kk = 0 (m 0..15)
        uint4 A1 = __ldg(base + 32);    // kk = 1 (m 16..31)
        float e0 = 0.f, e1 = 0.f, e2 = 0.f, e3 = 0.f;
        float f0 = 0.f, f1 = 0.f, f2 = 0.f, f3 = 0.f;
        mma_bf16(e0, e1, e2, e3, A0.x, A0.y, A0.z, A0.w, P.x, P.y);
        mma_bf16(f0, f1, f2, f3, A0.x, A0.y, A0.z, A0.w, R.x, R.y);
        mma_bf16(e0, e1, e2, e3, A1.x, A1.y, A1.z, A1.w, P.z, P.w);
        mma_bf16(f0, f1, f2, f3, A1.x, A1.y, A1.z, A1.w, R.z, R.w);

        const int c1 = ct * 16 + gid;
        const int c2 = c1 + 8;
        const float v1 = __ldg(&vs[c1]), v2 = __ldg(&vs[c2]);
        float2 x10 = *(const float2*)(xp + (size_t)c1 * NN + jj);
        float2 x11 = *(const float2*)(xp + (size_t)c1 * NN + 8 + jj);
        float2 x20 = *(const float2*)(xp + (size_t)c2 * NN + jj);
        float2 x21 = *(const float2*)(xp + (size_t)c2 * NN + 8 + jj);
        float2 o10, o11, o20, o21;
        o10.x = x10.x + gt0e * (v1 + e0);
        o10.y = x10.y + gt0o * (v1 + e1);
        o11.x = x11.x + gt1e * (v1 + f0);
        o11.y = x11.y + gt1o * (v1 + f1);
        o20.x = x20.x + gt0e * (v2 + e2);
        o20.y = x20.y + gt0o * (v2 + e3);
        o21.x = x21.x + gt1e * (v2 + f2);
        o21.y = x21.y + gt1o * (v2 + f3);
        __stcs((float2*)(op + (size_t)c1 * NN + jj),     o10);
        __stcs((float2*)(op + (size_t)c1 * NN + 8 + jj), o11);
        __stcs((float2*)(op + (size_t)c2 * NN + jj),     o20);
        __stcs((float2*)(op + (size_t)c2 * NN + 8 + jj), o21);
    }
}

// ---------------- launch --------------------------------------------------
extern "C" void kernel_launch(void* const* d_in, const int* in_sizes, int n_in,
                              void* d_out, int out_size) {
    const float* x     = (const float*)d_in[0];
    const float* Wq    = (const float*)d_in[1];
    const float* bq    = (const float*)d_in[2];
    const float* Wk    = (const float*)d_in[3];
    const float* bk    = (const float*)d_in[4];
    const float* Wv    = (const float*)d_in[5];
    const float* bv    = (const float*)d_in[6];
    const float* gamma = (const float*)d_in[7];
    float* out = (float*)d_out;

    const int shMat = (CC * CQ + 16 * 257 + CC + CQ) * (int)sizeof(float);
    cudaFuncSetAttribute(k_mat, cudaFuncAttributeMaxDynamicSharedMemorySize, shMat);

    k_prep<<<256, 256>>>(Wq, Wk);
    k_fused<<<BB * 64, 256>>>(x, bq, bk);      // 512 blocks: proj(4-tile ILP) + mpT
    k_mat<<<BB * 16, 256, shMat>>>(Wv, bv);    // 128 blocks
    k_pass2<<<BB * 128, 256>>>(x, gamma, out); // 1024 blocks, warp = 16 j (R12 optimum)
}

// round 15
// speedup vs baseline: 1.7835x; 1.0299x over previous
#include <cuda_runtime.h>
#include <cstdint>

#define BB   8
#define CC   256
#define CQ   32
#define NN   16384
#define EPSV 1e-6f

// ---------------- scratch (device globals) ---------------------------------
__device__ __align__(16) uint32_t g_WtF[4 * 16 * 32 * 4];   // bf16 A-frags; wo 0-1 = Wq, 2-3 = Wk
__device__ float g_mpT[BB * CC * CQ];                       // (Kn @ x^T)^T : [b][c][m]
__device__ float g_S[BB * CQ];                              // sum_n Kn
__device__ float g_xsum[BB * CC];                           // sum_n x
__device__ __align__(16) uint32_t g_mfrag[BB * 16 * 2 * 32 * 4]; // matT bf16 A-frags
__device__ float g_vsum[BB * CC];                           // value_sum
__device__ __align__(16) uint4 g_qfrag[(size_t)BB * 2048 * 32]; // Qn bf16 B-frags [b][jt][lane]

// pack two fp32 -> bf16x2 (lo in bits 0-15, hi in bits 16-31)
__device__ __forceinline__ uint32_t f2bf2(float lo, float hi) {
    uint32_t r;
    asm("cvt.rn.bf16x2.f32 %0, %1, %2;" : "=r"(r) : "f"(hi), "f"(lo));
    return r;
}
__device__ __forceinline__ float bf_lo(uint32_t v) { return __uint_as_float(v << 16); }
__device__ __forceinline__ float bf_hi(uint32_t v) { return __uint_as_float(v & 0xffff0000u); }

__device__ __forceinline__ void mma_bf16(float& d0, float& d1, float& d2, float& d3,
                                         uint32_t a0, uint32_t a1, uint32_t a2, uint32_t a3,
                                         uint32_t b0, uint32_t b1) {
    asm volatile(
        "mma.sync.aligned.m16n8k16.row.col.f32.bf16.bf16.f32 "
        "{%0,%1,%2,%3},{%4,%5,%6,%7},{%8,%9},{%0,%1,%2,%3};"
        : "+f"(d0), "+f"(d1), "+f"(d2), "+f"(d3)
        : "r"(a0), "r"(a1), "r"(a2), "r"(a3), "r"(b0), "r"(b1));
}

// ---------------- kernel 0: zero accumulators + build bf16 W-fragments -----
__global__ void k_prep(const float* __restrict__ Wq, const float* __restrict__ Wk) {
    int idx = blockIdx.x * blockDim.x + threadIdx.x;      // 65536 threads
    if (idx < BB * CC * CQ) g_mpT[idx] = 0.f;
    if (idx < 8192) {
        int f    = idx & 3;           // a0..a3
        int lane = (idx >> 2) & 31;
        int kk   = (idx >> 7) & 15;
        int wo   = (idx >> 11) & 3;
        int gid = lane >> 2, tig = lane & 3;
        int o = (wo & 1) * 16 + gid + (f & 1) * 8;
        int c = kk * 16 + 2 * tig + (f >> 1) * 8;
        const float* W = (wo < 2) ? Wq : Wk;
        g_WtF[idx] = f2bf2(W[o * CC + c], W[o * CC + c + 1]);
    }
    if (idx < BB * CC) g_xsum[idx] = 0.f;
    if (idx < BB * CQ) g_S[idx] = 0.f;
}

// ---------------- kernel 1: FUSED Q+K proj + Qn frags + S + xsum + mpT ------
// block = (b, 256-j slice). Phase A: proj with 4 subtiles interleaved per warp.
// Phase B: mpT mma (x re-read, L2).
__global__ void __launch_bounds__(256)
k_fused(const float* __restrict__ x, const float* __restrict__ bq,
        const float* __restrict__ bk) {
    __shared__ uint32_t kb[32][132];     // Kn bf16x2 j-pairs: [m][jpair]
    __shared__ float qts[8 * 288];       // per-warp Qn fp32 transpose scratch

    const int tid = threadIdx.x;
    const int w = tid >> 5, lane = tid & 31, gid = lane >> 2, tig = lane & 3;
    const int b   = blockIdx.x >> 6;
    const int jsl = blockIdx.x & 63;                 // 256-j slice
    const float* xb = x + (size_t)b * CC * NN;

    const float bq0 = __ldg(&bq[gid]),      bq1 = __ldg(&bq[gid + 8]);
    const float bq2 = __ldg(&bq[gid + 16]), bq3 = __ldg(&bq[gid + 24]);
    const float bk0 = __ldg(&bk[gid]),      bk1 = __ldg(&bk[gid + 8]);
    const float bk2 = __ldg(&bk[gid + 16]), bk3 = __ldg(&bk[gid + 24]);

    const uint4* Wt = (const uint4*)g_WtF + lane;
    float* Qf = qts + w * 288;                       // [32 o][9] fp32 slice

    float S0 = 0.f, S1 = 0.f, S2 = 0.f, S3 = 0.f;

    // ================= phase A: projections, 4 subtiles interleaved ==========
    {
        const int jb = jsl * 256 + w * 8;            // tile t at jb + 64*t
        const float* xp = xb + (size_t)(2 * tig) * NN + jb + gid;

        float dq[4][2][4], dk[4][2][4];    // [tile][o-half][quad]
        #pragma unroll
        for (int t = 0; t < 4; t++)
            #pragma unroll
            for (int h = 0; h < 2; h++)
                #pragma unroll
                for (int q = 0; q < 4; q++) { dq[t][h][q] = 0.f; dk[t][h][q] = 0.f; }

        #pragma unroll 2
        for (int kk = 0; kk < 16; kk++) {
            const size_t r0 = (size_t)(16 * kk) * NN;
            uint32_t pb[4][2];
            #pragma unroll
            for (int t = 0; t < 4; t++) {
                const float* p = xp + 64 * t + r0;
                float u0 = __ldg(p);
                float u1 = __ldg(p + NN);
                float u2 = __ldg(p + 8 * NN);
                float u3 = __ldg(p + 9 * NN);
                pb[t][0] = f2bf2(u0, u1);
                pb[t][1] = f2bf2(u2, u3);
            }
            uint4 a0 = Wt[kk * 32];
            uint4 a1 = Wt[512 + kk * 32];
            uint4 a2 = Wt[1024 + kk * 32];
            uint4 a3 = Wt[1536 + kk * 32];
            #pragma unroll
            for (int t = 0; t < 4; t++) {
                mma_bf16(dq[t][0][0], dq[t][0][1], dq[t][0][2], dq[t][0][3],
                         a0.x, a0.y, a0.z, a0.w, pb[t][0], pb[t][1]);
                mma_bf16(dq[t][1][0], dq[t][1][1], dq[t][1][2], dq[t][1][3],
                         a1.x, a1.y, a1.z, a1.w, pb[t][0], pb[t][1]);
                mma_bf16(dk[t][0][0], dk[t][0][1], dk[t][0][2], dk[t][0][3],
                         a2.x, a2.y, a2.z, a2.w, pb[t][0], pb[t][1]);
                mma_bf16(dk[t][1][0], dk[t][1][1], dk[t][1][2], dk[t][1][3],
                         a3.x, a3.y, a3.z, a3.w, pb[t][0], pb[t][1]);
            }
        }

        // ---- per-tile epilogue (norms, S, kb, qfrag) ----
        #pragma unroll
        for (int t = 0; t < 4; t++) {
            const int jbase = jb + 64 * t;
            const int jt = jbase >> 3;

            float q00 = dq[t][0][0] + bq0, q01 = dq[t][0][1] + bq0;
            float q02 = dq[t][0][2] + bq1, q03 = dq[t][0][3] + bq1;
            float q10 = dq[t][1][0] + bq2, q11 = dq[t][1][1] + bq2;
            float q12 = dq[t][1][2] + bq3, q13 = dq[t][1][3] + bq3;
            float c00 = dk[t][0][0] + bk0, c01 = dk[t][0][1] + bk0;
            float c02 = dk[t][0][2] + bk1, c03 = dk[t][0][3] + bk1;
            float c10 = dk[t][1][0] + bk2, c11 = dk[t][1][1] + bk2;
            float c12 = dk[t][1][2] + bk3, c13 = dk[t][1][3] + bk3;

            float qe = q00*q00 + q02*q02 + q10*q10 + q12*q12;
            float qo = q01*q01 + q03*q03 + q11*q11 + q13*q13;
            float ke = c00*c00 + c02*c02 + c10*c10 + c12*c12;
            float ko = c01*c01 + c03*c03 + c11*c11 + c13*c13;
            #pragma unroll
            for (int off = 4; off <= 16; off <<= 1) {
                qe += __shfl_xor_sync(0xffffffffu, qe, off);
                qo += __shfl_xor_sync(0xffffffffu, qo, off);
                ke += __shfl_xor_sync(0xffffffffu, ke, off);
                ko += __shfl_xor_sync(0xffffffffu, ko, off);
            }
            const float rqe = rsqrtf(qe), rqo = rsqrtf(qo);
            const float rke = rsqrtf(ke), rko = rsqrtf(ko);

            float k00 = c00*rke, k01 = c01*rko, k02 = c02*rke, k03 = c03*rko;
            float k10 = c10*rke, k11 = c11*rko, k12 = c12*rke, k13 = c13*rko;
            float s0 = k00 + k01, s1 = k02 + k03, s2 = k10 + k11, s3 = k12 + k13;
            s0 += __shfl_xor_sync(0xffffffffu, s0, 1); s0 += __shfl_xor_sync(0xffffffffu, s0, 2);
            s1 += __shfl_xor_sync(0xffffffffu, s1, 1); s1 += __shfl_xor_sync(0xffffffffu, s1, 2);
            s2 += __shfl_xor_sync(0xffffffffu, s2, 1); s2 += __shfl_xor_sync(0xffffffffu, s2, 2);
            s3 += __shfl_xor_sync(0xffffffffu, s3, 1); s3 += __shfl_xor_sync(0xffffffffu, s3, 2);
            S0 += s0; S1 += s1; S2 += s2; S3 += s3;

            // Kn bf16 j-pairs -> kb  (pair index = local j / 2)
            {
                const int jp = 32 * t + 4 * w + tig;
                kb[gid][jp]      = f2bf2(k00, k01);
                kb[gid + 8][jp]  = f2bf2(k02, k03);
                kb[gid + 16][jp] = f2bf2(k10, k11);
                kb[gid + 24][jp] = f2bf2(k12, k13);
            }

            // Qn -> scratch -> bf16 B-frags -> qfrag
            const int jl = 2 * tig;
            Qf[(gid)      * 9 + jl]     = q00 * rqe;
            Qf[(gid)      * 9 + jl + 1] = q01 * rqo;
            Qf[(gid + 8)  * 9 + jl]     = q02 * rqe;
            Qf[(gid + 8)  * 9 + jl + 1] = q03 * rqo;
            Qf[(gid + 16) * 9 + jl]     = q10 * rqe;
            Qf[(gid + 16) * 9 + jl + 1] = q11 * rqo;
            Qf[(gid + 24) * 9 + jl]     = q12 * rqe;
            Qf[(gid + 24) * 9 + jl + 1] = q13 * rqo;
            __syncwarp();
            {
                uint4 Bv;
                Bv.x = f2bf2(Qf[(2 * tig)      * 9 + gid], Qf[(2 * tig + 1)  * 9 + gid]);
                Bv.y = f2bf2(Qf[(2 * tig + 8)  * 9 + gid], Qf[(2 * tig + 9)  * 9 + gid]);
                Bv.z = f2bf2(Qf[(2 * tig + 16) * 9 + gid], Qf[(2 * tig + 17) * 9 + gid]);
                Bv.w = f2bf2(Qf[(2 * tig + 24) * 9 + gid], Qf[(2 * tig + 25) * 9 + gid]);
                g_qfrag[(size_t)(b * 2048 + jt) * 32 + lane] = Bv;
            }
            __syncwarp();
        }
    }

    if (tig == 0) {
        atomicAdd(&g_S[b * CQ + gid],      S0);
        atomicAdd(&g_S[b * CQ + gid + 8],  S1);
        atomicAdd(&g_S[b * CQ + gid + 16], S2);
        atomicAdd(&g_S[b * CQ + gid + 24], S3);
    }
    __syncthreads();         // all Kn pairs visible

    // ================= phase B: mpT = x @ Kn^T over this slice (k16) ========
    float e[2][4][4];
    #pragma unroll
    for (int ct = 0; ct < 2; ct++)
        #pragma unroll
        for (int mt = 0; mt < 4; mt++)
            #pragma unroll
            for (int q = 0; q < 4; q++) e[ct][mt][q] = 0.f;
    float sx[2][2] = {{0.f, 0.f}, {0.f, 0.f}};

    #pragma unroll 4
    for (int kk = 0; kk < 16; kk++) {
        const int jg = jsl * 256 + kk * 16;
        uint32_t bb0[4], bb1[4];
        #pragma unroll
        for (int mt = 0; mt < 4; mt++) {
            bb0[mt] = kb[8 * mt + gid][8 * kk + tig];
            bb1[mt] = kb[8 * mt + gid][8 * kk + 4 + tig];
        }
        #pragma unroll
        for (int ct = 0; ct < 2; ct++) {
            const int c0 = 32 * w + 16 * ct;
            float2 v0 = *(const float2*)(xb + (size_t)(c0 + gid)     * NN + jg + 2 * tig);
            float2 v1 = *(const float2*)(xb + (size_t)(c0 + 8 + gid) * NN + jg + 2 * tig);
            float2 v2 = *(const float2*)(xb + (size_t)(c0 + gid)     * NN + jg + 8 + 2 * tig);
            float2 v3 = *(const float2*)(xb + (size_t)(c0 + 8 + gid) * NN + jg + 8 + 2 * tig);
            sx[ct][0] += v0.x + v0.y + v2.x + v2.y;
            sx[ct][1] += v1.x + v1.y + v3.x + v3.y;
            uint32_t a0 = f2bf2(v0.x, v0.y);
            uint32_t a1 = f2bf2(v1.x, v1.y);
            uint32_t a2 = f2bf2(v2.x, v2.y);
            uint32_t a3 = f2bf2(v3.x, v3.y);
            #pragma unroll
            for (int mt = 0; mt < 4; mt++)
                mma_bf16(e[ct][mt][0], e[ct][mt][1], e[ct][mt][2], e[ct][mt][3],
                         a0, a1, a2, a3, bb0[mt], bb1[mt]);
        }
    }

    #pragma unroll
    for (int ct = 0; ct < 2; ct++) {
        float v0 = sx[ct][0], v1 = sx[ct][1];
        v0 += __shfl_xor_sync(0xffffffffu, v0, 1); v0 += __shfl_xor_sync(0xffffffffu, v0, 2);
        v1 += __shfl_xor_sync(0xffffffffu, v1, 1); v1 += __shfl_xor_sync(0xffffffffu, v1, 2);
        if (tig == 0) {
            const int c0 = 32 * w + 16 * ct;
            atomicAdd(&g_xsum[b * CC + c0 + gid],     v0);
            atomicAdd(&g_xsum[b * CC + c0 + 8 + gid], v1);
        }
    }
    float* mpb = &g_mpT[b * CC * CQ];
    #pragma unroll
    for (int ct = 0; ct < 2; ct++) {
        const int c0 = 32 * w + 16 * ct;
        #pragma unroll
        for (int mt = 0; mt < 4; mt++) {
            const int m0 = mt * 8 + 2 * tig;
            atomicAdd(&mpb[(c0 + gid) * CQ + m0],         e[ct][mt][0]);
            atomicAdd(&mpb[(c0 + gid) * CQ + m0 + 1],     e[ct][mt][1]);
            atomicAdd(&mpb[(c0 + 8 + gid) * CQ + m0],     e[ct][mt][2]);
            atomicAdd(&mpb[(c0 + 8 + gid) * CQ + m0 + 1], e[ct][mt][3]);
        }
    }
}

// ---------------- kernel 2: matrix = mp @ Wv^T + bv (x) S ; vsum; fragments -
// 128 blocks. Thread layout: warp w = m-group (4 m), lane = (cl 0..15, ch 0..1).
// Each thread reduces over 128 c; shfl_xor(16) combines the two c-halves.
__global__ void __launch_bounds__(256)
k_mat(const float* __restrict__ Wv, const float* __restrict__ bv) {
    extern __shared__ float shm[];
    float* mpT_s = shm;                 // [256 c][32 m]
    float* wv_s  = shm + CC * CQ;       // [16 cl][257]
    float* xs_s  = wv_s + 16 * 257;     // [256]
    float* S_s   = xs_s + CC;           // [32]

    const int b  = blockIdx.x >> 4;
    const int cg = (blockIdx.x & 15) * 16;
    const int tid = threadIdx.x;
    const int w = tid >> 5, lane = tid & 31;
    const int cl = lane & 15, ch = lane >> 4;

    for (int idx = tid; idx < CC * CQ; idx += 256)
        mpT_s[idx] = g_mpT[b * CC * CQ + idx];
    for (int idx = tid; idx < 16 * CC; idx += 256) {
        int l = idx >> 8, c = idx & 255;
        wv_s[l * 257 + c] = Wv[(cg + l) * CC + c];
    }
    xs_s[tid] = g_xsum[b * CC + tid];
    if (tid < 32) S_s[tid] = g_S[b * CQ + tid];
    __syncthreads();

    const int cp = cg + cl;
    const int m0 = 4 * w;
    const float bvv = __ldg(&bv[cp]);

    float acc[4];
    #pragma unroll
    for (int i = 0; i < 4; i++)
        acc[i] = (ch == 0) ? bvv * S_s[m0 + i] : 0.f;
    float vs = (ch == 0) ? (float)NN * bvv : 0.f;

    const float* wrow = &wv_s[cl * 257] + ch * 128;
    const float* xsp  = xs_s + ch * 128;
    const float* mpp  = mpT_s + (ch * 128) * CQ + m0;
    #pragma unroll 8
    for (int c = 0; c < 128; ++c) {
        float wv = wrow[c];
        vs += wv * xsp[c];
        const float4 mv = *(const float4*)(mpp + c * CQ);
        acc[0] += mv.x * wv; acc[1] += mv.y * wv;
        acc[2] += mv.z * wv; acc[3] += mv.w * wv;
    }
    #pragma unroll
    for (int i = 0; i < 4; i++)
        acc[i] += __shfl_xor_sync(0xffffffffu, acc[i], 16);
    vs += __shfl_xor_sync(0xffffffffu, vs, 16);

    if (ch == 0) {
        if (w == 0) g_vsum[b * CC + cp] = vs;
        // scatter pairs (m0,m0+1) and (m0+2,m0+3) into bf16 mfrag layout
        const int ct = cp >> 4, cl16 = cp & 15;
        const int gidf = cl16 & 7, hi_row = cl16 >> 3;
        #pragma unroll
        for (int p = 0; p < 2; p++) {
            const int mg = 2 * w + p;
            const int kk = mg >> 3, tigf = mg & 3, half = (mg >> 2) & 1;
            const int elem = hi_row + 2 * half;
            g_mfrag[((((b * 16 + ct) * 2 + kk) * 32) + gidf * 4 + tigf) * 4 + elem] =
                f2bf2(acc[2 * p], acc[2 * p + 1]);
        }
    }
}

// ---------------- kernel 3: streaming epilogue, 2 j-tiles x 128 c per block -
__global__ void __launch_bounds__(256)
k_pass2(const float* __restrict__ x, const float* __restrict__ gamma,
        float* __restrict__ out) {
    const int tid = threadIdx.x;
    const int w = tid >> 5, lane = tid & 31, gid = lane >> 2, tig = lane & 3;
    const int b    = blockIdx.x >> 8;
    const int inner = blockIdx.x & 255;
    const int ch   = inner & 1;                    // c-half: ct 0..7 or 8..15
    const int jt0  = (inner >> 1) * 16 + w * 2;
    const int n0   = jt0 * 8;
    const float gm = __ldg(&gamma[0]);

    const uint4* qf = g_qfrag + (size_t)(b * 2048 + jt0) * 32 + lane;
    uint4 P = __ldg(qf);          // tile 0
    uint4 R = __ldg(qf + 32);     // tile 1

    const int mt2 = 2 * tig;
    float se[8];
    #pragma unroll
    for (int i = 0; i < 4; i++) {
        se[2 * i]     = __ldg(&g_S[b * CQ + 8 * i + mt2])     + EPSV;
        se[2 * i + 1] = __ldg(&g_S[b * CQ + 8 * i + mt2 + 1]) + EPSV;
    }
    float tl0 = bf_lo(P.x) * se[0] + bf_hi(P.x) * se[1]
              + bf_lo(P.y) * se[2] + bf_hi(P.y) * se[3]
              + bf_lo(P.z) * se[4] + bf_hi(P.z) * se[5]
              + bf_lo(P.w) * se[6] + bf_hi(P.w) * se[7];
    float tl1 = bf_lo(R.x) * se[0] + bf_hi(R.x) * se[1]
              + bf_lo(R.y) * se[2] + bf_hi(R.y) * se[3]
              + bf_lo(R.z) * se[4] + bf_hi(R.z) * se[5]
              + bf_lo(R.w) * se[6] + bf_hi(R.w) * se[7];
    tl0 += __shfl_xor_sync(0xffffffffu, tl0, 1);
    tl0 += __shfl_xor_sync(0xffffffffu, tl0, 2);
    tl1 += __shfl_xor_sync(0xffffffffu, tl1, 1);
    tl1 += __shfl_xor_sync(0xffffffffu, tl1, 2);
    const float g0 = gm / (16384.f + tl0);
    const float g1 = gm / (16384.f + tl1);
    const float gt0e = __shfl_sync(0xffffffffu, g0, 8 * tig);
    const float gt0o = __shfl_sync(0xffffffffu, g0, 8 * tig + 4);
    const float gt1e = __shfl_sync(0xffffffffu, g1, 8 * tig);
    const float gt1o = __shfl_sync(0xffffffffu, g1, 8 * tig + 4);

    const float* xp = x   + (size_t)b * CC * NN + n0;
    float*       op = out + (size_t)b * CC * NN + n0;
    const uint4* mf = (const uint4*)g_mfrag + (size_t)b * 16 * 2 * 32 + lane;
    const float* vs = g_vsum + b * CC;
    const int jj = 2 * tig;
    const int ct0 = 8 * ch;

    #pragma unroll 4
    for (int ci = 0; ci < 8; ci++) {
        const int ct = ct0 + ci;
        const uint4* base = mf + ct * 64;
        uint4 A0 = __ldg(base);         // kk = 0 (m 0..15)
        uint4 A1 = __ldg(base + 32);    // kk = 1 (m 16..31)
        float e0 = 0.f, e1 = 0.f, e2 = 0.f, e3 = 0.f;
        float f0 = 0.f, f1 = 0.f, f2 = 0.f, f3 = 0.f;
        mma_bf16(e0, e1, e2, e3, A0.x, A0.y, A0.z, A0.w, P.x, P.y);
        mma_bf16(f0, f1, f2, f3, A0.x, A0.y, A0.z, A0.w, R.x, R.y);
        mma_bf16(e0, e1, e2, e3, A1.x, A1.y, A1.z, A1.w, P.z, P.w);
        mma_bf16(f0, f1, f2, f3, A1.x, A1.y, A1.z, A1.w, R.z, R.w);

        const int c1 = ct * 16 + gid;
        const int c2 = c1 + 8;
        const float v1 = __ldg(&vs[c1]), v2 = __ldg(&vs[c2]);
        float2 x10 = *(const float2*)(xp + (size_t)c1 * NN + jj);
        float2 x11 = *(const float2*)(xp + (size_t)c1 * NN + 8 + jj);
        float2 x20 = *(const float2*)(xp + (size_t)c2 * NN + jj);
        float2 x21 = *(const float2*)(xp + (size_t)c2 * NN + 8 + jj);
        float2 o10, o11, o20, o21;
        o10.x = x10.x + gt0e * (v1 + e0);
        o10.y = x10.y + gt0o * (v1 + e1);
        o11.x = x11.x + gt1e * (v1 + f0);
        o11.y = x11.y + gt1o * (v1 + f1);
        o20.x = x20.x + gt0e * (v2 + e2);
        o20.y = x20.y + gt0o * (v2 + e3);
        o21.x = x21.x + gt1e * (v2 + f2);
        o21.y = x21.y + gt1o * (v2 + f3);
        __stcs((float2*)(op + (size_t)c1 * NN + jj),     o10);
        __stcs((float2*)(op + (size_t)c1 * NN + 8 + jj), o11);
        __stcs((float2*)(op + (size_t)c2 * NN + jj),     o20);
        __stcs((float2*)(op + (size_t)c2 * NN + 8 + jj), o21);
    }
}

// ---------------- launch --------------------------------------------------
extern "C" void kernel_launch(void* const* d_in, const int* in_sizes, int n_in,
                              void* d_out, int out_size) {
    const float* x     = (const float*)d_in[0];
    const float* Wq    = (const float*)d_in[1];
    const float* bq    = (const float*)d_in[2];
    const float* Wk    = (const float*)d_in[3];
    const float* bk    = (const float*)d_in[4];
    const float* Wv    = (const float*)d_in[5];
    const float* bv    = (const float*)d_in[6];
    const float* gamma = (const float*)d_in[7];
    float* out = (float*)d_out;

    const int shMat = (CC * CQ + 16 * 257 + CC + CQ) * (int)sizeof(float);
    cudaFuncSetAttribute(k_mat, cudaFuncAttributeMaxDynamicSharedMemorySize, shMat);

    k_prep<<<256, 256>>>(Wq, Wk);
    k_fused<<<BB * 64, 256>>>(x, bq, bk);       // 512 blocks: proj(4-tile ILP) + mpT
    k_mat<<<BB * 16, 256, shMat>>>(Wv, bv);     // 128 blocks, split-c reduction
    k_pass2<<<BB * 256, 256>>>(x, gamma, out);  // 2048 blocks: 16 j x 128 c each
}